// round 4
// baseline (speedup 1.0000x reference)
#include <cuda_runtime.h>
#include <cuda_bf16.h>
#include <cstdint>
#include <math.h>

#define SQ   2048
#define DM   4096
#define PR   2048
#define NH   32
#define DH   128
#define RP   64

// ===================== small helpers ========================================
static __device__ __forceinline__ uint32_t smem_u32(const void* p) {
    uint32_t a;
    asm("{ .reg .u64 t; cvta.to.shared.u64 t, %1; cvt.u32.u64 %0, t; }"
        : "=r"(a) : "l"(p));
    return a;
}

static __device__ __forceinline__ uint32_t cvt_bf16x2(float a, float b) {
    uint32_t r;
    asm("cvt.rn.bf16x2.f32 %0, %1, %2;" : "=r"(r) : "f"(b), "f"(a));
    return r;
}

#define LDSM4(r, addr) \
    asm volatile("ldmatrix.sync.aligned.m8n8.x4.shared.b16 {%0,%1,%2,%3}, [%4];" \
        : "=r"((r)[0]), "=r"((r)[1]), "=r"((r)[2]), "=r"((r)[3]) : "r"(addr))

#define MMA(d, a, b0v, b1v) \
    asm volatile("mma.sync.aligned.m16n8k16.row.col.f32.bf16.bf16.f32 " \
        "{%0,%1,%2,%3}, {%4,%5,%6,%7}, {%8,%9}, {%0,%1,%2,%3};" \
        : "+f"((d)[0]), "+f"((d)[1]), "+f"((d)[2]), "+f"((d)[3]) \
        : "r"((a)[0]), "r"((a)[1]), "r"((a)[2]), "r"((a)[3]), "r"(b0v), "r"(b1v))

#define MMA_S8(d, a, b0v, b1v) \
    asm volatile("mma.sync.aligned.m16n8k32.row.col.s32.s8.s8.s32 " \
        "{%0,%1,%2,%3}, {%4,%5,%6,%7}, {%8,%9}, {%0,%1,%2,%3};" \
        : "+r"((d)[0]), "+r"((d)[1]), "+r"((d)[2]), "+r"((d)[3]) \
        : "r"((a)[0]), "r"((a)[1]), "r"((a)[2]), "r"((a)[3]), "r"(b0v), "r"(b1v))

#define CP_ASYNC16(sp, gp) \
    asm volatile("cp.async.cg.shared.global [%0], [%1], 16;" :: "r"(sp), "l"(gp))
#define CP_COMMIT() asm volatile("cp.async.commit_group;" ::: "memory")
#define CP_WAIT2()  asm volatile("cp.async.wait_group 2;" ::: "memory")

// ===================== scratch (device globals) =============================
__device__ float g_scales[16];
// 0:x 1:WDQ 2:WUQ 3:WDKV 4:WUK 5:WUV 6:WKR 7:WO 8:cq 9:ckv 10:attno

__device__ float g_cq   [(size_t)SQ * PR];
__device__ float g_ckv  [(size_t)SQ * PR];
__device__ float g_q    [(size_t)SQ * DM];
__device__ float g_knope[(size_t)SQ * PR];
__device__ float g_v    [(size_t)SQ * DM];
__device__ float g_krope[(size_t)SQ * RP];
__device__ float g_attno[(size_t)SQ * DM];
__device__ float g_scores[(size_t)NH * SQ * SQ];

// int8 limbs, activations (row-major [M,K])
__device__ int8_t g_xq1 [(size_t)SQ * DM], g_xq2 [(size_t)SQ * DM];
__device__ int8_t g_cqq1[(size_t)SQ * PR], g_cqq2[(size_t)SQ * PR];
__device__ int8_t g_ckq1[(size_t)SQ * PR], g_ckq2[(size_t)SQ * PR];
__device__ int8_t g_aoq1[(size_t)SQ * DM], g_aoq2[(size_t)SQ * DM];

// int8 limbs, weights transposed to [N,K]
__device__ int8_t g_wdq1 [(size_t)PR * DM], g_wdq2 [(size_t)PR * DM];
__device__ int8_t g_wuq1 [(size_t)DM * PR], g_wuq2 [(size_t)DM * PR];
__device__ int8_t g_wdk1 [(size_t)PR * DM], g_wdk2 [(size_t)PR * DM];
__device__ int8_t g_wuk1 [(size_t)PR * PR], g_wuk2 [(size_t)PR * PR];
__device__ int8_t g_wuv1 [(size_t)DM * PR], g_wuv2 [(size_t)DM * PR];
__device__ int8_t g_wkr1 [(size_t)RP * DM], g_wkr2 [(size_t)RP * DM];
__device__ int8_t g_wo1  [(size_t)DM * DM], g_wo2  [(size_t)DM * DM];

// bf16 attention operands
__device__ __nv_bfloat16 g_qa_hi[(size_t)SQ * DM], g_qa_lo[(size_t)SQ * DM];
__device__ __nv_bfloat16 g_kh_hi[(size_t)NH * SQ * DH], g_kh_lo[(size_t)NH * SQ * DH];
__device__ __nv_bfloat16 g_vt_hi[(size_t)NH * DH * SQ], g_vt_lo[(size_t)NH * DH * SQ];
__device__ __nv_bfloat16 g_p_hi [(size_t)NH * SQ * SQ], g_p_lo [(size_t)NH * SQ * SQ];

// ===================== scale utilities =======================================
__global__ void zero_scales_kernel(float* s)
{
    if (threadIdx.x < 16) s[threadIdx.x] = 0.0f;
}

__global__ void absmax_kernel(const float* __restrict__ in, long long n, float* slot)
{
    __shared__ float red[256];
    float m = 0.0f;
    for (long long i = (long long)blockIdx.x * 256 + threadIdx.x; i < n;
         i += (long long)gridDim.x * 256)
        m = fmaxf(m, fabsf(in[i]));
    red[threadIdx.x] = m; __syncthreads();
    for (int s = 128; s > 0; s >>= 1) {
        if (threadIdx.x < s) red[threadIdx.x] = fmaxf(red[threadIdx.x], red[threadIdx.x + s]);
        __syncthreads();
    }
    if (threadIdx.x == 0) atomicMax((int*)slot, __float_as_int(red[0]));
}

static __device__ __forceinline__ int q_clamp(float v)
{
    int q = __float2int_rn(v);
    return (q > 127) ? 127 : ((q < -127) ? -127 : q);
}

// row-major activation quant: limb1 + limb2 (scale s/128)
__global__ void quant_act(const float4* __restrict__ in,
                          char4* __restrict__ q1, char4* __restrict__ q2,
                          int n4, const float* __restrict__ slot)
{
    const int i = blockIdx.x * blockDim.x + threadIdx.x;
    if (i >= n4) return;
    const float am = slot[0];
    const float s   = am * (1.0f / 127.0f);
    const float inv = (am > 0.0f) ? (127.0f / am) : 0.0f;
    const float4 f = in[i];
    char4 a, b;
    int   t;
    t = q_clamp(f.x * inv); a.x = (char)t; b.x = (char)q_clamp((f.x - t * s) * 128.0f * inv);
    t = q_clamp(f.y * inv); a.y = (char)t; b.y = (char)q_clamp((f.y - t * s) * 128.0f * inv);
    t = q_clamp(f.z * inv); a.z = (char)t; b.z = (char)q_clamp((f.z - t * s) * 128.0f * inv);
    t = q_clamp(f.w * inv); a.w = (char)t; b.w = (char)q_clamp((f.w - t * s) * 128.0f * inv);
    q1[i] = a;  q2[i] = b;
}

// weight transpose-quant: in [K,N] fp32 -> out [N,K] int8 limbs
__global__ void transpose_quant(const float* __restrict__ in,
                                int8_t* __restrict__ o1, int8_t* __restrict__ o2,
                                int ldin, int ldout, const float* __restrict__ slot)
{
    __shared__ float t[32][33];
    const int c0 = blockIdx.x * 32, r0 = blockIdx.y * 32;
    const int tx = threadIdx.x, ty = threadIdx.y;
#pragma unroll
    for (int j = 0; j < 32; j += 8)
        t[ty + j][tx] = in[(long long)(r0 + ty + j) * ldin + c0 + tx];
    __syncthreads();
    const float am = slot[0];
    const float s   = am * (1.0f / 127.0f);
    const float inv = (am > 0.0f) ? (127.0f / am) : 0.0f;
#pragma unroll
    for (int j = 0; j < 32; j += 8) {
        const float f = t[tx][ty + j];
        const int q = q_clamp(f * inv);
        const long long o = (long long)(c0 + ty + j) * ldout + r0 + tx;
        o1[o] = (int8_t)q;
        o2[o] = (int8_t)q_clamp((f - q * s) * 128.0f * inv);
    }
}

// ===================== int8 2-limb HMMA GEMM =================================
// C = alpha*sA*sB*(acc11 + acc_cross/128) (+bias).  A:[M,K] row-major limbs,
// B:[N,K] K-major limbs.  CTA 128x128, BK=64 (64B rows), 3-stage cp.async.
#define STAGE_BYTES 40960
#define GEMM_SMEM   (3 * STAGE_BYTES)

__global__ void __launch_bounds__(256, 1)
gemm_s8(const int8_t* __restrict__ A1, const int8_t* __restrict__ A2,
        const int8_t* __restrict__ B1, const int8_t* __restrict__ B2,
        float* __restrict__ Cf,
        int M, int N, int K, int lda, int ldb, int ldc,
        float alpha, const float* __restrict__ bias,
        const float* __restrict__ sAp, const float* __restrict__ sBp)
{
    extern __shared__ char smem[];
    const uint32_t sbase = smem_u32(smem);
    const int tid  = threadIdx.x;
    const int lane = tid & 31;
    const int w    = tid >> 5;
    const int wm   = w & 1;
    const int wn   = w >> 1;

    const int m0 = blockIdx.y * 128;
    const int n0 = blockIdx.x * 128;
    const int nk = K >> 6;

    const int lr   = tid >> 2;
    const int lcol = tid & 3;

    auto load_stage = [&](int kt, int slot) {
        const int k0 = kt << 6;
        const uint32_t sb = sbase + slot * STAGE_BYTES;
#pragma unroll
        for (int i = 0; i < 8; ++i) {
            const int r   = ((i & 1) << 6) + lr;
            const int mat = i >> 1;               // 0:A1 1:A2 2:B1 3:B2
            const int8_t* gp;
            if (mat < 2) {
                const int8_t* base = (mat == 0) ? A1 : A2;
                gp = base + (long long)(m0 + r) * lda + k0 + lcol * 16;
            } else {
                int rn = n0 + r; if (rn >= N) rn = N - 1;
                const int8_t* base = (mat == 2) ? B1 : B2;
                gp = base + (long long)rn * ldb + k0 + lcol * 16;
            }
            const uint32_t sp = sb + mat * 10240 + r * 80 + lcol * 16;
            CP_ASYNC16(sp, gp);
        }
        CP_COMMIT();
    };

    const uint32_t aOff = (uint32_t)((wm * 64 + (lane & 15)) * 80 + ((lane >> 4) & 1) * 16);
    const uint32_t bOff = (uint32_t)((wn * 32 + ((lane >> 4) & 1) * 8 + (lane & 7)) * 80
                                     + ((lane >> 3) & 1) * 16);

    int acc1[4][4][4], acc2[4][4][4];
#pragma unroll
    for (int a = 0; a < 4; a++)
#pragma unroll
        for (int b = 0; b < 4; b++)
#pragma unroll
            for (int c = 0; c < 4; c++) { acc1[a][b][c] = 0; acc2[a][b][c] = 0; }

    load_stage(0, 0);
    if (nk > 1) load_stage(1, 1); else CP_COMMIT();

    for (int kt = 0; kt < nk; ++kt) {
        if (kt + 2 < nk) load_stage(kt + 2, (kt + 2) % 3);
        else CP_COMMIT();
        CP_WAIT2();
        __syncthreads();

        const uint32_t sb = sbase + (kt % 3) * STAGE_BYTES;
#pragma unroll
        for (int kk = 0; kk < 2; ++kk) {
            uint32_t a1[4][4], a2[4][4], b1[2][4], b2[2][4];
#pragma unroll
            for (int mt = 0; mt < 4; ++mt) {
                const uint32_t ad = sb + aOff + mt * 1280 + kk * 32;
                LDSM4(a1[mt], ad);
                LDSM4(a2[mt], ad + 10240);
            }
#pragma unroll
            for (int bt = 0; bt < 2; ++bt) {
                const uint32_t bd = sb + 20480 + bOff + bt * 1280 + kk * 32;
                LDSM4(b1[bt], bd);
                LDSM4(b2[bt], bd + 10240);
            }
#pragma unroll
            for (int mt = 0; mt < 4; ++mt)
#pragma unroll
                for (int nt = 0; nt < 4; ++nt) {
                    const int bt = nt >> 1, s2 = (nt & 1) * 2;
                    MMA_S8(acc1[mt][nt], a1[mt], b1[bt][s2], b1[bt][s2 + 1]);
                    MMA_S8(acc2[mt][nt], a1[mt], b2[bt][s2], b2[bt][s2 + 1]);
                    MMA_S8(acc2[mt][nt], a2[mt], b1[bt][s2], b1[bt][s2 + 1]);
                }
        }
        __syncthreads();
    }

    const float scale = sAp[0] * sBp[0] * (1.0f / (127.0f * 127.0f)) * alpha;
    const int er = lane >> 2;
    const int ec = (lane & 3) << 1;
#pragma unroll
    for (int mt = 0; mt < 4; ++mt) {
#pragma unroll
        for (int nt = 0; nt < 4; ++nt) {
            const int gr = m0 + wm * 64 + mt * 16 + er;
            const int gc = n0 + wn * 32 + nt * 8 + ec;
            if (gc >= N) continue;
            float v0 = ((float)acc1[mt][nt][0] + (float)acc2[mt][nt][0] * 0.0078125f) * scale;
            float v1 = ((float)acc1[mt][nt][1] + (float)acc2[mt][nt][1] * 0.0078125f) * scale;
            float v2 = ((float)acc1[mt][nt][2] + (float)acc2[mt][nt][2] * 0.0078125f) * scale;
            float v3 = ((float)acc1[mt][nt][3] + (float)acc2[mt][nt][3] * 0.0078125f) * scale;
            if (bias) {
                const float b0 = bias[gc], b1 = bias[gc + 1];
                v0 += b0; v1 += b1; v2 += b0; v3 += b1;
            }
            *(float2*)&Cf[(long long)gr * ldc + gc]       = make_float2(v0, v1);
            *(float2*)&Cf[(long long)(gr + 8) * ldc + gc] = make_float2(v2, v3);
        }
    }
}

// ===================== split-bf16 HMMA GEMM (attention) ======================
__global__ void __launch_bounds__(256, 1)
gemm_bf16(const __nv_bfloat16* __restrict__ Ahi, const __nv_bfloat16* __restrict__ Alo,
          const __nv_bfloat16* __restrict__ Bhi, const __nv_bfloat16* __restrict__ Blo,
          float* __restrict__ Cf,
          __nv_bfloat16* __restrict__ Chi, __nv_bfloat16* __restrict__ Clo,
          int M, int N, int K, int lda, int ldb, int ldc,
          long long sA, long long sB, long long sC,
          float alpha, const float* __restrict__ bias)
{
    extern __shared__ char smem[];
    const uint32_t sbase = smem_u32(smem);
    const int tid  = threadIdx.x;
    const int lane = tid & 31;
    const int w    = tid >> 5;
    const int wm   = w & 1;
    const int wn   = w >> 1;

    const long long z = blockIdx.z;
    Ahi += z * sA;  Alo += z * sA;
    Bhi += z * sB;  Blo += z * sB;
    if (Cf)  Cf  += z * sC;
    if (Chi) { Chi += z * sC; Clo += z * sC; }

    const int m0 = blockIdx.y * 128;
    const int n0 = blockIdx.x * 128;
    const int nk = K >> 5;

    const int lr   = tid >> 2;
    const int lcol = tid & 3;

    auto load_stage = [&](int kt, int slot) {
        const int k0 = kt << 5;
        const uint32_t sb = sbase + slot * STAGE_BYTES;
#pragma unroll
        for (int i = 0; i < 8; ++i) {
            const int r   = ((i & 1) << 6) + lr;
            const int mat = i >> 1;
            const __nv_bfloat16* gp;
            if (mat < 2) {
                const __nv_bfloat16* base = (mat == 0) ? Ahi : Alo;
                gp = base + (long long)(m0 + r) * lda + k0 + lcol * 8;
            } else {
                int rn = n0 + r; if (rn >= N) rn = N - 1;
                const __nv_bfloat16* base = (mat == 2) ? Bhi : Blo;
                gp = base + (long long)rn * ldb + k0 + lcol * 8;
            }
            const uint32_t sp = sb + mat * 10240 + r * 80 + lcol * 16;
            CP_ASYNC16(sp, gp);
        }
        CP_COMMIT();
    };

    const uint32_t aOff = (uint32_t)((wm * 64 + (lane & 15)) * 80 + ((lane >> 4) & 1) * 16);
    const uint32_t bOff = (uint32_t)((wn * 32 + ((lane >> 4) & 1) * 8 + (lane & 7)) * 80
                                     + ((lane >> 3) & 1) * 16);

    float acc[4][4][4];
#pragma unroll
    for (int a = 0; a < 4; a++)
#pragma unroll
        for (int b = 0; b < 4; b++)
#pragma unroll
            for (int c = 0; c < 4; c++) acc[a][b][c] = 0.0f;

    load_stage(0, 0);
    if (nk > 1) load_stage(1, 1); else CP_COMMIT();

    for (int kt = 0; kt < nk; ++kt) {
        if (kt + 2 < nk) load_stage(kt + 2, (kt + 2) % 3);
        else CP_COMMIT();
        CP_WAIT2();
        __syncthreads();

        const uint32_t sb = sbase + (kt % 3) * STAGE_BYTES;
#pragma unroll
        for (int kk = 0; kk < 2; ++kk) {
            uint32_t ah[4][4], al[4][4], bh[2][4], bl[2][4];
#pragma unroll
            for (int mt = 0; mt < 4; ++mt) {
                const uint32_t ad = sb + aOff + mt * 1280 + kk * 32;
                LDSM4(ah[mt], ad);
                LDSM4(al[mt], ad + 10240);
            }
#pragma unroll
            for (int bt = 0; bt < 2; ++bt) {
                const uint32_t bd = sb + 20480 + bOff + bt * 1280 + kk * 32;
                LDSM4(bh[bt], bd);
                LDSM4(bl[bt], bd + 10240);
            }
#pragma unroll
            for (int mt = 0; mt < 4; ++mt)
#pragma unroll
                for (int nt = 0; nt < 4; ++nt) {
                    const int bt = nt >> 1, s2 = (nt & 1) * 2;
                    MMA(acc[mt][nt], ah[mt], bh[bt][s2], bh[bt][s2 + 1]);
                    MMA(acc[mt][nt], ah[mt], bl[bt][s2], bl[bt][s2 + 1]);
                    MMA(acc[mt][nt], al[mt], bh[bt][s2], bh[bt][s2 + 1]);
                }
        }
        __syncthreads();
    }

    const int er = lane >> 2;
    const int ec = (lane & 3) << 1;
#pragma unroll
    for (int mt = 0; mt < 4; ++mt) {
#pragma unroll
        for (int nt = 0; nt < 4; ++nt) {
            const int gr = m0 + wm * 64 + mt * 16 + er;
            const int gc = n0 + wn * 32 + nt * 8 + ec;
            if (gc >= N) continue;
            float v0 = acc[mt][nt][0] * alpha;
            float v1 = acc[mt][nt][1] * alpha;
            float v2 = acc[mt][nt][2] * alpha;
            float v3 = acc[mt][nt][3] * alpha;
            if (bias) {
                const float b0 = bias[gc], b1 = bias[gc + 1];
                v0 += b0; v1 += b1; v2 += b0; v3 += b1;
            }
            const long long o0 = (long long)gr * ldc + gc;
            const long long o1 = (long long)(gr + 8) * ldc + gc;
            if (Cf) {
                *(float2*)&Cf[o0] = make_float2(v0, v1);
                *(float2*)&Cf[o1] = make_float2(v2, v3);
            }
            if (Chi) {
                uint32_t h = cvt_bf16x2(v0, v1);
                uint32_t l = cvt_bf16x2(v0 - __uint_as_float(h << 16),
                                        v1 - __uint_as_float(h & 0xFFFF0000u));
                *(uint32_t*)&Chi[o0] = h;
                *(uint32_t*)&Clo[o0] = l;
                h = cvt_bf16x2(v2, v3);
                l = cvt_bf16x2(v2 - __uint_as_float(h << 16),
                               v3 - __uint_as_float(h & 0xFFFF0000u));
                *(uint32_t*)&Chi[o1] = h;
                *(uint32_t*)&Clo[o1] = l;
            }
        }
    }
}

// ===================== elementwise split fp32 -> bf16 hi/lo ==================
__global__ void split_f32(const float4* __restrict__ in,
                          uint2* __restrict__ hi, uint2* __restrict__ lo, int n4)
{
    const int i = blockIdx.x * blockDim.x + threadIdx.x;
    if (i >= n4) return;
    const float4 f = in[i];
    const uint32_t h01 = cvt_bf16x2(f.x, f.y);
    const uint32_t h23 = cvt_bf16x2(f.z, f.w);
    const uint32_t l01 = cvt_bf16x2(f.x - __uint_as_float(h01 << 16),
                                    f.y - __uint_as_float(h01 & 0xFFFF0000u));
    const uint32_t l23 = cvt_bf16x2(f.z - __uint_as_float(h23 << 16),
                                    f.w - __uint_as_float(h23 & 0xFFFF0000u));
    hi[i] = make_uint2(h01, h23);
    lo[i] = make_uint2(l01, l23);
}

// ===================== transpose + split fp32 -> bf16 hi/lo =================
__global__ void transpose_split(const float* __restrict__ in,
                                __nv_bfloat16* __restrict__ ohi,
                                __nv_bfloat16* __restrict__ olo,
                                int R, int C, int ldin, int ldout,
                                long long sIn, long long sOut)
{
    __shared__ float t[32][33];
    const long long z = blockIdx.z;
    in += z * sIn;  ohi += z * sOut;  olo += z * sOut;
    const int c0 = blockIdx.x * 32, r0 = blockIdx.y * 32;
    const int tx = threadIdx.x, ty = threadIdx.y;
#pragma unroll
    for (int j = 0; j < 32; j += 8)
        t[ty + j][tx] = in[(long long)(r0 + ty + j) * ldin + c0 + tx];
    __syncthreads();
#pragma unroll
    for (int j = 0; j < 32; j += 8) {
        const float f = t[tx][ty + j];
        const __nv_bfloat16 h = __float2bfloat16(f);
        const __nv_bfloat16 l = __float2bfloat16(f - __bfloat162float(h));
        const long long o = (long long)(c0 + ty + j) * ldout + r0 + tx;
        ohi[o] = h;  olo[o] = l;
    }
}

// ===================== RoPE ==================================================
__device__ __forceinline__ void rope_pair(float* base, int i, int pos)
{
    const float f = __expf(-(2.0f * (float)i / 128.0f) * 9.210340371976184f);
    const float ang = (float)pos * f;
    const float c = cosf(ang), s = sinf(ang);
    const float a = base[i];
    const float b = base[i + 32];
    base[i]      = a * c - b * s;
    base[i + 32] = b * c + a * s;
}

__global__ void rope_q_kernel(float* q, const int* past)
{
    const int idx = blockIdx.x * blockDim.x + threadIdx.x;
    if (idx >= SQ * NH * 32) return;
    const int s = idx / (NH * 32);
    const int r = idx % (NH * 32);
    rope_pair(q + (size_t)s * DM + (r / 32) * DH + 64, r % 32, past[0] + s);
}

__global__ void rope_k_kernel(float* krope, const int* past)
{
    const int idx = blockIdx.x * blockDim.x + threadIdx.x;
    if (idx >= SQ * 32) return;
    rope_pair(krope + (size_t)(idx / 32) * RP, idx % 32, past[0] + idx / 32);
}

// ===================== assemble K heads -> bf16 hi/lo [h][s][d] ==============
__global__ void assemble_khead_split(const float* __restrict__ knope,
                                     const float* __restrict__ krope,
                                     __nv_bfloat16* __restrict__ khi,
                                     __nv_bfloat16* __restrict__ klo)
{
    const int idx = blockIdx.x * blockDim.x + threadIdx.x;
    if (idx >= NH * SQ * DH) return;
    const int d = idx & (DH - 1);
    const int s = (idx >> 7) & (SQ - 1);
    const int h = idx >> 18;
    float v;
    if (d < 64) v = knope[(size_t)s * PR + h * 64 + d];
    else        v = krope[(size_t)s * RP + (d - 64)];
    const __nv_bfloat16 hb = __float2bfloat16(v);
    khi[idx] = hb;
    klo[idx] = __float2bfloat16(v - __bfloat162float(hb));
}

// ===================== softmax -> split bf16 probs ===========================
__global__ void softmax_split(const float* __restrict__ scores,
                              __nv_bfloat16* __restrict__ phi,
                              __nv_bfloat16* __restrict__ plo)
{
    const int row = blockIdx.x;
    const int h   = blockIdx.y;
    const size_t base = ((size_t)h * SQ + row) * SQ;
    const float* p = scores + base;
    __nv_bfloat16* oh = phi + base;
    __nv_bfloat16* ol = plo + base;
    const int tid = threadIdx.x;
    __shared__ float red[256];

    float vals[8];
    float m = -1e30f;
#pragma unroll
    for (int i = 0; i < 8; ++i) {
        vals[i] = p[tid + i * 256];
        m = fmaxf(m, vals[i]);
    }
    red[tid] = m; __syncthreads();
    for (int s = 128; s > 0; s >>= 1) {
        if (tid < s) red[tid] = fmaxf(red[tid], red[tid + s]);
        __syncthreads();
    }
    m = red[0]; __syncthreads();

    float sum = 0.0f;
#pragma unroll
    for (int i = 0; i < 8; ++i) {
        vals[i] = __expf(vals[i] - m);
        sum += vals[i];
    }
    red[tid] = sum; __syncthreads();
    for (int s = 128; s > 0; s >>= 1) {
        if (tid < s) red[tid] += red[tid + s];
        __syncthreads();
    }
    const float inv = 1.0f / red[0];
#pragma unroll
    for (int i = 0; i < 8; ++i) {
        const float v = vals[i] * inv;
        const __nv_bfloat16 hb = __float2bfloat16(v);
        oh[tid + i * 256] = hb;
        ol[tid + i * 256] = __float2bfloat16(v - __bfloat162float(hb));
    }
}

// ===================== launch ================================================
extern "C" void kernel_launch(void* const* d_in, const int* in_sizes, int n_in,
                              void* d_out, int out_size)
{
    const float* x        = (const float*)d_in[0];
    const float* W_DQ     = (const float*)d_in[1];
    const float* W_UQ     = (const float*)d_in[2];
    const float* W_DKV    = (const float*)d_in[3];
    const float* W_UK     = (const float*)d_in[4];
    const float* W_UV     = (const float*)d_in[5];
    const float* W_K_rope = (const float*)d_in[6];
    const float* W_O      = (const float*)d_in[7];
    const float* b_O      = (const float*)d_in[8];
    const int*   past     = (const int*)d_in[9];
    float* out = (float*)d_out;

    float *scales, *cq, *ckv, *q, *knope, *v, *krope, *attno, *scores;
    cudaGetSymbolAddress((void**)&scales, g_scales);
    cudaGetSymbolAddress((void**)&cq,     g_cq);
    cudaGetSymbolAddress((void**)&ckv,    g_ckv);
    cudaGetSymbolAddress((void**)&q,      g_q);
    cudaGetSymbolAddress((void**)&knope,  g_knope);
    cudaGetSymbolAddress((void**)&v,      g_v);
    cudaGetSymbolAddress((void**)&krope,  g_krope);
    cudaGetSymbolAddress((void**)&attno,  g_attno);
    cudaGetSymbolAddress((void**)&scores, g_scores);

    int8_t *xq1, *xq2, *cqq1, *cqq2, *ckq1, *ckq2, *aoq1, *aoq2,
           *wdq1, *wdq2, *wuq1, *wuq2, *wdk1, *wdk2, *wuk1, *wuk2,
           *wuv1, *wuv2, *wkr1, *wkr2, *wo1, *wo2;
    cudaGetSymbolAddress((void**)&xq1,  g_xq1);  cudaGetSymbolAddress((void**)&xq2,  g_xq2);
    cudaGetSymbolAddress((void**)&cqq1, g_cqq1); cudaGetSymbolAddress((void**)&cqq2, g_cqq2);
    cudaGetSymbolAddress((void**)&ckq1, g_ckq1); cudaGetSymbolAddress((void**)&ckq2, g_ckq2);
    cudaGetSymbolAddress((void**)&aoq1, g_aoq1); cudaGetSymbolAddress((void**)&aoq2, g_aoq2);
    cudaGetSymbolAddress((void**)&wdq1, g_wdq1); cudaGetSymbolAddress((void**)&wdq2, g_wdq2);
    cudaGetSymbolAddress((void**)&wuq1, g_wuq1); cudaGetSymbolAddress((void**)&wuq2, g_wuq2);
    cudaGetSymbolAddress((void**)&wdk1, g_wdk1); cudaGetSymbolAddress((void**)&wdk2, g_wdk2);
    cudaGetSymbolAddress((void**)&wuk1, g_wuk1); cudaGetSymbolAddress((void**)&wuk2, g_wuk2);
    cudaGetSymbolAddress((void**)&wuv1, g_wuv1); cudaGetSymbolAddress((void**)&wuv2, g_wuv2);
    cudaGetSymbolAddress((void**)&wkr1, g_wkr1); cudaGetSymbolAddress((void**)&wkr2, g_wkr2);
    cudaGetSymbolAddress((void**)&wo1,  g_wo1);  cudaGetSymbolAddress((void**)&wo2,  g_wo2);

    __nv_bfloat16 *qa_h, *qa_l, *kh_h, *kh_l, *vt_h, *vt_l, *p_h, *p_l;
    cudaGetSymbolAddress((void**)&qa_h, g_qa_hi); cudaGetSymbolAddress((void**)&qa_l, g_qa_lo);
    cudaGetSymbolAddress((void**)&kh_h, g_kh_hi); cudaGetSymbolAddress((void**)&kh_l, g_kh_lo);
    cudaGetSymbolAddress((void**)&vt_h, g_vt_hi); cudaGetSymbolAddress((void**)&vt_l, g_vt_lo);
    cudaGetSymbolAddress((void**)&p_h,  g_p_hi);  cudaGetSymbolAddress((void**)&p_l,  g_p_lo);

    cudaFuncSetAttribute(gemm_s8,   cudaFuncAttributeMaxDynamicSharedMemorySize, GEMM_SMEM);
    cudaFuncSetAttribute(gemm_bf16, cudaFuncAttributeMaxDynamicSharedMemorySize, GEMM_SMEM);

    const dim3 blk(256);
    const dim3 tb(32, 8);
    const int AMB = 1024;   // absmax grid

    // 0-4: setup so launch #5 (ncu -s 5) is the first big int8 GEMM
    zero_scales_kernel<<<1, 32>>>(scales);
    absmax_kernel<<<AMB, 256>>>(x, (long long)SQ * DM, scales + 0);
    quant_act<<<(SQ * DM / 4 + 255) / 256, blk>>>(
        (const float4*)x, (char4*)xq1, (char4*)xq2, SQ * DM / 4, scales + 0);
    absmax_kernel<<<AMB, 256>>>(W_DQ, (long long)DM * PR, scales + 1);
    transpose_quant<<<dim3(PR / 32, DM / 32), tb>>>(W_DQ, wdq1, wdq2, PR, DM, scales + 1);

    // 5: cq = x @ W_DQ   (K=4096)
    gemm_s8<<<dim3(PR / 128, SQ / 128), blk, GEMM_SMEM>>>(
        xq1, xq2, wdq1, wdq2, cq, SQ, PR, DM, DM, DM, PR,
        1.0f, nullptr, scales + 0, scales + 1);

    // ckv = x @ W_DKV
    absmax_kernel<<<AMB, 256>>>(W_DKV, (long long)DM * PR, scales + 3);
    transpose_quant<<<dim3(PR / 32, DM / 32), tb>>>(W_DKV, wdk1, wdk2, PR, DM, scales + 3);
    gemm_s8<<<dim3(PR / 128, SQ / 128), blk, GEMM_SMEM>>>(
        xq1, xq2, wdk1, wdk2, ckv, SQ, PR, DM, DM, DM, PR,
        1.0f, nullptr, scales + 0, scales + 3);

    // krope = x @ W_K_rope  (N=64)
    absmax_kernel<<<AMB, 256>>>(W_K_rope, (long long)DM * RP, scales + 6);
    transpose_quant<<<dim3(RP / 32, DM / 32), tb>>>(W_K_rope, wkr1, wkr2, RP, DM, scales + 6);
    gemm_s8<<<dim3(1, SQ / 128), blk, GEMM_SMEM>>>(
        xq1, xq2, wkr1, wkr2, krope, SQ, RP, DM, DM, DM, RP,
        1.0f, nullptr, scales + 0, scales + 6);

    // quant cq, ckv
    absmax_kernel<<<AMB, 256>>>(cq, (long long)SQ * PR, scales + 8);
    quant_act<<<(SQ * PR / 4 + 255) / 256, blk>>>(
        (const float4*)cq, (char4*)cqq1, (char4*)cqq2, SQ * PR / 4, scales + 8);
    absmax_kernel<<<AMB, 256>>>(ckv, (long long)SQ * PR, scales + 9);
    quant_act<<<(SQ * PR / 4 + 255) / 256, blk>>>(
        (const float4*)ckv, (char4*)ckq1, (char4*)ckq2, SQ * PR / 4, scales + 9);

    // q = cq @ W_UQ   (K=2048)
    absmax_kernel<<<AMB, 256>>>(W_UQ, (long long)PR * DM, scales + 2);
    transpose_quant<<<dim3(DM / 32, PR / 32), tb>>>(W_UQ, wuq1, wuq2, DM, PR, scales + 2);
    gemm_s8<<<dim3(DM / 128, SQ / 128), blk, GEMM_SMEM>>>(
        cqq1, cqq2, wuq1, wuq2, q, SQ, DM, PR, PR, PR, DM,
        1.0f, nullptr, scales + 8, scales + 2);

    // knope = ckv @ W_UK
    absmax_kernel<<<AMB, 256>>>(W_UK, (long long)PR * PR, scales + 4);
    transpose_quant<<<dim3(PR / 32, PR / 32), tb>>>(W_UK, wuk1, wuk2, PR, PR, scales + 4);
    gemm_s8<<<dim3(PR / 128, SQ / 128), blk, GEMM_SMEM>>>(
        ckq1, ckq2, wuk1, wuk2, knope, SQ, PR, PR, PR, PR, PR,
        1.0f, nullptr, scales + 9, scales + 4);

    // v = ckv @ W_UV
    absmax_kernel<<<AMB, 256>>>(W_UV, (long long)PR * DM, scales + 5);
    transpose_quant<<<dim3(DM / 32, PR / 32), tb>>>(W_UV, wuv1, wuv2, DM, PR, scales + 5);
    gemm_s8<<<dim3(DM / 128, SQ / 128), blk, GEMM_SMEM>>>(
        ckq1, ckq2, wuv1, wuv2, v, SQ, DM, PR, PR, PR, DM,
        1.0f, nullptr, scales + 9, scales + 5);

    // RoPE + bf16 operand prep
    rope_q_kernel<<<(SQ * NH * 32 + 255) / 256, blk>>>(q, past);
    rope_k_kernel<<<(SQ * 32 + 255) / 256, blk>>>(krope, past);
    split_f32<<<(SQ * DM / 4 + 255) / 256, blk>>>(
        (const float4*)q, (uint2*)qa_h, (uint2*)qa_l, SQ * DM / 4);
    assemble_khead_split<<<(NH * SQ * DH + 255) / 256, blk>>>(knope, krope, kh_h, kh_l);
    transpose_split<<<dim3(DH / 32, SQ / 32, NH), tb>>>(
        v, vt_h, vt_l, SQ, DH, DM, SQ, (long long)DH, (long long)DH * SQ);

    // scores[h] = (Q_h @ K_h^T) / sqrt(128)
    const float alpha = 0.08838834764831845f;
    gemm_bf16<<<dim3(SQ / 128, SQ / 128, NH), blk, GEMM_SMEM>>>(
        qa_h, qa_l, kh_h, kh_l, scores, nullptr, nullptr,
        SQ, SQ, DH, DM, DH, SQ,
        (long long)DH, (long long)SQ * DH, (long long)SQ * SQ, alpha, nullptr);

    // softmax -> split probs
    softmax_split<<<dim3(SQ, NH), blk>>>(scores, p_h, p_l);

    // attno[h] = P_h @ V_h   (fp32, interleaved [s][h*DH])
    gemm_bf16<<<dim3(1, SQ / 128, NH), blk, GEMM_SMEM>>>(
        p_h, p_l, vt_h, vt_l, attno, nullptr, nullptr,
        SQ, DH, SQ, SQ, SQ, DM,
        (long long)SQ * SQ, (long long)DH * SQ, (long long)DH, 1.0f, nullptr);

    // out = attno @ W_O + b_O
    absmax_kernel<<<AMB, 256>>>(attno, (long long)SQ * DM, scales + 10);
    quant_act<<<(SQ * DM / 4 + 255) / 256, blk>>>(
        (const float4*)attno, (char4*)aoq1, (char4*)aoq2, SQ * DM / 4, scales + 10);
    absmax_kernel<<<AMB, 256>>>(W_O, (long long)DM * DM, scales + 7);
    transpose_quant<<<dim3(DM / 32, DM / 32), tb>>>(W_O, wo1, wo2, DM, DM, scales + 7);
    gemm_s8<<<dim3(DM / 128, SQ / 128), blk, GEMM_SMEM>>>(
        aoq1, aoq2, wo1, wo2, out, SQ, DM, DM, DM, DM, DM,
        1.0f, b_O, scales + 10, scales + 7);
}

// round 5
// speedup vs baseline: 1.9316x; 1.9316x over previous
#include <cuda_runtime.h>
#include <cuda_bf16.h>
#include <cstdint>
#include <math.h>

#define SQ   2048
#define DM   4096
#define PR   2048
#define NH   32
#define DH   128
#define RP   64

// ===================== small helpers ========================================
static __device__ __forceinline__ uint32_t smem_u32(const void* p) {
    uint32_t a;
    asm("{ .reg .u64 t; cvta.to.shared.u64 t, %1; cvt.u32.u64 %0, t; }"
        : "=r"(a) : "l"(p));
    return a;
}

static __device__ __forceinline__ uint32_t cvt_bf16x2(float a, float b) {
    uint32_t r;
    asm("cvt.rn.bf16x2.f32 %0, %1, %2;" : "=r"(r) : "f"(b), "f"(a));
    return r;
}

#define LDSM4(r, addr) \
    asm volatile("ldmatrix.sync.aligned.m8n8.x4.shared.b16 {%0,%1,%2,%3}, [%4];" \
        : "=r"((r)[0]), "=r"((r)[1]), "=r"((r)[2]), "=r"((r)[3]) : "r"(addr))

#define MMA(d, a, b0v, b1v) \
    asm volatile("mma.sync.aligned.m16n8k16.row.col.f32.bf16.bf16.f32 " \
        "{%0,%1,%2,%3}, {%4,%5,%6,%7}, {%8,%9}, {%0,%1,%2,%3};" \
        : "+f"((d)[0]), "+f"((d)[1]), "+f"((d)[2]), "+f"((d)[3]) \
        : "r"((a)[0]), "r"((a)[1]), "r"((a)[2]), "r"((a)[3]), "r"(b0v), "r"(b1v))

#define CP_ASYNC16(sp, gp) \
    asm volatile("cp.async.cg.shared.global [%0], [%1], 16;" :: "r"(sp), "l"(gp))
#define CP_COMMIT() asm volatile("cp.async.commit_group;" ::: "memory")
#define CP_WAIT2()  asm volatile("cp.async.wait_group 2;" ::: "memory")
#define CP_WAIT1()  asm volatile("cp.async.wait_group 1;" ::: "memory")

#define LOG2E 1.4426950408889634f

// ===================== scratch (device globals) =============================
__device__ float g_cq   [(size_t)SQ * PR];      // unused fp32 (kept for layout)
__device__ float g_q    [(size_t)SQ * DM];
__device__ float g_knope[(size_t)SQ * PR];
__device__ float g_v    [(size_t)SQ * DM];
__device__ float g_krope[(size_t)SQ * RP];
__device__ float g_scores[(size_t)NH * SQ * SQ];          // 512 MB
__device__ float2 g_stats[(size_t)NH * SQ];               // row max, 1/sum

// split activations (A operands, row-major [M,K])
__device__ __nv_bfloat16 g_xa_hi [(size_t)SQ * DM],  g_xa_lo [(size_t)SQ * DM];
__device__ __nv_bfloat16 g_cq_hi [(size_t)SQ * PR],  g_cq_lo [(size_t)SQ * PR];
__device__ __nv_bfloat16 g_ckv_hi[(size_t)SQ * PR],  g_ckv_lo[(size_t)SQ * PR];
__device__ __nv_bfloat16 g_qa_hi [(size_t)SQ * DM],  g_qa_lo [(size_t)SQ * DM];
__device__ __nv_bfloat16 g_ao_hi [(size_t)SQ * DM],  g_ao_lo [(size_t)SQ * DM];

// split, transposed B operands ([N,K] K-major)
__device__ __nv_bfloat16 g_wdq_hi [(size_t)PR * DM],  g_wdq_lo [(size_t)PR * DM];
__device__ __nv_bfloat16 g_wuq_hi [(size_t)DM * PR],  g_wuq_lo [(size_t)DM * PR];
__device__ __nv_bfloat16 g_wdkv_hi[(size_t)PR * DM],  g_wdkv_lo[(size_t)PR * DM];
__device__ __nv_bfloat16 g_wuk_hi [(size_t)PR * PR],  g_wuk_lo [(size_t)PR * PR];
__device__ __nv_bfloat16 g_wuv_hi [(size_t)DM * PR],  g_wuv_lo [(size_t)DM * PR];
__device__ __nv_bfloat16 g_wkr_hi [(size_t)RP * DM],  g_wkr_lo [(size_t)RP * DM];
__device__ __nv_bfloat16 g_wo_hi  [(size_t)DM * DM],  g_wo_lo  [(size_t)DM * DM];
__device__ __nv_bfloat16 g_kh_hi  [(size_t)NH * SQ * DH], g_kh_lo [(size_t)NH * SQ * DH];
__device__ __nv_bfloat16 g_vt_hi  [(size_t)NH * DH * SQ], g_vt_lo [(size_t)NH * DH * SQ];

// ===================== split-bf16 HMMA GEMM =================================
// C = alpha * A @ B^T (+bias).  A: split bf16 hi/lo [M,K] row-major.
// B: split bf16 hi/lo [N,K] K-major.  3-term: AhBh + AhBl + AlBh.
// CTA tile 128x128, BK=32, 8 warps (2x4), warp tile 64x32, 3-stage cp.async.
#define STAGE_BYTES 40960              // 4 matrices * 128 rows * 80 B
#define GEMM_SMEM   (3 * STAGE_BYTES)  // 122880
#define PV_SMEM     (2 * STAGE_BYTES)  // 81920

__global__ void __launch_bounds__(256, 1)
gemm_bf16(const __nv_bfloat16* __restrict__ Ahi, const __nv_bfloat16* __restrict__ Alo,
          const __nv_bfloat16* __restrict__ Bhi, const __nv_bfloat16* __restrict__ Blo,
          float* __restrict__ Cf,
          __nv_bfloat16* __restrict__ Chi, __nv_bfloat16* __restrict__ Clo,
          int M, int N, int K, int lda, int ldb, int ldc,
          long long sA, long long sB, long long sC,
          float alpha, const float* __restrict__ bias)
{
    extern __shared__ char smem[];
    const uint32_t sbase = smem_u32(smem);
    const int tid  = threadIdx.x;
    const int lane = tid & 31;
    const int w    = tid >> 5;
    const int wm   = w & 1;
    const int wn   = w >> 1;

    const long long z = blockIdx.z;
    Ahi += z * sA;  Alo += z * sA;
    Bhi += z * sB;  Blo += z * sB;
    if (Cf)  Cf  += z * sC;
    if (Chi) { Chi += z * sC; Clo += z * sC; }

    const int m0 = blockIdx.y * 128;
    const int n0 = blockIdx.x * 128;
    const int nk = K >> 5;

    const int lr   = tid >> 2;
    const int lcol = tid & 3;

    auto load_stage = [&](int kt, int slot) {
        const int k0 = kt << 5;
        const uint32_t sb = sbase + slot * STAGE_BYTES;
#pragma unroll
        for (int i = 0; i < 8; ++i) {
            const int r   = ((i & 1) << 6) + lr;
            const int mat = i >> 1;
            const __nv_bfloat16* gp;
            if (mat < 2) {
                const __nv_bfloat16* base = (mat == 0) ? Ahi : Alo;
                gp = base + (long long)(m0 + r) * lda + k0 + lcol * 8;
            } else {
                int rn = n0 + r; if (rn >= N) rn = N - 1;
                const __nv_bfloat16* base = (mat == 2) ? Bhi : Blo;
                gp = base + (long long)rn * ldb + k0 + lcol * 8;
            }
            const uint32_t sp = sb + mat * 10240 + r * 80 + lcol * 16;
            CP_ASYNC16(sp, gp);
        }
        CP_COMMIT();
    };

    const uint32_t aOff = (uint32_t)((wm * 64 + (lane & 15)) * 80 + ((lane >> 4) & 1) * 16);
    const uint32_t bOff = (uint32_t)((wn * 32 + ((lane >> 4) & 1) * 8 + (lane & 7)) * 80
                                     + ((lane >> 3) & 1) * 16);

    float acc[4][4][4];
#pragma unroll
    for (int a = 0; a < 4; a++)
#pragma unroll
        for (int b = 0; b < 4; b++)
#pragma unroll
            for (int c = 0; c < 4; c++) acc[a][b][c] = 0.0f;

    load_stage(0, 0);
    if (nk > 1) load_stage(1, 1); else CP_COMMIT();

    for (int kt = 0; kt < nk; ++kt) {
        if (kt + 2 < nk) load_stage(kt + 2, (kt + 2) % 3);
        else CP_COMMIT();
        CP_WAIT2();
        __syncthreads();

        const uint32_t sb = sbase + (kt % 3) * STAGE_BYTES;
#pragma unroll
        for (int kk = 0; kk < 2; ++kk) {
            uint32_t ah[4][4], al[4][4], bh[2][4], bl[2][4];
#pragma unroll
            for (int mt = 0; mt < 4; ++mt) {
                const uint32_t ad = sb + aOff + mt * 1280 + kk * 32;
                LDSM4(ah[mt], ad);
                LDSM4(al[mt], ad + 10240);
            }
#pragma unroll
            for (int bt = 0; bt < 2; ++bt) {
                const uint32_t bd = sb + 20480 + bOff + bt * 1280 + kk * 32;
                LDSM4(bh[bt], bd);
                LDSM4(bl[bt], bd + 10240);
            }
#pragma unroll
            for (int mt = 0; mt < 4; ++mt)
#pragma unroll
                for (int nt = 0; nt < 4; ++nt) {
                    const int bt = nt >> 1, s2 = (nt & 1) * 2;
                    MMA(acc[mt][nt], ah[mt], bh[bt][s2], bh[bt][s2 + 1]);
                    MMA(acc[mt][nt], ah[mt], bl[bt][s2], bl[bt][s2 + 1]);
                    MMA(acc[mt][nt], al[mt], bh[bt][s2], bh[bt][s2 + 1]);
                }
        }
        __syncthreads();
    }

    const int er = lane >> 2;
    const int ec = (lane & 3) << 1;
#pragma unroll
    for (int mt = 0; mt < 4; ++mt) {
#pragma unroll
        for (int nt = 0; nt < 4; ++nt) {
            const int gr = m0 + wm * 64 + mt * 16 + er;
            const int gc = n0 + wn * 32 + nt * 8 + ec;
            if (gc >= N) continue;
            float v0 = acc[mt][nt][0] * alpha;
            float v1 = acc[mt][nt][1] * alpha;
            float v2 = acc[mt][nt][2] * alpha;
            float v3 = acc[mt][nt][3] * alpha;
            if (bias) {
                const float b0 = bias[gc], b1 = bias[gc + 1];
                v0 += b0; v1 += b1; v2 += b0; v3 += b1;
            }
            const long long o0 = (long long)gr * ldc + gc;
            const long long o1 = (long long)(gr + 8) * ldc + gc;
            if (Cf) {
                *(float2*)&Cf[o0] = make_float2(v0, v1);
                *(float2*)&Cf[o1] = make_float2(v2, v3);
            }
            if (Chi) {
                uint32_t h = cvt_bf16x2(v0, v1);
                uint32_t l = cvt_bf16x2(v0 - __uint_as_float(h << 16),
                                        v1 - __uint_as_float(h & 0xFFFF0000u));
                *(uint32_t*)&Chi[o0] = h;
                *(uint32_t*)&Clo[o0] = l;
                h = cvt_bf16x2(v2, v3);
                l = cvt_bf16x2(v2 - __uint_as_float(h << 16),
                               v3 - __uint_as_float(h & 0xFFFF0000u));
                *(uint32_t*)&Chi[o1] = h;
                *(uint32_t*)&Clo[o1] = l;
            }
        }
    }
}

// ===================== fused softmax P@V GEMM ================================
// O[h] = softmax(S[h]) @ V[h].  A path: read fp32 scores, apply
// p = exp2((s-m)*log2e)*invl in regs, split bf16 hi/lo -> SMEM (ldmatrix layout).
// B = V^T split bf16 [DH, SQ] K-major per head.  Output: split bf16 ao.
__global__ void __launch_bounds__(256, 1)
gemm_pv(const float* __restrict__ S, const float2* __restrict__ stats,
        const __nv_bfloat16* __restrict__ Bhi, const __nv_bfloat16* __restrict__ Blo,
        __nv_bfloat16* __restrict__ Chi, __nv_bfloat16* __restrict__ Clo)
{
    extern __shared__ char smem[];
    const uint32_t sbase = smem_u32(smem);
    const int tid  = threadIdx.x;
    const int lane = tid & 31;
    const int w    = tid >> 5;
    const int wm   = w & 1;
    const int wn   = w >> 1;

    const long long z = blockIdx.y;          // head
    S     += z * SQ * SQ;
    stats += z * SQ;
    Bhi   += z * (long long)DH * SQ;
    Blo   += z * (long long)DH * SQ;
    Chi   += z * DH;
    Clo   += z * DH;

    const int m0 = blockIdx.x * 128;
    const int nk = SQ >> 5;                  // 64

    // A transform mapping: 2 threads per row, 16 fp32 each
    const int arow = tid >> 1;
    const int ahalf = tid & 1;
    const float2 st = stats[m0 + arow];
    const float sm = st.x, sinvl = st.y;
    const float* arowp = S + (long long)(m0 + arow) * SQ + ahalf * 16;

    // B load mapping
    const int lr   = tid >> 2;
    const int lcol = tid & 3;

    auto cpB = [&](int kt, int slot) {
        const int k0 = kt << 5;
        const uint32_t sb = sbase + slot * STAGE_BYTES;
#pragma unroll
        for (int i = 0; i < 4; ++i) {
            const int r   = ((i & 1) << 6) + lr;     // d row 0..127
            const int mat = 2 + (i >> 1);            // 2:Bh 3:Bl
            const __nv_bfloat16* base = (mat == 2) ? Bhi : Blo;
            const __nv_bfloat16* gp = base + (long long)r * SQ + k0 + lcol * 8;
            const uint32_t sp = sb + mat * 10240 + r * 80 + lcol * 16;
            CP_ASYNC16(sp, gp);
        }
        CP_COMMIT();
    };

    auto ldA = [&](int kt, float* reg) {
        const float* p = arowp + (kt << 5);
#pragma unroll
        for (int i = 0; i < 4; ++i)
            *(float4*)(reg + i * 4) = *(const float4*)(p + i * 4);
    };

    auto stsA = [&](int slot, const float* reg) {
        float pv[16];
#pragma unroll
        for (int i = 0; i < 16; ++i)
            pv[i] = exp2f((reg[i] - sm) * LOG2E) * sinvl;
        uint32_t hi[8], lo[8];
#pragma unroll
        for (int i = 0; i < 8; ++i) {
            const float f0 = pv[2 * i], f1 = pv[2 * i + 1];
            const uint32_t h = cvt_bf16x2(f0, f1);
            hi[i] = h;
            lo[i] = cvt_bf16x2(f0 - __uint_as_float(h << 16),
                               f1 - __uint_as_float(h & 0xFFFF0000u));
        }
        const uint32_t sb = sbase + slot * STAGE_BYTES;
        const uint32_t ha = sb + arow * 80 + ahalf * 32;
        *(uint4*)(smem + (ha - sbase))          = *(uint4*)&hi[0];
        *(uint4*)(smem + (ha - sbase) + 16)     = *(uint4*)&hi[4];
        *(uint4*)(smem + (ha - sbase) + 10240)      = *(uint4*)&lo[0];
        *(uint4*)(smem + (ha - sbase) + 10240 + 16) = *(uint4*)&lo[4];
    };

    const uint32_t aOff = (uint32_t)((wm * 64 + (lane & 15)) * 80 + ((lane >> 4) & 1) * 16);
    const uint32_t bOff = (uint32_t)((wn * 32 + ((lane >> 4) & 1) * 8 + (lane & 7)) * 80
                                     + ((lane >> 3) & 1) * 16);

    float acc[4][4][4];
#pragma unroll
    for (int a = 0; a < 4; a++)
#pragma unroll
        for (int b = 0; b < 4; b++)
#pragma unroll
            for (int c = 0; c < 4; c++) acc[a][b][c] = 0.0f;

    float cur[16], nxt[16];
    cpB(0, 0);
    ldA(0, cur);

    for (int kt = 0; kt < nk; ++kt) {
        const int slot = kt & 1;
        if (kt + 1 < nk) { cpB(kt + 1, slot ^ 1); ldA(kt + 1, nxt); }
        else CP_COMMIT();

        stsA(slot, cur);
        CP_WAIT1();
        __syncthreads();

        const uint32_t sb = sbase + slot * STAGE_BYTES;
#pragma unroll
        for (int kk = 0; kk < 2; ++kk) {
            uint32_t ah[4][4], al[4][4], bh[2][4], bl[2][4];
#pragma unroll
            for (int mt = 0; mt < 4; ++mt) {
                const uint32_t ad = sb + aOff + mt * 1280 + kk * 32;
                LDSM4(ah[mt], ad);
                LDSM4(al[mt], ad + 10240);
            }
#pragma unroll
            for (int bt = 0; bt < 2; ++bt) {
                const uint32_t bd = sb + 20480 + bOff + bt * 1280 + kk * 32;
                LDSM4(bh[bt], bd);
                LDSM4(bl[bt], bd + 10240);
            }
#pragma unroll
            for (int mt = 0; mt < 4; ++mt)
#pragma unroll
                for (int nt = 0; nt < 4; ++nt) {
                    const int bt = nt >> 1, s2 = (nt & 1) * 2;
                    MMA(acc[mt][nt], ah[mt], bh[bt][s2], bh[bt][s2 + 1]);
                    MMA(acc[mt][nt], ah[mt], bl[bt][s2], bl[bt][s2 + 1]);
                    MMA(acc[mt][nt], al[mt], bh[bt][s2], bh[bt][s2 + 1]);
                }
        }
        __syncthreads();
#pragma unroll
        for (int i = 0; i < 16; ++i) cur[i] = nxt[i];
    }

    const int er = lane >> 2;
    const int ec = (lane & 3) << 1;
#pragma unroll
    for (int mt = 0; mt < 4; ++mt) {
#pragma unroll
        for (int nt = 0; nt < 4; ++nt) {
            const int gr = m0 + wm * 64 + mt * 16 + er;
            const int gc = wn * 32 + nt * 8 + ec;
            const float v0 = acc[mt][nt][0];
            const float v1 = acc[mt][nt][1];
            const float v2 = acc[mt][nt][2];
            const float v3 = acc[mt][nt][3];
            const long long o0 = (long long)gr * DM + gc;
            const long long o1 = (long long)(gr + 8) * DM + gc;
            uint32_t h = cvt_bf16x2(v0, v1);
            uint32_t l = cvt_bf16x2(v0 - __uint_as_float(h << 16),
                                    v1 - __uint_as_float(h & 0xFFFF0000u));
            *(uint32_t*)&Chi[o0] = h;
            *(uint32_t*)&Clo[o0] = l;
            h = cvt_bf16x2(v2, v3);
            l = cvt_bf16x2(v2 - __uint_as_float(h << 16),
                           v3 - __uint_as_float(h & 0xFFFF0000u));
            *(uint32_t*)&Chi[o1] = h;
            *(uint32_t*)&Clo[o1] = l;
        }
    }
}

// ===================== row stats (max + 1/sum of exp) ========================
__global__ void rowstats(const float* __restrict__ scores, float2* __restrict__ stats)
{
    const int row = blockIdx.x;
    const int h   = blockIdx.y;
    const float* p = scores + ((size_t)h * SQ + row) * SQ;
    const int tid = threadIdx.x;
    __shared__ float red[256];

    float vals[8];
    float m = -1e30f;
#pragma unroll
    for (int i = 0; i < 8; ++i) {
        vals[i] = p[tid + i * 256];
        m = fmaxf(m, vals[i]);
    }
    red[tid] = m; __syncthreads();
    for (int s = 128; s > 0; s >>= 1) {
        if (tid < s) red[tid] = fmaxf(red[tid], red[tid + s]);
        __syncthreads();
    }
    m = red[0]; __syncthreads();

    float sum = 0.0f;
#pragma unroll
    for (int i = 0; i < 8; ++i)
        sum += exp2f((vals[i] - m) * LOG2E);
    red[tid] = sum; __syncthreads();
    for (int s = 128; s > 0; s >>= 1) {
        if (tid < s) red[tid] += red[tid + s];
        __syncthreads();
    }
    if (tid == 0)
        stats[(size_t)h * SQ + row] = make_float2(m, 1.0f / red[0]);
}

// ===================== elementwise split fp32 -> bf16 hi/lo ==================
__global__ void split_f32(const float4* __restrict__ in,
                          uint2* __restrict__ hi, uint2* __restrict__ lo, int n4)
{
    const int i = blockIdx.x * blockDim.x + threadIdx.x;
    if (i >= n4) return;
    const float4 f = in[i];
    const uint32_t h01 = cvt_bf16x2(f.x, f.y);
    const uint32_t h23 = cvt_bf16x2(f.z, f.w);
    const uint32_t l01 = cvt_bf16x2(f.x - __uint_as_float(h01 << 16),
                                    f.y - __uint_as_float(h01 & 0xFFFF0000u));
    const uint32_t l23 = cvt_bf16x2(f.z - __uint_as_float(h23 << 16),
                                    f.w - __uint_as_float(h23 & 0xFFFF0000u));
    hi[i] = make_uint2(h01, h23);
    lo[i] = make_uint2(l01, l23);
}

// ===================== transpose + split fp32 -> bf16 hi/lo =================
__global__ void transpose_split(const float* __restrict__ in,
                                __nv_bfloat16* __restrict__ ohi,
                                __nv_bfloat16* __restrict__ olo,
                                int R, int C, int ldin, int ldout,
                                long long sIn, long long sOut)
{
    __shared__ float t[32][33];
    const long long z = blockIdx.z;
    in += z * sIn;  ohi += z * sOut;  olo += z * sOut;
    const int c0 = blockIdx.x * 32, r0 = blockIdx.y * 32;
    const int tx = threadIdx.x, ty = threadIdx.y;
#pragma unroll
    for (int j = 0; j < 32; j += 8)
        t[ty + j][tx] = in[(long long)(r0 + ty + j) * ldin + c0 + tx];
    __syncthreads();
#pragma unroll
    for (int j = 0; j < 32; j += 8) {
        const float f = t[tx][ty + j];
        const __nv_bfloat16 h = __float2bfloat16(f);
        const __nv_bfloat16 l = __float2bfloat16(f - __bfloat162float(h));
        const long long o = (long long)(c0 + ty + j) * ldout + r0 + tx;
        ohi[o] = h;  olo[o] = l;
    }
}

// ===================== RoPE ==================================================
__device__ __forceinline__ void rope_pair(float* base, int i, int pos)
{
    const float f = __expf(-(2.0f * (float)i / 128.0f) * 9.210340371976184f);
    const float ang = (float)pos * f;
    const float c = cosf(ang), s = sinf(ang);
    const float a = base[i];
    const float b = base[i + 32];
    base[i]      = a * c - b * s;
    base[i + 32] = b * c + a * s;
}

__global__ void rope_q_kernel(float* q, const int* past)
{
    const int idx = blockIdx.x * blockDim.x + threadIdx.x;
    if (idx >= SQ * NH * 32) return;
    const int s = idx / (NH * 32);
    const int r = idx % (NH * 32);
    rope_pair(q + (size_t)s * DM + (r / 32) * DH + 64, r % 32, past[0] + s);
}

__global__ void rope_k_kernel(float* krope, const int* past)
{
    const int idx = blockIdx.x * blockDim.x + threadIdx.x;
    if (idx >= SQ * 32) return;
    rope_pair(krope + (size_t)(idx / 32) * RP, idx % 32, past[0] + idx / 32);
}

// ===================== assemble K heads -> bf16 hi/lo [h][s][d] ==============
__global__ void assemble_khead_split(const float* __restrict__ knope,
                                     const float* __restrict__ krope,
                                     __nv_bfloat16* __restrict__ khi,
                                     __nv_bfloat16* __restrict__ klo)
{
    const int idx = blockIdx.x * blockDim.x + threadIdx.x;
    if (idx >= NH * SQ * DH) return;
    const int d = idx & (DH - 1);
    const int s = (idx >> 7) & (SQ - 1);
    const int h = idx >> 18;
    float v;
    if (d < 64) v = knope[(size_t)s * PR + h * 64 + d];
    else        v = krope[(size_t)s * RP + (d - 64)];
    const __nv_bfloat16 hb = __float2bfloat16(v);
    khi[idx] = hb;
    klo[idx] = __float2bfloat16(v - __bfloat162float(hb));
}

// ===================== launch ================================================
extern "C" void kernel_launch(void* const* d_in, const int* in_sizes, int n_in,
                              void* d_out, int out_size)
{
    const float* x        = (const float*)d_in[0];
    const float* W_DQ     = (const float*)d_in[1];
    const float* W_UQ     = (const float*)d_in[2];
    const float* W_DKV    = (const float*)d_in[3];
    const float* W_UK     = (const float*)d_in[4];
    const float* W_UV     = (const float*)d_in[5];
    const float* W_K_rope = (const float*)d_in[6];
    const float* W_O      = (const float*)d_in[7];
    const float* b_O      = (const float*)d_in[8];
    const int*   past     = (const int*)d_in[9];
    float* out = (float*)d_out;

    float *q, *knope, *v, *krope, *scores;
    float2* stats;
    cudaGetSymbolAddress((void**)&q,      g_q);
    cudaGetSymbolAddress((void**)&knope,  g_knope);
    cudaGetSymbolAddress((void**)&v,      g_v);
    cudaGetSymbolAddress((void**)&krope,  g_krope);
    cudaGetSymbolAddress((void**)&scores, g_scores);
    cudaGetSymbolAddress((void**)&stats,  g_stats);

    __nv_bfloat16 *xa_h, *xa_l, *cq_h, *cq_l, *ckv_h, *ckv_l, *qa_h, *qa_l,
                  *ao_h, *ao_l,
                  *wdq_h, *wdq_l, *wuq_h, *wuq_l, *wdkv_h, *wdkv_l,
                  *wuk_h, *wuk_l, *wuv_h, *wuv_l, *wkr_h, *wkr_l,
                  *wo_h, *wo_l, *kh_h, *kh_l, *vt_h, *vt_l;
    cudaGetSymbolAddress((void**)&xa_h,  g_xa_hi);  cudaGetSymbolAddress((void**)&xa_l,  g_xa_lo);
    cudaGetSymbolAddress((void**)&cq_h,  g_cq_hi);  cudaGetSymbolAddress((void**)&cq_l,  g_cq_lo);
    cudaGetSymbolAddress((void**)&ckv_h, g_ckv_hi); cudaGetSymbolAddress((void**)&ckv_l, g_ckv_lo);
    cudaGetSymbolAddress((void**)&qa_h,  g_qa_hi);  cudaGetSymbolAddress((void**)&qa_l,  g_qa_lo);
    cudaGetSymbolAddress((void**)&ao_h,  g_ao_hi);  cudaGetSymbolAddress((void**)&ao_l,  g_ao_lo);
    cudaGetSymbolAddress((void**)&wdq_h,  g_wdq_hi);  cudaGetSymbolAddress((void**)&wdq_l,  g_wdq_lo);
    cudaGetSymbolAddress((void**)&wuq_h,  g_wuq_hi);  cudaGetSymbolAddress((void**)&wuq_l,  g_wuq_lo);
    cudaGetSymbolAddress((void**)&wdkv_h, g_wdkv_hi); cudaGetSymbolAddress((void**)&wdkv_l, g_wdkv_lo);
    cudaGetSymbolAddress((void**)&wuk_h,  g_wuk_hi);  cudaGetSymbolAddress((void**)&wuk_l,  g_wuk_lo);
    cudaGetSymbolAddress((void**)&wuv_h,  g_wuv_hi);  cudaGetSymbolAddress((void**)&wuv_l,  g_wuv_lo);
    cudaGetSymbolAddress((void**)&wkr_h,  g_wkr_hi);  cudaGetSymbolAddress((void**)&wkr_l,  g_wkr_lo);
    cudaGetSymbolAddress((void**)&wo_h,   g_wo_hi);   cudaGetSymbolAddress((void**)&wo_l,   g_wo_lo);
    cudaGetSymbolAddress((void**)&kh_h,   g_kh_hi);   cudaGetSymbolAddress((void**)&kh_l,   g_kh_lo);
    cudaGetSymbolAddress((void**)&vt_h,   g_vt_hi);   cudaGetSymbolAddress((void**)&vt_l,   g_vt_lo);

    cudaFuncSetAttribute(gemm_bf16, cudaFuncAttributeMaxDynamicSharedMemorySize, GEMM_SMEM);
    cudaFuncSetAttribute(gemm_pv,   cudaFuncAttributeMaxDynamicSharedMemorySize, PV_SMEM);

    const dim3 blk(256);
    const dim3 tb(32, 8);

    // launches 0-4 (setup) so ncu -s 5 profiles the first big GEMM
    split_f32<<<(SQ * DM / 4 + 255) / 256, blk>>>(
        (const float4*)x, (uint2*)xa_h, (uint2*)xa_l, SQ * DM / 4);              // 0
    transpose_split<<<dim3(PR / 32, DM / 32, 1), tb>>>(W_DQ,  wdq_h,  wdq_l,  DM, PR, PR, DM, 0, 0); // 1
    transpose_split<<<dim3(DM / 32, PR / 32, 1), tb>>>(W_UQ,  wuq_h,  wuq_l,  PR, DM, DM, PR, 0, 0); // 2
    transpose_split<<<dim3(PR / 32, DM / 32, 1), tb>>>(W_DKV, wdkv_h, wdkv_l, DM, PR, PR, DM, 0, 0); // 3
    transpose_split<<<dim3(PR / 32, PR / 32, 1), tb>>>(W_UK,  wuk_h,  wuk_l,  PR, PR, PR, PR, 0, 0); // 4

    // 5: cq = x @ W_DQ (split output) — PROFILED
    gemm_bf16<<<dim3(PR / 128, SQ / 128, 1), blk, GEMM_SMEM>>>(
        xa_h, xa_l, wdq_h, wdq_l, nullptr, cq_h, cq_l,
        SQ, PR, DM, DM, DM, PR, 0, 0, 0, 1.0f, nullptr);

    // remaining weight preps
    transpose_split<<<dim3(DM / 32, PR / 32, 1), tb>>>(W_UV,  wuv_h,  wuv_l,  PR, DM, DM, PR, 0, 0);
    transpose_split<<<dim3(RP / 32, DM / 32, 1), tb>>>(W_K_rope, wkr_h, wkr_l, DM, RP, RP, DM, 0, 0);
    transpose_split<<<dim3(DM / 32, DM / 32, 1), tb>>>(W_O,   wo_h,   wo_l,   DM, DM, DM, DM, 0, 0);

    // ckv = x @ W_DKV (split output)
    gemm_bf16<<<dim3(PR / 128, SQ / 128, 1), blk, GEMM_SMEM>>>(
        xa_h, xa_l, wdkv_h, wdkv_l, nullptr, ckv_h, ckv_l,
        SQ, PR, DM, DM, DM, PR, 0, 0, 0, 1.0f, nullptr);
    // krope = x @ W_K_rope (fp32, N=64)
    gemm_bf16<<<dim3(1, SQ / 128, 1), blk, GEMM_SMEM>>>(
        xa_h, xa_l, wkr_h, wkr_l, krope, nullptr, nullptr,
        SQ, RP, DM, DM, DM, RP, 0, 0, 0, 1.0f, nullptr);
    // q = cq @ W_UQ (fp32 — rope needs it)
    gemm_bf16<<<dim3(DM / 128, SQ / 128, 1), blk, GEMM_SMEM>>>(
        cq_h, cq_l, wuq_h, wuq_l, q, nullptr, nullptr,
        SQ, DM, PR, PR, PR, DM, 0, 0, 0, 1.0f, nullptr);
    // knope = ckv @ W_UK (fp32)
    gemm_bf16<<<dim3(PR / 128, SQ / 128, 1), blk, GEMM_SMEM>>>(
        ckv_h, ckv_l, wuk_h, wuk_l, knope, nullptr, nullptr,
        SQ, PR, PR, PR, PR, PR, 0, 0, 0, 1.0f, nullptr);
    // v = ckv @ W_UV (fp32)
    gemm_bf16<<<dim3(DM / 128, SQ / 128, 1), blk, GEMM_SMEM>>>(
        ckv_h, ckv_l, wuv_h, wuv_l, v, nullptr, nullptr,
        SQ, DM, PR, PR, PR, DM, 0, 0, 0, 1.0f, nullptr);

    // RoPE + operand prep
    rope_q_kernel<<<(SQ * NH * 32 + 255) / 256, blk>>>(q, past);
    rope_k_kernel<<<(SQ * 32 + 255) / 256, blk>>>(krope, past);
    split_f32<<<(SQ * DM / 4 + 255) / 256, blk>>>(
        (const float4*)q, (uint2*)qa_h, (uint2*)qa_l, SQ * DM / 4);
    assemble_khead_split<<<(NH * SQ * DH + 255) / 256, blk>>>(knope, krope, kh_h, kh_l);
    transpose_split<<<dim3(DH / 32, SQ / 32, NH), tb>>>(
        v, vt_h, vt_l, SQ, DH, DM, SQ, (long long)DH, (long long)DH * SQ);

    // scores[h] = (Q_h @ K_h^T) / sqrt(128)  (fp32)
    const float alpha = 0.08838834764831845f;
    gemm_bf16<<<dim3(SQ / 128, SQ / 128, NH), blk, GEMM_SMEM>>>(
        qa_h, qa_l, kh_h, kh_l, scores, nullptr, nullptr,
        SQ, SQ, DH, DM, DH, SQ,
        (long long)DH, (long long)SQ * DH, (long long)SQ * SQ, alpha, nullptr);

    // row stats (max, 1/sum)
    rowstats<<<dim3(SQ, NH), blk>>>(scores, stats);

    // fused softmax + P@V -> split bf16 ao [s][h*DH]
    gemm_pv<<<dim3(SQ / 128, NH), blk, PV_SMEM>>>(
        scores, stats, vt_h, vt_l, ao_h, ao_l);

    // out = attno @ W_O + b_O (fp32)
    gemm_bf16<<<dim3(DM / 128, SQ / 128, 1), blk, GEMM_SMEM>>>(
        ao_h, ao_l, wo_h, wo_l, out, nullptr, nullptr,
        SQ, DM, DM, DM, DM, DM, 0, 0, 0, 1.0f, b_O);
}

// round 6
// speedup vs baseline: 2.5349x; 1.3123x over previous
#include <cuda_runtime.h>
#include <cuda_bf16.h>
#include <cuda_fp16.h>
#include <cstdint>
#include <math.h>

#define SQ   2048
#define DM   4096
#define PR   2048
#define NH   32
#define DH   128
#define RP   64

#define LOG2E  1.4426950408889634f
#define INV512 0.001953125f

// ===================== small helpers ========================================
static __device__ __forceinline__ uint32_t smem_u32(const void* p) {
    uint32_t a;
    asm("{ .reg .u64 t; cvta.to.shared.u64 t, %1; cvt.u32.u64 %0, t; }"
        : "=r"(a) : "l"(p));
    return a;
}

// pack two floats -> fp16x2 (lo half = a, hi half = b)
static __device__ __forceinline__ uint32_t cvt_f16x2(float a, float b) {
    uint32_t r;
    asm("cvt.rn.f16x2.f32 %0, %1, %2;" : "=r"(r) : "f"(b), "f"(a));
    return r;
}

#define LDSM4(r, addr) \
    asm volatile("ldmatrix.sync.aligned.m8n8.x4.shared.b16 {%0,%1,%2,%3}, [%4];" \
        : "=r"((r)[0]), "=r"((r)[1]), "=r"((r)[2]), "=r"((r)[3]) : "r"(addr))

#define MMA16(d, a, b0v, b1v) \
    asm volatile("mma.sync.aligned.m16n8k16.row.col.f32.f16.f16.f32 " \
        "{%0,%1,%2,%3}, {%4,%5,%6,%7}, {%8,%9}, {%0,%1,%2,%3};" \
        : "+f"((d)[0]), "+f"((d)[1]), "+f"((d)[2]), "+f"((d)[3]) \
        : "r"((a)[0]), "r"((a)[1]), "r"((a)[2]), "r"((a)[3]), "r"(b0v), "r"(b1v))

#define CP_ASYNC16(sp, gp) \
    asm volatile("cp.async.cg.shared.global [%0], [%1], 16;" :: "r"(sp), "l"(gp))
#define CP_COMMIT() asm volatile("cp.async.commit_group;" ::: "memory")
#define CP_WAIT3()  asm volatile("cp.async.wait_group 3;" ::: "memory")

// ===================== scratch (device globals) =============================
__device__ float g_q    [(size_t)SQ * DM];
__device__ float g_knope[(size_t)SQ * PR];
__device__ float g_v    [(size_t)SQ * DM];
__device__ float g_krope[(size_t)SQ * RP];
__device__ float g_scores[(size_t)NH * SQ * SQ];          // 512 MB

// single-fp16 activations (A operands)
__device__ __half g_xf  [(size_t)SQ * DM];
__device__ __half g_cqf [(size_t)SQ * PR];
__device__ __half g_ckvf[(size_t)SQ * PR];
__device__ __half g_qf  [(size_t)SQ * DM];
__device__ __half g_aof [(size_t)SQ * DM];
__device__ __half g_pf  [(size_t)NH * SQ * SQ];           // 256 MB

// 2-limb fp16 B operands ([N,K] K-major; lo limb pre-scaled x512)
__device__ __half g_wdq_h [(size_t)PR * DM],  g_wdq_l [(size_t)PR * DM];
__device__ __half g_wuq_h [(size_t)DM * PR],  g_wuq_l [(size_t)DM * PR];
__device__ __half g_wdkv_h[(size_t)PR * DM],  g_wdkv_l[(size_t)PR * DM];
__device__ __half g_wuk_h [(size_t)PR * PR],  g_wuk_l [(size_t)PR * PR];
__device__ __half g_wuv_h [(size_t)DM * PR],  g_wuv_l [(size_t)DM * PR];
__device__ __half g_wkr_h [(size_t)RP * DM],  g_wkr_l [(size_t)RP * DM];
__device__ __half g_wo_h  [(size_t)DM * DM],  g_wo_l  [(size_t)DM * DM];
__device__ __half g_kh_h  [(size_t)NH * SQ * DH], g_kh_l [(size_t)NH * SQ * DH];
__device__ __half g_vt_h  [(size_t)NH * DH * SQ], g_vt_l [(size_t)NH * DH * SQ];

// ===================== 2-term split-fp16 HMMA GEMM ==========================
// C = alpha * A @ B^T (+bias).  A: single fp16 [M,K] row-major.
// B: 2-limb fp16 [N,K] K-major (Bl pre-scaled x512).
// acc = A*Bh + (A*Bl)/512.  CTA 128x128, BK=32, 8 warps (2x4), 4-stage cp.async.
#define STAGE_BYTES 30720              // 3 matrices * 128 rows * 80 B
#define GEMM_SMEM   (4 * STAGE_BYTES)  // 122880

__global__ void __launch_bounds__(256, 1)
gemm_f16(const __half* __restrict__ Af,
         const __half* __restrict__ Bh, const __half* __restrict__ Bl,
         float* __restrict__ Cf, __half* __restrict__ Ch,
         int M, int N, int K, int lda, int ldb, int ldc,
         long long sA, long long sB, long long sC,
         float alpha, const float* __restrict__ bias)
{
    extern __shared__ char smem[];
    const uint32_t sbase = smem_u32(smem);
    const int tid  = threadIdx.x;
    const int lane = tid & 31;
    const int w    = tid >> 5;
    const int wm   = w & 1;        // M dir (2)
    const int wn   = w >> 1;       // N dir (4)

    const long long z = blockIdx.z;
    Af += z * sA;
    Bh += z * sB;  Bl += z * sB;
    if (Cf) Cf += z * sC;
    if (Ch) Ch += z * sC;

    const int m0 = blockIdx.y * 128;
    const int n0 = blockIdx.x * 128;
    const int nk = K >> 5;

    const int lr   = tid >> 2;        // 0..63
    const int lcol = tid & 3;         // 0..3

    auto load_stage = [&](int kt, int slot) {
        const int k0 = kt << 5;
        const uint32_t sb = sbase + slot * STAGE_BYTES;
        // A: 128 rows x 64B
#pragma unroll
        for (int i = 0; i < 2; ++i) {
            const int r = lr + i * 64;
            const __half* gp = Af + (long long)(m0 + r) * lda + k0 + lcol * 8;
            CP_ASYNC16(sb + r * 80 + lcol * 16, gp);
        }
        // Bh, Bl: 128 rows x 64B each
#pragma unroll
        for (int j = 0; j < 4; ++j) {
            const int mat = 1 + (j >> 1);          // 1:Bh 2:Bl
            const int r   = lr + (j & 1) * 64;
            int rn = n0 + r; if (rn >= N) rn = N - 1;
            const __half* base = (mat == 1) ? Bh : Bl;
            const __half* gp = base + (long long)rn * ldb + k0 + lcol * 8;
            CP_ASYNC16(sb + mat * 10240 + r * 80 + lcol * 16, gp);
        }
        CP_COMMIT();
    };

    const uint32_t aOff = (uint32_t)((wm * 64 + (lane & 15)) * 80 + ((lane >> 4) & 1) * 16);
    const uint32_t bOff = (uint32_t)((wn * 32 + ((lane >> 4) & 1) * 8 + (lane & 7)) * 80
                                     + ((lane >> 3) & 1) * 16);

    float acc1[4][4][4], acc2[4][4][4];
#pragma unroll
    for (int a = 0; a < 4; a++)
#pragma unroll
        for (int b = 0; b < 4; b++)
#pragma unroll
            for (int c = 0; c < 4; c++) { acc1[a][b][c] = 0.0f; acc2[a][b][c] = 0.0f; }

    load_stage(0, 0);
    if (nk > 1) load_stage(1, 1); else CP_COMMIT();
    if (nk > 2) load_stage(2, 2); else CP_COMMIT();

    for (int kt = 0; kt < nk; ++kt) {
        if (kt + 3 < nk) load_stage(kt + 3, (kt + 3) & 3);
        else CP_COMMIT();
        CP_WAIT3();
        __syncthreads();

        const uint32_t sb = sbase + (kt & 3) * STAGE_BYTES;
#pragma unroll
        for (int kk = 0; kk < 2; ++kk) {
            uint32_t af[4][4], bh[2][4], bl[2][4];
#pragma unroll
            for (int mt = 0; mt < 4; ++mt)
                LDSM4(af[mt], sb + aOff + mt * 1280 + kk * 32);
#pragma unroll
            for (int bt = 0; bt < 2; ++bt) {
                const uint32_t bd = sb + 10240 + bOff + bt * 1280 + kk * 32;
                LDSM4(bh[bt], bd);
                LDSM4(bl[bt], bd + 10240);
            }
#pragma unroll
            for (int mt = 0; mt < 4; ++mt)
#pragma unroll
                for (int nt = 0; nt < 4; ++nt) {
                    const int bt = nt >> 1, s2 = (nt & 1) * 2;
                    MMA16(acc1[mt][nt], af[mt], bh[bt][s2], bh[bt][s2 + 1]);
                    MMA16(acc2[mt][nt], af[mt], bl[bt][s2], bl[bt][s2 + 1]);
                }
        }
        __syncthreads();
    }

    const int er = lane >> 2;
    const int ec = (lane & 3) << 1;
#pragma unroll
    for (int mt = 0; mt < 4; ++mt) {
#pragma unroll
        for (int nt = 0; nt < 4; ++nt) {
            const int gr = m0 + wm * 64 + mt * 16 + er;
            const int gc = n0 + wn * 32 + nt * 8 + ec;
            if (gc >= N) continue;
            float v0 = (acc1[mt][nt][0] + acc2[mt][nt][0] * INV512) * alpha;
            float v1 = (acc1[mt][nt][1] + acc2[mt][nt][1] * INV512) * alpha;
            float v2 = (acc1[mt][nt][2] + acc2[mt][nt][2] * INV512) * alpha;
            float v3 = (acc1[mt][nt][3] + acc2[mt][nt][3] * INV512) * alpha;
            if (bias) {
                const float b0 = bias[gc], b1 = bias[gc + 1];
                v0 += b0; v1 += b1; v2 += b0; v3 += b1;
            }
            const long long o0 = (long long)gr * ldc + gc;
            const long long o1 = (long long)(gr + 8) * ldc + gc;
            if (Cf) {
                *(float2*)&Cf[o0] = make_float2(v0, v1);
                *(float2*)&Cf[o1] = make_float2(v2, v3);
            }
            if (Ch) {
                *(uint32_t*)&Ch[o0] = cvt_f16x2(v0, v1);
                *(uint32_t*)&Ch[o1] = cvt_f16x2(v2, v3);
            }
        }
    }
}

// ===================== fp32 -> fp16 convert ==================================
__global__ void conv_f16(const float4* __restrict__ in, uint2* __restrict__ o, int n4)
{
    const int i = blockIdx.x * blockDim.x + threadIdx.x;
    if (i >= n4) return;
    const float4 f = in[i];
    o[i] = make_uint2(cvt_f16x2(f.x, f.y), cvt_f16x2(f.z, f.w));
}

// ===================== transpose + 2-limb fp16 quant ========================
// in [K,N] fp32 -> out [N,K]: hi = fp16(w), lo = fp16((w-hi)*512)
__global__ void transpose_quant16(const float* __restrict__ in,
                                  __half* __restrict__ ohi, __half* __restrict__ olo,
                                  int ldin, int ldout)
{
    __shared__ float t[32][33];
    const int c0 = blockIdx.x * 32, r0 = blockIdx.y * 32;
    const int tx = threadIdx.x, ty = threadIdx.y;
#pragma unroll
    for (int j = 0; j < 32; j += 8)
        t[ty + j][tx] = in[(long long)(r0 + ty + j) * ldin + c0 + tx];
    __syncthreads();
#pragma unroll
    for (int j = 0; j < 32; j += 8) {
        const float f = t[tx][ty + j];
        const __half h = __float2half_rn(f);
        const __half l = __float2half_rn((f - __half2float(h)) * 512.0f);
        const long long o = (long long)(c0 + ty + j) * ldout + r0 + tx;
        ohi[o] = h;  olo[o] = l;
    }
}

// per-head V transpose: v fp32 [s][h*128+d] -> vt [h][d][s] 2-limb fp16
__global__ void transpose_v16(const float* __restrict__ in,
                              __half* __restrict__ ohi, __half* __restrict__ olo)
{
    __shared__ float t[32][33];
    const long long z = blockIdx.z;
    in  += z * DH;
    ohi += z * (long long)DH * SQ;
    olo += z * (long long)DH * SQ;
    const int c0 = blockIdx.x * 32, r0 = blockIdx.y * 32;   // c0: d, r0: s
    const int tx = threadIdx.x, ty = threadIdx.y;
#pragma unroll
    for (int j = 0; j < 32; j += 8)
        t[ty + j][tx] = in[(long long)(r0 + ty + j) * DM + c0 + tx];
    __syncthreads();
#pragma unroll
    for (int j = 0; j < 32; j += 8) {
        const float f = t[tx][ty + j];
        const __half h = __float2half_rn(f);
        const __half l = __float2half_rn((f - __half2float(h)) * 512.0f);
        const long long o = (long long)(c0 + ty + j) * SQ + r0 + tx;
        ohi[o] = h;  olo[o] = l;
    }
}

// ===================== RoPE ==================================================
__device__ __forceinline__ void rope_pair(float* base, int i, int pos)
{
    const float f = __expf(-(2.0f * (float)i / 128.0f) * 9.210340371976184f);
    const float ang = (float)pos * f;
    const float c = cosf(ang), s = sinf(ang);
    const float a = base[i];
    const float b = base[i + 32];
    base[i]      = a * c - b * s;
    base[i + 32] = b * c + a * s;
}

__global__ void rope_q_kernel(float* q, const int* past)
{
    const int idx = blockIdx.x * blockDim.x + threadIdx.x;
    if (idx >= SQ * NH * 32) return;
    const int s = idx / (NH * 32);
    const int r = idx % (NH * 32);
    rope_pair(q + (size_t)s * DM + (r / 32) * DH + 64, r % 32, past[0] + s);
}

__global__ void rope_k_kernel(float* krope, const int* past)
{
    const int idx = blockIdx.x * blockDim.x + threadIdx.x;
    if (idx >= SQ * 32) return;
    rope_pair(krope + (size_t)(idx / 32) * RP, idx % 32, past[0] + idx / 32);
}

// ===================== assemble K heads -> 2-limb fp16 [h][s][d] =============
__global__ void assemble_khead16(const float* __restrict__ knope,
                                 const float* __restrict__ krope,
                                 __half* __restrict__ khi, __half* __restrict__ klo)
{
    const int idx = blockIdx.x * blockDim.x + threadIdx.x;
    if (idx >= NH * SQ * DH) return;
    const int d = idx & (DH - 1);
    const int s = (idx >> 7) & (SQ - 1);
    const int h = idx >> 18;
    float v;
    if (d < 64) v = knope[(size_t)s * PR + h * 64 + d];
    else        v = krope[(size_t)s * RP + (d - 64)];
    const __half hb = __float2half_rn(v);
    khi[idx] = hb;
    klo[idx] = __float2half_rn((v - __half2float(hb)) * 512.0f);
}

// ===================== softmax -> single fp16 P ==============================
__global__ void softmax_f16(const float* __restrict__ scores, __half* __restrict__ P)
{
    const int row = blockIdx.x;
    const int h   = blockIdx.y;
    const size_t base = ((size_t)h * SQ + row) * SQ;
    const float* p = scores + base;
    __half* op = P + base;
    const int tid = threadIdx.x;
    __shared__ float red[256];

    float vals[8];
    float m = -1e30f;
#pragma unroll
    for (int i = 0; i < 8; ++i) {
        vals[i] = p[tid + i * 256];
        m = fmaxf(m, vals[i]);
    }
    red[tid] = m; __syncthreads();
    for (int s = 128; s > 0; s >>= 1) {
        if (tid < s) red[tid] = fmaxf(red[tid], red[tid + s]);
        __syncthreads();
    }
    m = red[0]; __syncthreads();

    float sum = 0.0f;
#pragma unroll
    for (int i = 0; i < 8; ++i) {
        vals[i] = exp2f((vals[i] - m) * LOG2E);
        sum += vals[i];
    }
    red[tid] = sum; __syncthreads();
    for (int s = 128; s > 0; s >>= 1) {
        if (tid < s) red[tid] += red[tid + s];
        __syncthreads();
    }
    const float inv = 1.0f / red[0];
#pragma unroll
    for (int i = 0; i < 8; ++i)
        op[tid + i * 256] = __float2half_rn(vals[i] * inv);
}

// ===================== launch ================================================
extern "C" void kernel_launch(void* const* d_in, const int* in_sizes, int n_in,
                              void* d_out, int out_size)
{
    const float* x        = (const float*)d_in[0];
    const float* W_DQ     = (const float*)d_in[1];
    const float* W_UQ     = (const float*)d_in[2];
    const float* W_DKV    = (const float*)d_in[3];
    const float* W_UK     = (const float*)d_in[4];
    const float* W_UV     = (const float*)d_in[5];
    const float* W_K_rope = (const float*)d_in[6];
    const float* W_O      = (const float*)d_in[7];
    const float* b_O      = (const float*)d_in[8];
    const int*   past     = (const int*)d_in[9];
    float* out = (float*)d_out;

    float *q, *knope, *v, *krope, *scores;
    cudaGetSymbolAddress((void**)&q,      g_q);
    cudaGetSymbolAddress((void**)&knope,  g_knope);
    cudaGetSymbolAddress((void**)&v,      g_v);
    cudaGetSymbolAddress((void**)&krope,  g_krope);
    cudaGetSymbolAddress((void**)&scores, g_scores);

    __half *xf, *cqf, *ckvf, *qf, *aof, *pf,
           *wdq_h, *wdq_l, *wuq_h, *wuq_l, *wdkv_h, *wdkv_l,
           *wuk_h, *wuk_l, *wuv_h, *wuv_l, *wkr_h, *wkr_l,
           *wo_h, *wo_l, *kh_h, *kh_l, *vt_h, *vt_l;
    cudaGetSymbolAddress((void**)&xf,   g_xf);
    cudaGetSymbolAddress((void**)&cqf,  g_cqf);
    cudaGetSymbolAddress((void**)&ckvf, g_ckvf);
    cudaGetSymbolAddress((void**)&qf,   g_qf);
    cudaGetSymbolAddress((void**)&aof,  g_aof);
    cudaGetSymbolAddress((void**)&pf,   g_pf);
    cudaGetSymbolAddress((void**)&wdq_h,  g_wdq_h);  cudaGetSymbolAddress((void**)&wdq_l,  g_wdq_l);
    cudaGetSymbolAddress((void**)&wuq_h,  g_wuq_h);  cudaGetSymbolAddress((void**)&wuq_l,  g_wuq_l);
    cudaGetSymbolAddress((void**)&wdkv_h, g_wdkv_h); cudaGetSymbolAddress((void**)&wdkv_l, g_wdkv_l);
    cudaGetSymbolAddress((void**)&wuk_h,  g_wuk_h);  cudaGetSymbolAddress((void**)&wuk_l,  g_wuk_l);
    cudaGetSymbolAddress((void**)&wuv_h,  g_wuv_h);  cudaGetSymbolAddress((void**)&wuv_l,  g_wuv_l);
    cudaGetSymbolAddress((void**)&wkr_h,  g_wkr_h);  cudaGetSymbolAddress((void**)&wkr_l,  g_wkr_l);
    cudaGetSymbolAddress((void**)&wo_h,   g_wo_h);   cudaGetSymbolAddress((void**)&wo_l,   g_wo_l);
    cudaGetSymbolAddress((void**)&kh_h,   g_kh_h);   cudaGetSymbolAddress((void**)&kh_l,   g_kh_l);
    cudaGetSymbolAddress((void**)&vt_h,   g_vt_h);   cudaGetSymbolAddress((void**)&vt_l,   g_vt_l);

    cudaFuncSetAttribute(gemm_f16, cudaFuncAttributeMaxDynamicSharedMemorySize, GEMM_SMEM);

    const dim3 blk(256);
    const dim3 tb(32, 8);

    // x -> fp16
    conv_f16<<<(SQ * DM / 4 + 255) / 256, blk>>>(
        (const float4*)x, (uint2*)xf, SQ * DM / 4);

    // weights -> [N,K] 2-limb fp16
    transpose_quant16<<<dim3(PR / 32, DM / 32), tb>>>(W_DQ,     wdq_h,  wdq_l,  PR, DM);
    transpose_quant16<<<dim3(DM / 32, PR / 32), tb>>>(W_UQ,     wuq_h,  wuq_l,  DM, PR);
    transpose_quant16<<<dim3(PR / 32, DM / 32), tb>>>(W_DKV,    wdkv_h, wdkv_l, PR, DM);
    transpose_quant16<<<dim3(PR / 32, PR / 32), tb>>>(W_UK,     wuk_h,  wuk_l,  PR, PR);
    transpose_quant16<<<dim3(DM / 32, PR / 32), tb>>>(W_UV,     wuv_h,  wuv_l,  DM, PR);
    transpose_quant16<<<dim3(RP / 32, DM / 32), tb>>>(W_K_rope, wkr_h,  wkr_l,  RP, DM);
    transpose_quant16<<<dim3(DM / 32, DM / 32), tb>>>(W_O,      wo_h,   wo_l,   DM, DM);

    // cq = x @ W_DQ  -> fp16
    gemm_f16<<<dim3(PR / 128, SQ / 128, 1), blk, GEMM_SMEM>>>(
        xf, wdq_h, wdq_l, nullptr, cqf,
        SQ, PR, DM, DM, DM, PR, 0, 0, 0, 1.0f, nullptr);
    // ckv = x @ W_DKV -> fp16
    gemm_f16<<<dim3(PR / 128, SQ / 128, 1), blk, GEMM_SMEM>>>(
        xf, wdkv_h, wdkv_l, nullptr, ckvf,
        SQ, PR, DM, DM, DM, PR, 0, 0, 0, 1.0f, nullptr);
    // krope = x @ W_K_rope -> fp32 (N=64)
    gemm_f16<<<dim3(1, SQ / 128, 1), blk, GEMM_SMEM>>>(
        xf, wkr_h, wkr_l, krope, nullptr,
        SQ, RP, DM, DM, DM, RP, 0, 0, 0, 1.0f, nullptr);
    // q = cq @ W_UQ -> fp32 (rope needs it)
    gemm_f16<<<dim3(DM / 128, SQ / 128, 1), blk, GEMM_SMEM>>>(
        cqf, wuq_h, wuq_l, q, nullptr,
        SQ, DM, PR, PR, PR, DM, 0, 0, 0, 1.0f, nullptr);
    // knope = ckv @ W_UK -> fp32
    gemm_f16<<<dim3(PR / 128, SQ / 128, 1), blk, GEMM_SMEM>>>(
        ckvf, wuk_h, wuk_l, knope, nullptr,
        SQ, PR, PR, PR, PR, PR, 0, 0, 0, 1.0f, nullptr);
    // v = ckv @ W_UV -> fp32
    gemm_f16<<<dim3(DM / 128, SQ / 128, 1), blk, GEMM_SMEM>>>(
        ckvf, wuv_h, wuv_l, v, nullptr,
        SQ, DM, PR, PR, PR, DM, 0, 0, 0, 1.0f, nullptr);

    // RoPE + operand prep
    rope_q_kernel<<<(SQ * NH * 32 + 255) / 256, blk>>>(q, past);
    rope_k_kernel<<<(SQ * 32 + 255) / 256, blk>>>(krope, past);
    conv_f16<<<(SQ * DM / 4 + 255) / 256, blk>>>(
        (const float4*)q, (uint2*)qf, SQ * DM / 4);
    assemble_khead16<<<(NH * SQ * DH + 255) / 256, blk>>>(knope, krope, kh_h, kh_l);
    transpose_v16<<<dim3(DH / 32, SQ / 32, NH), tb>>>(v, vt_h, vt_l);

    // scores[h] = (Q_h @ K_h^T) / sqrt(128)  (fp32)
    const float alpha = 0.08838834764831845f;
    gemm_f16<<<dim3(SQ / 128, SQ / 128, NH), blk, GEMM_SMEM>>>(
        qf, kh_h, kh_l, scores, nullptr,
        SQ, SQ, DH, DM, DH, SQ,
        (long long)DH, (long long)SQ * DH, (long long)SQ * SQ, alpha, nullptr);

    // softmax -> single fp16 P
    softmax_f16<<<dim3(SQ, NH), blk>>>(scores, pf);

    // attno[h] = P_h @ V_h -> fp16 [s][h*DH]
    gemm_f16<<<dim3(1, SQ / 128, NH), blk, GEMM_SMEM>>>(
        pf, vt_h, vt_l, nullptr, aof,
        SQ, DH, SQ, SQ, SQ, DM,
        (long long)SQ * SQ, (long long)DH * SQ, (long long)DH, 1.0f, nullptr);

    // out = attno @ W_O + b_O  (fp32)
    gemm_f16<<<dim3(DM / 128, SQ / 128, 1), blk, GEMM_SMEM>>>(
        aof, wo_h, wo_l, out, nullptr,
        SQ, DM, DM, DM, DM, DM, 0, 0, 0, 1.0f, b_O);
}

// round 7
// speedup vs baseline: 2.8312x; 1.1169x over previous
#include <cuda_runtime.h>
#include <cuda_bf16.h>
#include <cuda_fp16.h>
#include <cstdint>
#include <math.h>

#define SQ   2048
#define DM   4096
#define PR   2048
#define NH   32
#define DH   128
#define RP   64

#define LOG2E  1.4426950408889634f
#define INV512 0.001953125f

// ===================== small helpers ========================================
static __device__ __forceinline__ uint32_t smem_u32(const void* p) {
    uint32_t a;
    asm("{ .reg .u64 t; cvta.to.shared.u64 t, %1; cvt.u32.u64 %0, t; }"
        : "=r"(a) : "l"(p));
    return a;
}

// pack two floats -> fp16x2 (lo half = a, hi half = b)
static __device__ __forceinline__ uint32_t cvt_f16x2(float a, float b) {
    uint32_t r;
    asm("cvt.rn.f16x2.f32 %0, %1, %2;" : "=r"(r) : "f"(b), "f"(a));
    return r;
}

#define LDSM4(r, addr) \
    asm volatile("ldmatrix.sync.aligned.m8n8.x4.shared.b16 {%0,%1,%2,%3}, [%4];" \
        : "=r"((r)[0]), "=r"((r)[1]), "=r"((r)[2]), "=r"((r)[3]) : "r"(addr))

#define MMA16(d, a, b0v, b1v) \
    asm volatile("mma.sync.aligned.m16n8k16.row.col.f32.f16.f16.f32 " \
        "{%0,%1,%2,%3}, {%4,%5,%6,%7}, {%8,%9}, {%0,%1,%2,%3};" \
        : "+f"((d)[0]), "+f"((d)[1]), "+f"((d)[2]), "+f"((d)[3]) \
        : "r"((a)[0]), "r"((a)[1]), "r"((a)[2]), "r"((a)[3]), "r"(b0v), "r"(b1v))

#define CP_ASYNC16(sp, gp) \
    asm volatile("cp.async.cg.shared.global [%0], [%1], 16;" :: "r"(sp), "l"(gp))
#define CP_COMMIT() asm volatile("cp.async.commit_group;" ::: "memory")
#define CP_WAIT3()  asm volatile("cp.async.wait_group 3;" ::: "memory")
#define CP_WAIT1()  asm volatile("cp.async.wait_group 1;" ::: "memory")

// ===================== scratch (device globals) =============================
__device__ float g_q    [(size_t)SQ * DM];
__device__ float g_knope[(size_t)SQ * PR];
__device__ float g_v    [(size_t)SQ * DM];
__device__ float g_krope[(size_t)SQ * RP];

// single-fp16 activations (A operands)
__device__ __half g_xf  [(size_t)SQ * DM];
__device__ __half g_cqf [(size_t)SQ * PR];
__device__ __half g_ckvf[(size_t)SQ * PR];
__device__ __half g_qf  [(size_t)SQ * DM];
__device__ __half g_aof [(size_t)SQ * DM];

// 2-limb fp16 B operands ([N,K] K-major; lo limb pre-scaled x512)
__device__ __half g_wdq_h [(size_t)PR * DM],  g_wdq_l [(size_t)PR * DM];
__device__ __half g_wuq_h [(size_t)DM * PR],  g_wuq_l [(size_t)DM * PR];
__device__ __half g_wdkv_h[(size_t)PR * DM],  g_wdkv_l[(size_t)PR * DM];
__device__ __half g_wuk_h [(size_t)PR * PR],  g_wuk_l [(size_t)PR * PR];
__device__ __half g_wuv_h [(size_t)DM * PR],  g_wuv_l [(size_t)DM * PR];
__device__ __half g_wkr_h [(size_t)RP * DM],  g_wkr_l [(size_t)RP * DM];
__device__ __half g_wo_h  [(size_t)DM * DM],  g_wo_l  [(size_t)DM * DM];
__device__ __half g_kh_h  [(size_t)NH * SQ * DH], g_kh_l [(size_t)NH * SQ * DH];
__device__ __half g_vt_h  [(size_t)NH * DH * SQ], g_vt_l [(size_t)NH * DH * SQ];

// ===================== 2-term split-fp16 HMMA GEMM ==========================
#define STAGE_BYTES 30720              // 3 matrices * 128 rows * 80 B
#define GEMM_SMEM   (4 * STAGE_BYTES)  // 122880

__global__ void __launch_bounds__(256, 1)
gemm_f16(const __half* __restrict__ Af,
         const __half* __restrict__ Bh, const __half* __restrict__ Bl,
         float* __restrict__ Cf, __half* __restrict__ Ch,
         int M, int N, int K, int lda, int ldb, int ldc,
         long long sA, long long sB, long long sC,
         float alpha, const float* __restrict__ bias)
{
    extern __shared__ char smem[];
    const uint32_t sbase = smem_u32(smem);
    const int tid  = threadIdx.x;
    const int lane = tid & 31;
    const int w    = tid >> 5;
    const int wm   = w & 1;
    const int wn   = w >> 1;

    const long long z = blockIdx.z;
    Af += z * sA;
    Bh += z * sB;  Bl += z * sB;
    if (Cf) Cf += z * sC;
    if (Ch) Ch += z * sC;

    const int m0 = blockIdx.y * 128;
    const int n0 = blockIdx.x * 128;
    const int nk = K >> 5;

    const int lr   = tid >> 2;
    const int lcol = tid & 3;

    auto load_stage = [&](int kt, int slot) {
        const int k0 = kt << 5;
        const uint32_t sb = sbase + slot * STAGE_BYTES;
#pragma unroll
        for (int i = 0; i < 2; ++i) {
            const int r = lr + i * 64;
            const __half* gp = Af + (long long)(m0 + r) * lda + k0 + lcol * 8;
            CP_ASYNC16(sb + r * 80 + lcol * 16, gp);
        }
#pragma unroll
        for (int j = 0; j < 4; ++j) {
            const int mat = 1 + (j >> 1);
            const int r   = lr + (j & 1) * 64;
            int rn = n0 + r; if (rn >= N) rn = N - 1;
            const __half* base = (mat == 1) ? Bh : Bl;
            const __half* gp = base + (long long)rn * ldb + k0 + lcol * 8;
            CP_ASYNC16(sb + mat * 10240 + r * 80 + lcol * 16, gp);
        }
        CP_COMMIT();
    };

    const uint32_t aOff = (uint32_t)((wm * 64 + (lane & 15)) * 80 + ((lane >> 4) & 1) * 16);
    const uint32_t bOff = (uint32_t)((wn * 32 + ((lane >> 4) & 1) * 8 + (lane & 7)) * 80
                                     + ((lane >> 3) & 1) * 16);

    float acc1[4][4][4], acc2[4][4][4];
#pragma unroll
    for (int a = 0; a < 4; a++)
#pragma unroll
        for (int b = 0; b < 4; b++)
#pragma unroll
            for (int c = 0; c < 4; c++) { acc1[a][b][c] = 0.0f; acc2[a][b][c] = 0.0f; }

    load_stage(0, 0);
    if (nk > 1) load_stage(1, 1); else CP_COMMIT();
    if (nk > 2) load_stage(2, 2); else CP_COMMIT();

    for (int kt = 0; kt < nk; ++kt) {
        if (kt + 3 < nk) load_stage(kt + 3, (kt + 3) & 3);
        else CP_COMMIT();
        CP_WAIT3();
        __syncthreads();

        const uint32_t sb = sbase + (kt & 3) * STAGE_BYTES;
#pragma unroll
        for (int kk = 0; kk < 2; ++kk) {
            uint32_t af[4][4], bh[2][4], bl[2][4];
#pragma unroll
            for (int mt = 0; mt < 4; ++mt)
                LDSM4(af[mt], sb + aOff + mt * 1280 + kk * 32);
#pragma unroll
            for (int bt = 0; bt < 2; ++bt) {
                const uint32_t bd = sb + 10240 + bOff + bt * 1280 + kk * 32;
                LDSM4(bh[bt], bd);
                LDSM4(bl[bt], bd + 10240);
            }
#pragma unroll
            for (int mt = 0; mt < 4; ++mt)
#pragma unroll
                for (int nt = 0; nt < 4; ++nt) {
                    const int bt = nt >> 1, s2 = (nt & 1) * 2;
                    MMA16(acc1[mt][nt], af[mt], bh[bt][s2], bh[bt][s2 + 1]);
                    MMA16(acc2[mt][nt], af[mt], bl[bt][s2], bl[bt][s2 + 1]);
                }
        }
        __syncthreads();
    }

    const int er = lane >> 2;
    const int ec = (lane & 3) << 1;
#pragma unroll
    for (int mt = 0; mt < 4; ++mt) {
#pragma unroll
        for (int nt = 0; nt < 4; ++nt) {
            const int gr = m0 + wm * 64 + mt * 16 + er;
            const int gc = n0 + wn * 32 + nt * 8 + ec;
            if (gc >= N) continue;
            float v0 = (acc1[mt][nt][0] + acc2[mt][nt][0] * INV512) * alpha;
            float v1 = (acc1[mt][nt][1] + acc2[mt][nt][1] * INV512) * alpha;
            float v2 = (acc1[mt][nt][2] + acc2[mt][nt][2] * INV512) * alpha;
            float v3 = (acc1[mt][nt][3] + acc2[mt][nt][3] * INV512) * alpha;
            if (bias) {
                const float b0 = bias[gc], b1 = bias[gc + 1];
                v0 += b0; v1 += b1; v2 += b0; v3 += b1;
            }
            const long long o0 = (long long)gr * ldc + gc;
            const long long o1 = (long long)(gr + 8) * ldc + gc;
            if (Cf) {
                *(float2*)&Cf[o0] = make_float2(v0, v1);
                *(float2*)&Cf[o1] = make_float2(v2, v3);
            }
            if (Ch) {
                *(uint32_t*)&Ch[o0] = cvt_f16x2(v0, v1);
                *(uint32_t*)&Ch[o1] = cvt_f16x2(v2, v3);
            }
        }
    }
}

// ===================== fused flash attention =================================
// Per (q-block 128, head): O = softmax(Q K^T / sqrt(DH)) V, online softmax.
// Q: single fp16 [s][h*DH+d].  K: 2-limb fp16 [h][s][d] (lo x512).
// V^T: 2-limb fp16 [h][d][s] (lo x512).  O: fp16 [s][h*DH+d].
// 8 warps; warp w owns rows w*16..w*16+15 (full 64-key width per chunk).
#define FA_QPITCH 272
#define FA_KPITCH 272
#define FA_VPITCH 144
#define FA_Q      0
#define FA_KBUF   34816                 // 2 bufs x (2 limbs x 64*272)
#define FA_VBUF   (FA_KBUF + 2 * 34816) // 2 bufs x (2 limbs x 128*144)
#define FA_SMEM   (FA_VBUF + 2 * 36864) // 178176

__global__ void __launch_bounds__(256, 1)
fa_kernel(const __half* __restrict__ Qf,
          const __half* __restrict__ Kh, const __half* __restrict__ Kl,
          const __half* __restrict__ Vh, const __half* __restrict__ Vl,
          __half* __restrict__ O)
{
    extern __shared__ char smem[];
    const uint32_t sb = smem_u32(smem);
    const int tid  = threadIdx.x;
    const int lane = tid & 31;
    const int w    = tid >> 5;
    const int h    = blockIdx.y;
    const int m0   = blockIdx.x * 128;

    Kh += (size_t)h * SQ * DH;  Kl += (size_t)h * SQ * DH;
    Vh += (size_t)h * DH * SQ;  Vl += (size_t)h * DH * SQ;

    // Q tile: 128 rows x 256 B (pitch 272)
    {
        const __half* qg = Qf + (size_t)m0 * DM + h * DH;
#pragma unroll
        for (int i = 0; i < 8; ++i) {
            const int id = tid + i * 256;
            const int r = id >> 4, c = id & 15;
            CP_ASYNC16(sb + FA_Q + r * FA_QPITCH + c * 16, qg + (size_t)r * DM + c * 8);
        }
    }
    auto loadKV = [&](int c, int buf) {
        const int k0 = c << 6;
        const uint32_t kb = sb + FA_KBUF + buf * 34816;
#pragma unroll
        for (int i = 0; i < 4; ++i) {
            const int id = tid + i * 256;
            const int r = id >> 4, cc = id & 15;
            CP_ASYNC16(kb + r * FA_KPITCH + cc * 16,
                       Kh + (size_t)(k0 + r) * DH + cc * 8);
            CP_ASYNC16(kb + 17408 + r * FA_KPITCH + cc * 16,
                       Kl + (size_t)(k0 + r) * DH + cc * 8);
        }
        const uint32_t vb = sb + FA_VBUF + buf * 36864;
#pragma unroll
        for (int i = 0; i < 4; ++i) {
            const int id = tid + i * 256;
            const int r = id >> 3, cc = id & 7;
            CP_ASYNC16(vb + r * FA_VPITCH + cc * 16,
                       Vh + (size_t)r * SQ + k0 + cc * 8);
            CP_ASYNC16(vb + 18432 + r * FA_VPITCH + cc * 16,
                       Vl + (size_t)r * SQ + k0 + cc * 8);
        }
    };

    loadKV(0, 0);
    CP_COMMIT();

    const uint32_t qOff = sb + FA_Q + (w * 16 + (lane & 15)) * FA_QPITCH
                          + ((lane >> 4) & 1) * 16;
    const uint32_t kOff = (uint32_t)((((lane >> 4) & 1) * 8 + (lane & 7)) * FA_KPITCH
                          + ((lane >> 3) & 1) * 16);
    const uint32_t vOff = (uint32_t)((((lane >> 4) & 1) * 8 + (lane & 7)) * FA_VPITCH
                          + ((lane >> 3) & 1) * 16);

    float acc_o[16][4];
#pragma unroll
    for (int i = 0; i < 16; ++i)
#pragma unroll
        for (int j = 0; j < 4; ++j) acc_o[i][j] = 0.0f;

    float mr0 = -1e30f, mr1 = -1e30f, l0 = 0.0f, l1 = 0.0f;
    const float sc_al = 0.08838834764831845f * LOG2E;   // alpha * log2(e)

    const int NC = SQ / 64;   // 32 chunks
    for (int c = 0; c < NC; ++c) {
        if (c + 1 < NC) loadKV(c + 1, (c + 1) & 1);
        CP_COMMIT();
        CP_WAIT1();
        __syncthreads();

        const uint32_t kb = sb + FA_KBUF + (c & 1) * 34816;
        const uint32_t vb = sb + FA_VBUF + (c & 1) * 36864;

        // ---- S = Q @ K^T (2-term) ----
        float s[8][4], s2[8][4];
#pragma unroll
        for (int i = 0; i < 8; ++i)
#pragma unroll
            for (int j = 0; j < 4; ++j) { s[i][j] = 0.0f; s2[i][j] = 0.0f; }

#pragma unroll
        for (int kk = 0; kk < 8; ++kk) {
            uint32_t aq[4];
            LDSM4(aq, qOff + kk * 32);
#pragma unroll
            for (int ntp = 0; ntp < 4; ++ntp) {
                uint32_t kh4[4], kl4[4];
                const uint32_t kd = kb + kOff + ntp * (16 * FA_KPITCH) + kk * 32;
                LDSM4(kh4, kd);
                LDSM4(kl4, kd + 17408);
                MMA16(s[2 * ntp],      aq, kh4[0], kh4[1]);
                MMA16(s[2 * ntp + 1],  aq, kh4[2], kh4[3]);
                MMA16(s2[2 * ntp],     aq, kl4[0], kl4[1]);
                MMA16(s2[2 * ntp + 1], aq, kl4[2], kl4[3]);
            }
        }
        // combine limbs, scale into base-2 domain
#pragma unroll
        for (int nt = 0; nt < 8; ++nt)
#pragma unroll
            for (int j = 0; j < 4; ++j)
                s[nt][j] = (s[nt][j] + s2[nt][j] * INV512) * sc_al;

        // ---- online softmax (rows er, er+8 per thread) ----
        float mx0 = -1e30f, mx1 = -1e30f;
#pragma unroll
        for (int nt = 0; nt < 8; ++nt) {
            mx0 = fmaxf(mx0, fmaxf(s[nt][0], s[nt][1]));
            mx1 = fmaxf(mx1, fmaxf(s[nt][2], s[nt][3]));
        }
        mx0 = fmaxf(mx0, __shfl_xor_sync(0xffffffffu, mx0, 1));
        mx0 = fmaxf(mx0, __shfl_xor_sync(0xffffffffu, mx0, 2));
        mx1 = fmaxf(mx1, __shfl_xor_sync(0xffffffffu, mx1, 1));
        mx1 = fmaxf(mx1, __shfl_xor_sync(0xffffffffu, mx1, 2));

        const float mn0 = fmaxf(mr0, mx0);
        const float mn1 = fmaxf(mr1, mx1);
        const float sc0 = exp2f(mr0 - mn0);
        const float sc1 = exp2f(mr1 - mn1);

        float rs0 = 0.0f, rs1 = 0.0f;
#pragma unroll
        for (int nt = 0; nt < 8; ++nt) {
            s[nt][0] = exp2f(s[nt][0] - mn0);
            s[nt][1] = exp2f(s[nt][1] - mn0);
            s[nt][2] = exp2f(s[nt][2] - mn1);
            s[nt][3] = exp2f(s[nt][3] - mn1);
            rs0 += s[nt][0] + s[nt][1];
            rs1 += s[nt][2] + s[nt][3];
        }
        rs0 += __shfl_xor_sync(0xffffffffu, rs0, 1);
        rs0 += __shfl_xor_sync(0xffffffffu, rs0, 2);
        rs1 += __shfl_xor_sync(0xffffffffu, rs1, 1);
        rs1 += __shfl_xor_sync(0xffffffffu, rs1, 2);

        l0 = l0 * sc0 + rs0;
        l1 = l1 * sc1 + rs1;
        mr0 = mn0;  mr1 = mn1;

#pragma unroll
        for (int nt = 0; nt < 16; ++nt) {
            acc_o[nt][0] *= sc0;  acc_o[nt][1] *= sc0;
            acc_o[nt][2] *= sc1;  acc_o[nt][3] *= sc1;
        }

        // ---- O += P @ V (P from registers; V 2-limb via P/512 trick) ----
#pragma unroll
        for (int kg = 0; kg < 4; ++kg) {
            uint32_t A[4], AL[4];
            A[0] = cvt_f16x2(s[2 * kg][0],     s[2 * kg][1]);
            A[1] = cvt_f16x2(s[2 * kg][2],     s[2 * kg][3]);
            A[2] = cvt_f16x2(s[2 * kg + 1][0], s[2 * kg + 1][1]);
            A[3] = cvt_f16x2(s[2 * kg + 1][2], s[2 * kg + 1][3]);
            AL[0] = cvt_f16x2(s[2 * kg][0] * INV512,     s[2 * kg][1] * INV512);
            AL[1] = cvt_f16x2(s[2 * kg][2] * INV512,     s[2 * kg][3] * INV512);
            AL[2] = cvt_f16x2(s[2 * kg + 1][0] * INV512, s[2 * kg + 1][1] * INV512);
            AL[3] = cvt_f16x2(s[2 * kg + 1][2] * INV512, s[2 * kg + 1][3] * INV512);
#pragma unroll
            for (int dp = 0; dp < 8; ++dp) {
                uint32_t vh4[4], vl4[4];
                const uint32_t vd = vb + vOff + dp * (16 * FA_VPITCH) + kg * 32;
                LDSM4(vh4, vd);
                LDSM4(vl4, vd + 18432);
                MMA16(acc_o[2 * dp],     A,  vh4[0], vh4[1]);
                MMA16(acc_o[2 * dp + 1], A,  vh4[2], vh4[3]);
                MMA16(acc_o[2 * dp],     AL, vl4[0], vl4[1]);
                MMA16(acc_o[2 * dp + 1], AL, vl4[2], vl4[3]);
            }
        }
        __syncthreads();
    }

    // ---- epilogue: O / l -> fp16 ----
    const float i0 = 1.0f / l0;
    const float i1 = 1.0f / l1;
    const int er = lane >> 2;
    const int ec = (lane & 3) << 1;
    const int gr0 = m0 + w * 16 + er;
    __half* ob = O + (size_t)gr0 * DM + h * DH + ec;
#pragma unroll
    for (int nt = 0; nt < 16; ++nt) {
        *(uint32_t*)(ob + nt * 8) =
            cvt_f16x2(acc_o[nt][0] * i0, acc_o[nt][1] * i0);
        *(uint32_t*)(ob + (size_t)8 * DM + nt * 8) =
            cvt_f16x2(acc_o[nt][2] * i1, acc_o[nt][3] * i1);
    }
}

// ===================== fp32 -> fp16 convert ==================================
__global__ void conv_f16(const float4* __restrict__ in, uint2* __restrict__ o, int n4)
{
    const int i = blockIdx.x * blockDim.x + threadIdx.x;
    if (i >= n4) return;
    const float4 f = in[i];
    o[i] = make_uint2(cvt_f16x2(f.x, f.y), cvt_f16x2(f.z, f.w));
}

// ===================== transpose + 2-limb fp16 quant ========================
__global__ void transpose_quant16(const float* __restrict__ in,
                                  __half* __restrict__ ohi, __half* __restrict__ olo,
                                  int ldin, int ldout)
{
    __shared__ float t[32][33];
    const int c0 = blockIdx.x * 32, r0 = blockIdx.y * 32;
    const int tx = threadIdx.x, ty = threadIdx.y;
#pragma unroll
    for (int j = 0; j < 32; j += 8)
        t[ty + j][tx] = in[(long long)(r0 + ty + j) * ldin + c0 + tx];
    __syncthreads();
#pragma unroll
    for (int j = 0; j < 32; j += 8) {
        const float f = t[tx][ty + j];
        const __half h = __float2half_rn(f);
        const __half l = __float2half_rn((f - __half2float(h)) * 512.0f);
        const long long o = (long long)(c0 + ty + j) * ldout + r0 + tx;
        ohi[o] = h;  olo[o] = l;
    }
}

// per-head V transpose: v fp32 [s][h*128+d] -> vt [h][d][s] 2-limb fp16
__global__ void transpose_v16(const float* __restrict__ in,
                              __half* __restrict__ ohi, __half* __restrict__ olo)
{
    __shared__ float t[32][33];
    const long long z = blockIdx.z;
    in  += z * DH;
    ohi += z * (long long)DH * SQ;
    olo += z * (long long)DH * SQ;
    const int c0 = blockIdx.x * 32, r0 = blockIdx.y * 32;
    const int tx = threadIdx.x, ty = threadIdx.y;
#pragma unroll
    for (int j = 0; j < 32; j += 8)
        t[ty + j][tx] = in[(long long)(r0 + ty + j) * DM + c0 + tx];
    __syncthreads();
#pragma unroll
    for (int j = 0; j < 32; j += 8) {
        const float f = t[tx][ty + j];
        const __half h = __float2half_rn(f);
        const __half l = __float2half_rn((f - __half2float(h)) * 512.0f);
        const long long o = (long long)(c0 + ty + j) * SQ + r0 + tx;
        ohi[o] = h;  olo[o] = l;
    }
}

// ===================== RoPE ==================================================
__device__ __forceinline__ void rope_pair(float* base, int i, int pos)
{
    const float f = __expf(-(2.0f * (float)i / 128.0f) * 9.210340371976184f);
    const float ang = (float)pos * f;
    const float c = cosf(ang), s = sinf(ang);
    const float a = base[i];
    const float b = base[i + 32];
    base[i]      = a * c - b * s;
    base[i + 32] = b * c + a * s;
}

__global__ void rope_q_kernel(float* q, const int* past)
{
    const int idx = blockIdx.x * blockDim.x + threadIdx.x;
    if (idx >= SQ * NH * 32) return;
    const int s = idx / (NH * 32);
    const int r = idx % (NH * 32);
    rope_pair(q + (size_t)s * DM + (r / 32) * DH + 64, r % 32, past[0] + s);
}

__global__ void rope_k_kernel(float* krope, const int* past)
{
    const int idx = blockIdx.x * blockDim.x + threadIdx.x;
    if (idx >= SQ * 32) return;
    rope_pair(krope + (size_t)(idx / 32) * RP, idx % 32, past[0] + idx / 32);
}

// ===================== assemble K heads -> 2-limb fp16 [h][s][d] =============
__global__ void assemble_khead16(const float* __restrict__ knope,
                                 const float* __restrict__ krope,
                                 __half* __restrict__ khi, __half* __restrict__ klo)
{
    const int idx = blockIdx.x * blockDim.x + threadIdx.x;
    if (idx >= NH * SQ * DH) return;
    const int d = idx & (DH - 1);
    const int s = (idx >> 7) & (SQ - 1);
    const int h = idx >> 18;
    float v;
    if (d < 64) v = knope[(size_t)s * PR + h * 64 + d];
    else        v = krope[(size_t)s * RP + (d - 64)];
    const __half hb = __float2half_rn(v);
    khi[idx] = hb;
    klo[idx] = __float2half_rn((v - __half2float(hb)) * 512.0f);
}

// ===================== launch ================================================
extern "C" void kernel_launch(void* const* d_in, const int* in_sizes, int n_in,
                              void* d_out, int out_size)
{
    const float* x        = (const float*)d_in[0];
    const float* W_DQ     = (const float*)d_in[1];
    const float* W_UQ     = (const float*)d_in[2];
    const float* W_DKV    = (const float*)d_in[3];
    const float* W_UK     = (const float*)d_in[4];
    const float* W_UV     = (const float*)d_in[5];
    const float* W_K_rope = (const float*)d_in[6];
    const float* W_O      = (const float*)d_in[7];
    const float* b_O      = (const float*)d_in[8];
    const int*   past     = (const int*)d_in[9];
    float* out = (float*)d_out;

    float *q, *knope, *v, *krope;
    cudaGetSymbolAddress((void**)&q,      g_q);
    cudaGetSymbolAddress((void**)&knope,  g_knope);
    cudaGetSymbolAddress((void**)&v,      g_v);
    cudaGetSymbolAddress((void**)&krope,  g_krope);

    __half *xf, *cqf, *ckvf, *qf, *aof,
           *wdq_h, *wdq_l, *wuq_h, *wuq_l, *wdkv_h, *wdkv_l,
           *wuk_h, *wuk_l, *wuv_h, *wuv_l, *wkr_h, *wkr_l,
           *wo_h, *wo_l, *kh_h, *kh_l, *vt_h, *vt_l;
    cudaGetSymbolAddress((void**)&xf,   g_xf);
    cudaGetSymbolAddress((void**)&cqf,  g_cqf);
    cudaGetSymbolAddress((void**)&ckvf, g_ckvf);
    cudaGetSymbolAddress((void**)&qf,   g_qf);
    cudaGetSymbolAddress((void**)&aof,  g_aof);
    cudaGetSymbolAddress((void**)&wdq_h,  g_wdq_h);  cudaGetSymbolAddress((void**)&wdq_l,  g_wdq_l);
    cudaGetSymbolAddress((void**)&wuq_h,  g_wuq_h);  cudaGetSymbolAddress((void**)&wuq_l,  g_wuq_l);
    cudaGetSymbolAddress((void**)&wdkv_h, g_wdkv_h); cudaGetSymbolAddress((void**)&wdkv_l, g_wdkv_l);
    cudaGetSymbolAddress((void**)&wuk_h,  g_wuk_h);  cudaGetSymbolAddress((void**)&wuk_l,  g_wuk_l);
    cudaGetSymbolAddress((void**)&wuv_h,  g_wuv_h);  cudaGetSymbolAddress((void**)&wuv_l,  g_wuv_l);
    cudaGetSymbolAddress((void**)&wkr_h,  g_wkr_h);  cudaGetSymbolAddress((void**)&wkr_l,  g_wkr_l);
    cudaGetSymbolAddress((void**)&wo_h,   g_wo_h);   cudaGetSymbolAddress((void**)&wo_l,   g_wo_l);
    cudaGetSymbolAddress((void**)&kh_h,   g_kh_h);   cudaGetSymbolAddress((void**)&kh_l,   g_kh_l);
    cudaGetSymbolAddress((void**)&vt_h,   g_vt_h);   cudaGetSymbolAddress((void**)&vt_l,   g_vt_l);

    cudaFuncSetAttribute(gemm_f16,  cudaFuncAttributeMaxDynamicSharedMemorySize, GEMM_SMEM);
    cudaFuncSetAttribute(fa_kernel, cudaFuncAttributeMaxDynamicSharedMemorySize, FA_SMEM);

    const dim3 blk(256);
    const dim3 tb(32, 8);

    // 0-4: setup so ncu -s 5 profiles the first big GEMM
    conv_f16<<<(SQ * DM / 4 + 255) / 256, blk>>>(
        (const float4*)x, (uint2*)xf, SQ * DM / 4);
    transpose_quant16<<<dim3(PR / 32, DM / 32), tb>>>(W_DQ,  wdq_h,  wdq_l,  PR, DM);
    transpose_quant16<<<dim3(DM / 32, PR / 32), tb>>>(W_UQ,  wuq_h,  wuq_l,  DM, PR);
    transpose_quant16<<<dim3(PR / 32, DM / 32), tb>>>(W_DKV, wdkv_h, wdkv_l, PR, DM);
    transpose_quant16<<<dim3(PR / 32, PR / 32), tb>>>(W_UK,  wuk_h,  wuk_l,  PR, PR);

    // 5: cq = x @ W_DQ  -> fp16 — PROFILED
    gemm_f16<<<dim3(PR / 128, SQ / 128, 1), blk, GEMM_SMEM>>>(
        xf, wdq_h, wdq_l, nullptr, cqf,
        SQ, PR, DM, DM, DM, PR, 0, 0, 0, 1.0f, nullptr);

    transpose_quant16<<<dim3(DM / 32, PR / 32), tb>>>(W_UV,     wuv_h, wuv_l, DM, PR);
    transpose_quant16<<<dim3(RP / 32, DM / 32), tb>>>(W_K_rope, wkr_h, wkr_l, RP, DM);
    transpose_quant16<<<dim3(DM / 32, DM / 32), tb>>>(W_O,      wo_h,  wo_l,  DM, DM);

    // ckv = x @ W_DKV -> fp16
    gemm_f16<<<dim3(PR / 128, SQ / 128, 1), blk, GEMM_SMEM>>>(
        xf, wdkv_h, wdkv_l, nullptr, ckvf,
        SQ, PR, DM, DM, DM, PR, 0, 0, 0, 1.0f, nullptr);
    // krope = x @ W_K_rope -> fp32 (N=64)
    gemm_f16<<<dim3(1, SQ / 128, 1), blk, GEMM_SMEM>>>(
        xf, wkr_h, wkr_l, krope, nullptr,
        SQ, RP, DM, DM, DM, RP, 0, 0, 0, 1.0f, nullptr);
    // q = cq @ W_UQ -> fp32 (rope needs it)
    gemm_f16<<<dim3(DM / 128, SQ / 128, 1), blk, GEMM_SMEM>>>(
        cqf, wuq_h, wuq_l, q, nullptr,
        SQ, DM, PR, PR, PR, DM, 0, 0, 0, 1.0f, nullptr);
    // knope = ckv @ W_UK -> fp32
    gemm_f16<<<dim3(PR / 128, SQ / 128, 1), blk, GEMM_SMEM>>>(
        ckvf, wuk_h, wuk_l, knope, nullptr,
        SQ, PR, PR, PR, PR, PR, 0, 0, 0, 1.0f, nullptr);
    // v = ckv @ W_UV -> fp32
    gemm_f16<<<dim3(DM / 128, SQ / 128, 1), blk, GEMM_SMEM>>>(
        ckvf, wuv_h, wuv_l, v, nullptr,
        SQ, DM, PR, PR, PR, DM, 0, 0, 0, 1.0f, nullptr);

    // RoPE + operand prep
    rope_q_kernel<<<(SQ * NH * 32 + 255) / 256, blk>>>(q, past);
    rope_k_kernel<<<(SQ * 32 + 255) / 256, blk>>>(krope, past);
    conv_f16<<<(SQ * DM / 4 + 255) / 256, blk>>>(
        (const float4*)q, (uint2*)qf, SQ * DM / 4);
    assemble_khead16<<<(NH * SQ * DH + 255) / 256, blk>>>(knope, krope, kh_h, kh_l);
    transpose_v16<<<dim3(DH / 32, SQ / 32, NH), tb>>>(v, vt_h, vt_l);

    // fused attention: O = softmax(QK^T/sqrt(DH)) V  -> fp16 [s][h*DH]
    fa_kernel<<<dim3(SQ / 128, NH), blk, FA_SMEM>>>(
        qf, kh_h, kh_l, vt_h, vt_l, aof);

    // out = attno @ W_O + b_O  (fp32)
    gemm_f16<<<dim3(DM / 128, SQ / 128, 1), blk, GEMM_SMEM>>>(
        aof, wo_h, wo_l, out, nullptr,
        SQ, DM, DM, DM, DM, DM, 0, 0, 0, 1.0f, b_O);
}

// round 8
// speedup vs baseline: 4.5482x; 1.6065x over previous
#include <cuda_runtime.h>
#include <cuda_bf16.h>
#include <cuda_fp16.h>
#include <cstdint>
#include <math.h>

#define SQ   2048
#define DM   4096
#define PR   2048
#define NH   32
#define DH   128
#define RP   64

#define LOG2E  1.4426950408889634f
#define INV512 0.001953125f

// ===================== small helpers ========================================
static __device__ __forceinline__ uint32_t smem_u32(const void* p) {
    uint32_t a;
    asm("{ .reg .u64 t; cvta.to.shared.u64 t, %1; cvt.u32.u64 %0, t; }"
        : "=r"(a) : "l"(p));
    return a;
}

// pack two floats -> fp16x2 (lo half = a, hi half = b)
static __device__ __forceinline__ uint32_t cvt_f16x2(float a, float b) {
    uint32_t r;
    asm("cvt.rn.f16x2.f32 %0, %1, %2;" : "=r"(r) : "f"(b), "f"(a));
    return r;
}

#define LDSM4(r, addr) \
    asm volatile("ldmatrix.sync.aligned.m8n8.x4.shared.b16 {%0,%1,%2,%3}, [%4];" \
        : "=r"((r)[0]), "=r"((r)[1]), "=r"((r)[2]), "=r"((r)[3]) : "r"(addr))

#define MMA16(d, a, b0v, b1v) \
    asm volatile("mma.sync.aligned.m16n8k16.row.col.f32.f16.f16.f32 " \
        "{%0,%1,%2,%3}, {%4,%5,%6,%7}, {%8,%9}, {%0,%1,%2,%3};" \
        : "+f"((d)[0]), "+f"((d)[1]), "+f"((d)[2]), "+f"((d)[3]) \
        : "r"((a)[0]), "r"((a)[1]), "r"((a)[2]), "r"((a)[3]), "r"(b0v), "r"(b1v))

#define CP_ASYNC16(sp, gp) \
    asm volatile("cp.async.cg.shared.global [%0], [%1], 16;" :: "r"(sp), "l"(gp))
#define CP_COMMIT() asm volatile("cp.async.commit_group;" ::: "memory")
#define CP_WAIT3()  asm volatile("cp.async.wait_group 3;" ::: "memory")
#define CP_WAIT1()  asm volatile("cp.async.wait_group 1;" ::: "memory")

// ===================== scratch (device globals) =============================
__device__ float g_q    [(size_t)SQ * DM];
__device__ float g_knope[(size_t)SQ * PR];
__device__ float g_v    [(size_t)SQ * DM];
__device__ float g_krope[(size_t)SQ * RP];

// single-fp16 activations (A operands)
__device__ __half g_xf  [(size_t)SQ * DM];
__device__ __half g_cqf [(size_t)SQ * PR];
__device__ __half g_ckvf[(size_t)SQ * PR];
__device__ __half g_qf  [(size_t)SQ * DM];
__device__ __half g_aof [(size_t)SQ * DM];

// single-fp16 weights ([N,K] K-major)
__device__ __half g_wdq [(size_t)PR * DM];
__device__ __half g_wuq [(size_t)DM * PR];
__device__ __half g_wdkv[(size_t)PR * DM];
__device__ __half g_wuk [(size_t)PR * PR];
__device__ __half g_wuv [(size_t)DM * PR];
__device__ __half g_wkr [(size_t)RP * DM];
__device__ __half g_wo  [(size_t)DM * DM];

// 2-limb fp16 attention operands (lo limb pre-scaled x512)
__device__ __half g_kh_h[(size_t)NH * SQ * DH], g_kh_l[(size_t)NH * SQ * DH];
__device__ __half g_vt_h[(size_t)NH * DH * SQ], g_vt_l[(size_t)NH * DH * SQ];

// ===================== single-fp16 HMMA GEMM ================================
// C = alpha * A @ B^T (+bias).  A: fp16 [M,K] row-major, B: fp16 [N,K] K-major.
// CTA tile 128x128, BK=32, 8 warps (2x4), warp tile 64x32, 4-stage cp.async.
#define STAGE_BYTES 20480              // 2 matrices * 128 rows * 80 B
#define GEMM_SMEM   (4 * STAGE_BYTES)  // 81920

__global__ void __launch_bounds__(256, 2)
gemm_f16(const __half* __restrict__ Af, const __half* __restrict__ Bh,
         float* __restrict__ Cf, __half* __restrict__ Ch,
         int M, int N, int K, int lda, int ldb, int ldc,
         long long sA, long long sB, long long sC,
         float alpha, const float* __restrict__ bias)
{
    extern __shared__ char smem[];
    const uint32_t sbase = smem_u32(smem);
    const int tid  = threadIdx.x;
    const int lane = tid & 31;
    const int w    = tid >> 5;
    const int wm   = w & 1;        // M dir (2)
    const int wn   = w >> 1;       // N dir (4)

    const long long z = blockIdx.z;
    Af += z * sA;  Bh += z * sB;
    if (Cf) Cf += z * sC;
    if (Ch) Ch += z * sC;

    const int m0 = blockIdx.y * 128;
    const int n0 = blockIdx.x * 128;
    const int nk = K >> 5;

    const int lr   = tid >> 2;        // 0..63
    const int lcol = tid & 3;         // 0..3

    auto load_stage = [&](int kt, int slot) {
        const int k0 = kt << 5;
        const uint32_t sb = sbase + slot * STAGE_BYTES;
#pragma unroll
        for (int i = 0; i < 2; ++i) {
            const int r = lr + i * 64;
            const __half* gp = Af + (long long)(m0 + r) * lda + k0 + lcol * 8;
            CP_ASYNC16(sb + r * 80 + lcol * 16, gp);
        }
#pragma unroll
        for (int i = 0; i < 2; ++i) {
            const int r = lr + i * 64;
            int rn = n0 + r; if (rn >= N) rn = N - 1;
            const __half* gp = Bh + (long long)rn * ldb + k0 + lcol * 8;
            CP_ASYNC16(sb + 10240 + r * 80 + lcol * 16, gp);
        }
        CP_COMMIT();
    };

    const uint32_t aOff = (uint32_t)((wm * 64 + (lane & 15)) * 80 + ((lane >> 4) & 1) * 16);
    const uint32_t bOff = (uint32_t)((wn * 32 + ((lane >> 4) & 1) * 8 + (lane & 7)) * 80
                                     + ((lane >> 3) & 1) * 16);

    float acc[4][4][4];
#pragma unroll
    for (int a = 0; a < 4; a++)
#pragma unroll
        for (int b = 0; b < 4; b++)
#pragma unroll
            for (int c = 0; c < 4; c++) acc[a][b][c] = 0.0f;

    load_stage(0, 0);
    if (nk > 1) load_stage(1, 1); else CP_COMMIT();
    if (nk > 2) load_stage(2, 2); else CP_COMMIT();

    for (int kt = 0; kt < nk; ++kt) {
        if (kt + 3 < nk) load_stage(kt + 3, (kt + 3) & 3);
        else CP_COMMIT();
        CP_WAIT3();
        __syncthreads();

        const uint32_t sb = sbase + (kt & 3) * STAGE_BYTES;
#pragma unroll
        for (int kk = 0; kk < 2; ++kk) {
            uint32_t af[4][4], bh[2][4];
#pragma unroll
            for (int mt = 0; mt < 4; ++mt)
                LDSM4(af[mt], sb + aOff + mt * 1280 + kk * 32);
#pragma unroll
            for (int bt = 0; bt < 2; ++bt)
                LDSM4(bh[bt], sb + 10240 + bOff + bt * 1280 + kk * 32);
#pragma unroll
            for (int mt = 0; mt < 4; ++mt)
#pragma unroll
                for (int nt = 0; nt < 4; ++nt) {
                    const int bt = nt >> 1, s2 = (nt & 1) * 2;
                    MMA16(acc[mt][nt], af[mt], bh[bt][s2], bh[bt][s2 + 1]);
                }
        }
        __syncthreads();
    }

    const int er = lane >> 2;
    const int ec = (lane & 3) << 1;
#pragma unroll
    for (int mt = 0; mt < 4; ++mt) {
#pragma unroll
        for (int nt = 0; nt < 4; ++nt) {
            const int gr = m0 + wm * 64 + mt * 16 + er;
            const int gc = n0 + wn * 32 + nt * 8 + ec;
            if (gc >= N) continue;
            float v0 = acc[mt][nt][0] * alpha;
            float v1 = acc[mt][nt][1] * alpha;
            float v2 = acc[mt][nt][2] * alpha;
            float v3 = acc[mt][nt][3] * alpha;
            if (bias) {
                const float b0 = bias[gc], b1 = bias[gc + 1];
                v0 += b0; v1 += b1; v2 += b0; v3 += b1;
            }
            const long long o0 = (long long)gr * ldc + gc;
            const long long o1 = (long long)(gr + 8) * ldc + gc;
            if (Cf) {
                *(float2*)&Cf[o0] = make_float2(v0, v1);
                *(float2*)&Cf[o1] = make_float2(v2, v3);
            }
            if (Ch) {
                *(uint32_t*)&Ch[o0] = cvt_f16x2(v0, v1);
                *(uint32_t*)&Ch[o1] = cvt_f16x2(v2, v3);
            }
        }
    }
}

// ===================== fused flash attention =================================
// Per (q-block 128, head): O = softmax(Q K^T / sqrt(DH)) V, online softmax.
// Q: single fp16 [s][h*DH+d].  K: 2-limb fp16 [h][s][d] (lo x512).
// V^T: 2-limb fp16 [h][d][s] (lo x512).  O: fp16 [s][h*DH+d].
#define FA_QPITCH 272
#define FA_KPITCH 272
#define FA_VPITCH 144
#define FA_Q      0
#define FA_KBUF   34816                 // 2 bufs x (2 limbs x 64*272)
#define FA_VBUF   (FA_KBUF + 2 * 34816) // 2 bufs x (2 limbs x 128*144)
#define FA_SMEM   (FA_VBUF + 2 * 36864) // 178176

__global__ void __launch_bounds__(256, 1)
fa_kernel(const __half* __restrict__ Qf,
          const __half* __restrict__ Kh, const __half* __restrict__ Kl,
          const __half* __restrict__ Vh, const __half* __restrict__ Vl,
          __half* __restrict__ O)
{
    extern __shared__ char smem[];
    const uint32_t sb = smem_u32(smem);
    const int tid  = threadIdx.x;
    const int lane = tid & 31;
    const int w    = tid >> 5;
    const int h    = blockIdx.y;
    const int m0   = blockIdx.x * 128;

    Kh += (size_t)h * SQ * DH;  Kl += (size_t)h * SQ * DH;
    Vh += (size_t)h * DH * SQ;  Vl += (size_t)h * DH * SQ;

    {
        const __half* qg = Qf + (size_t)m0 * DM + h * DH;
#pragma unroll
        for (int i = 0; i < 8; ++i) {
            const int id = tid + i * 256;
            const int r = id >> 4, c = id & 15;
            CP_ASYNC16(sb + FA_Q + r * FA_QPITCH + c * 16, qg + (size_t)r * DM + c * 8);
        }
    }
    auto loadKV = [&](int c, int buf) {
        const int k0 = c << 6;
        const uint32_t kb = sb + FA_KBUF + buf * 34816;
#pragma unroll
        for (int i = 0; i < 4; ++i) {
            const int id = tid + i * 256;
            const int r = id >> 4, cc = id & 15;
            CP_ASYNC16(kb + r * FA_KPITCH + cc * 16,
                       Kh + (size_t)(k0 + r) * DH + cc * 8);
            CP_ASYNC16(kb + 17408 + r * FA_KPITCH + cc * 16,
                       Kl + (size_t)(k0 + r) * DH + cc * 8);
        }
        const uint32_t vb = sb + FA_VBUF + buf * 36864;
#pragma unroll
        for (int i = 0; i < 4; ++i) {
            const int id = tid + i * 256;
            const int r = id >> 3, cc = id & 7;
            CP_ASYNC16(vb + r * FA_VPITCH + cc * 16,
                       Vh + (size_t)r * SQ + k0 + cc * 8);
            CP_ASYNC16(vb + 18432 + r * FA_VPITCH + cc * 16,
                       Vl + (size_t)r * SQ + k0 + cc * 8);
        }
    };

    loadKV(0, 0);
    CP_COMMIT();

    const uint32_t qOff = sb + FA_Q + (w * 16 + (lane & 15)) * FA_QPITCH
                          + ((lane >> 4) & 1) * 16;
    const uint32_t kOff = (uint32_t)((((lane >> 4) & 1) * 8 + (lane & 7)) * FA_KPITCH
                          + ((lane >> 3) & 1) * 16);
    const uint32_t vOff = (uint32_t)((((lane >> 4) & 1) * 8 + (lane & 7)) * FA_VPITCH
                          + ((lane >> 3) & 1) * 16);

    float acc_o[16][4];
#pragma unroll
    for (int i = 0; i < 16; ++i)
#pragma unroll
        for (int j = 0; j < 4; ++j) acc_o[i][j] = 0.0f;

    float mr0 = -1e30f, mr1 = -1e30f, l0 = 0.0f, l1 = 0.0f;
    const float sc_al = 0.08838834764831845f * LOG2E;

    const int NC = SQ / 64;
    for (int c = 0; c < NC; ++c) {
        if (c + 1 < NC) loadKV(c + 1, (c + 1) & 1);
        CP_COMMIT();
        CP_WAIT1();
        __syncthreads();

        const uint32_t kb = sb + FA_KBUF + (c & 1) * 34816;
        const uint32_t vb = sb + FA_VBUF + (c & 1) * 36864;

        float s[8][4], s2[8][4];
#pragma unroll
        for (int i = 0; i < 8; ++i)
#pragma unroll
            for (int j = 0; j < 4; ++j) { s[i][j] = 0.0f; s2[i][j] = 0.0f; }

#pragma unroll
        for (int kk = 0; kk < 8; ++kk) {
            uint32_t aq[4];
            LDSM4(aq, qOff + kk * 32);
#pragma unroll
            for (int ntp = 0; ntp < 4; ++ntp) {
                uint32_t kh4[4], kl4[4];
                const uint32_t kd = kb + kOff + ntp * (16 * FA_KPITCH) + kk * 32;
                LDSM4(kh4, kd);
                LDSM4(kl4, kd + 17408);
                MMA16(s[2 * ntp],      aq, kh4[0], kh4[1]);
                MMA16(s[2 * ntp + 1],  aq, kh4[2], kh4[3]);
                MMA16(s2[2 * ntp],     aq, kl4[0], kl4[1]);
                MMA16(s2[2 * ntp + 1], aq, kl4[2], kl4[3]);
            }
        }
#pragma unroll
        for (int nt = 0; nt < 8; ++nt)
#pragma unroll
            for (int j = 0; j < 4; ++j)
                s[nt][j] = (s[nt][j] + s2[nt][j] * INV512) * sc_al;

        float mx0 = -1e30f, mx1 = -1e30f;
#pragma unroll
        for (int nt = 0; nt < 8; ++nt) {
            mx0 = fmaxf(mx0, fmaxf(s[nt][0], s[nt][1]));
            mx1 = fmaxf(mx1, fmaxf(s[nt][2], s[nt][3]));
        }
        mx0 = fmaxf(mx0, __shfl_xor_sync(0xffffffffu, mx0, 1));
        mx0 = fmaxf(mx0, __shfl_xor_sync(0xffffffffu, mx0, 2));
        mx1 = fmaxf(mx1, __shfl_xor_sync(0xffffffffu, mx1, 1));
        mx1 = fmaxf(mx1, __shfl_xor_sync(0xffffffffu, mx1, 2));

        const float mn0 = fmaxf(mr0, mx0);
        const float mn1 = fmaxf(mr1, mx1);
        const float sc0 = exp2f(mr0 - mn0);
        const float sc1 = exp2f(mr1 - mn1);

        float rs0 = 0.0f, rs1 = 0.0f;
#pragma unroll
        for (int nt = 0; nt < 8; ++nt) {
            s[nt][0] = exp2f(s[nt][0] - mn0);
            s[nt][1] = exp2f(s[nt][1] - mn0);
            s[nt][2] = exp2f(s[nt][2] - mn1);
            s[nt][3] = exp2f(s[nt][3] - mn1);
            rs0 += s[nt][0] + s[nt][1];
            rs1 += s[nt][2] + s[nt][3];
        }
        rs0 += __shfl_xor_sync(0xffffffffu, rs0, 1);
        rs0 += __shfl_xor_sync(0xffffffffu, rs0, 2);
        rs1 += __shfl_xor_sync(0xffffffffu, rs1, 1);
        rs1 += __shfl_xor_sync(0xffffffffu, rs1, 2);

        l0 = l0 * sc0 + rs0;
        l1 = l1 * sc1 + rs1;
        mr0 = mn0;  mr1 = mn1;

#pragma unroll
        for (int nt = 0; nt < 16; ++nt) {
            acc_o[nt][0] *= sc0;  acc_o[nt][1] *= sc0;
            acc_o[nt][2] *= sc1;  acc_o[nt][3] *= sc1;
        }

#pragma unroll
        for (int kg = 0; kg < 4; ++kg) {
            uint32_t A[4], AL[4];
            A[0] = cvt_f16x2(s[2 * kg][0],     s[2 * kg][1]);
            A[1] = cvt_f16x2(s[2 * kg][2],     s[2 * kg][3]);
            A[2] = cvt_f16x2(s[2 * kg + 1][0], s[2 * kg + 1][1]);
            A[3] = cvt_f16x2(s[2 * kg + 1][2], s[2 * kg + 1][3]);
            AL[0] = cvt_f16x2(s[2 * kg][0] * INV512,     s[2 * kg][1] * INV512);
            AL[1] = cvt_f16x2(s[2 * kg][2] * INV512,     s[2 * kg][3] * INV512);
            AL[2] = cvt_f16x2(s[2 * kg + 1][0] * INV512, s[2 * kg + 1][1] * INV512);
            AL[3] = cvt_f16x2(s[2 * kg + 1][2] * INV512, s[2 * kg + 1][3] * INV512);
#pragma unroll
            for (int dp = 0; dp < 8; ++dp) {
                uint32_t vh4[4], vl4[4];
                const uint32_t vd = vb + vOff + dp * (16 * FA_VPITCH) + kg * 32;
                LDSM4(vh4, vd);
                LDSM4(vl4, vd + 18432);
                MMA16(acc_o[2 * dp],     A,  vh4[0], vh4[1]);
                MMA16(acc_o[2 * dp + 1], A,  vh4[2], vh4[3]);
                MMA16(acc_o[2 * dp],     AL, vl4[0], vl4[1]);
                MMA16(acc_o[2 * dp + 1], AL, vl4[2], vl4[3]);
            }
        }
        __syncthreads();
    }

    const float i0 = 1.0f / l0;
    const float i1 = 1.0f / l1;
    const int er = lane >> 2;
    const int ec = (lane & 3) << 1;
    const int gr0 = m0 + w * 16 + er;
    __half* ob = O + (size_t)gr0 * DM + h * DH + ec;
#pragma unroll
    for (int nt = 0; nt < 16; ++nt) {
        *(uint32_t*)(ob + nt * 8) =
            cvt_f16x2(acc_o[nt][0] * i0, acc_o[nt][1] * i0);
        *(uint32_t*)(ob + (size_t)8 * DM + nt * 8) =
            cvt_f16x2(acc_o[nt][2] * i1, acc_o[nt][3] * i1);
    }
}

// ===================== fp32 -> fp16 convert ==================================
__global__ void conv_f16(const float4* __restrict__ in, uint2* __restrict__ o, int n4)
{
    const int i = blockIdx.x * blockDim.x + threadIdx.x;
    if (i >= n4) return;
    const float4 f = in[i];
    o[i] = make_uint2(cvt_f16x2(f.x, f.y), cvt_f16x2(f.z, f.w));
}

// ===================== transpose + single fp16 ===============================
// in [K,N] fp32 -> out [N,K] fp16
__global__ void transpose_f16w(const float* __restrict__ in,
                               __half* __restrict__ o, int ldin, int ldout)
{
    __shared__ float t[32][33];
    const int c0 = blockIdx.x * 32, r0 = blockIdx.y * 32;
    const int tx = threadIdx.x, ty = threadIdx.y;
#pragma unroll
    for (int j = 0; j < 32; j += 8)
        t[ty + j][tx] = in[(long long)(r0 + ty + j) * ldin + c0 + tx];
    __syncthreads();
#pragma unroll
    for (int j = 0; j < 32; j += 8)
        o[(long long)(c0 + ty + j) * ldout + r0 + tx] = __float2half_rn(t[tx][ty + j]);
}

// per-head V transpose: v fp32 [s][h*128+d] -> vt [h][d][s] 2-limb fp16
__global__ void transpose_v16(const float* __restrict__ in,
                              __half* __restrict__ ohi, __half* __restrict__ olo)
{
    __shared__ float t[32][33];
    const long long z = blockIdx.z;
    in  += z * DH;
    ohi += z * (long long)DH * SQ;
    olo += z * (long long)DH * SQ;
    const int c0 = blockIdx.x * 32, r0 = blockIdx.y * 32;
    const int tx = threadIdx.x, ty = threadIdx.y;
#pragma unroll
    for (int j = 0; j < 32; j += 8)
        t[ty + j][tx] = in[(long long)(r0 + ty + j) * DM + c0 + tx];
    __syncthreads();
#pragma unroll
    for (int j = 0; j < 32; j += 8) {
        const float f = t[tx][ty + j];
        const __half h = __float2half_rn(f);
        const __half l = __float2half_rn((f - __half2float(h)) * 512.0f);
        const long long o = (long long)(c0 + ty + j) * SQ + r0 + tx;
        ohi[o] = h;  olo[o] = l;
    }
}

// ===================== RoPE ==================================================
__device__ __forceinline__ void rope_pair(float* base, int i, int pos)
{
    const float f = __expf(-(2.0f * (float)i / 128.0f) * 9.210340371976184f);
    const float ang = (float)pos * f;
    const float c = cosf(ang), s = sinf(ang);
    const float a = base[i];
    const float b = base[i + 32];
    base[i]      = a * c - b * s;
    base[i + 32] = b * c + a * s;
}

__global__ void rope_q_kernel(float* q, const int* past)
{
    const int idx = blockIdx.x * blockDim.x + threadIdx.x;
    if (idx >= SQ * NH * 32) return;
    const int s = idx / (NH * 32);
    const int r = idx % (NH * 32);
    rope_pair(q + (size_t)s * DM + (r / 32) * DH + 64, r % 32, past[0] + s);
}

__global__ void rope_k_kernel(float* krope, const int* past)
{
    const int idx = blockIdx.x * blockDim.x + threadIdx.x;
    if (idx >= SQ * 32) return;
    rope_pair(krope + (size_t)(idx / 32) * RP, idx % 32, past[0] + idx / 32);
}

// ===================== assemble K heads -> 2-limb fp16 [h][s][d] =============
__global__ void assemble_khead16(const float* __restrict__ knope,
                                 const float* __restrict__ krope,
                                 __half* __restrict__ khi, __half* __restrict__ klo)
{
    const int idx = blockIdx.x * blockDim.x + threadIdx.x;
    if (idx >= NH * SQ * DH) return;
    const int d = idx & (DH - 1);
    const int s = (idx >> 7) & (SQ - 1);
    const int h = idx >> 18;
    float v;
    if (d < 64) v = knope[(size_t)s * PR + h * 64 + d];
    else        v = krope[(size_t)s * RP + (d - 64)];
    const __half hb = __float2half_rn(v);
    khi[idx] = hb;
    klo[idx] = __float2half_rn((v - __half2float(hb)) * 512.0f);
}

// ===================== launch ================================================
extern "C" void kernel_launch(void* const* d_in, const int* in_sizes, int n_in,
                              void* d_out, int out_size)
{
    const float* x        = (const float*)d_in[0];
    const float* W_DQ     = (const float*)d_in[1];
    const float* W_UQ     = (const float*)d_in[2];
    const float* W_DKV    = (const float*)d_in[3];
    const float* W_UK     = (const float*)d_in[4];
    const float* W_UV     = (const float*)d_in[5];
    const float* W_K_rope = (const float*)d_in[6];
    const float* W_O      = (const float*)d_in[7];
    const float* b_O      = (const float*)d_in[8];
    const int*   past     = (const int*)d_in[9];
    float* out = (float*)d_out;

    float *q, *knope, *v, *krope;
    cudaGetSymbolAddress((void**)&q,      g_q);
    cudaGetSymbolAddress((void**)&knope,  g_knope);
    cudaGetSymbolAddress((void**)&v,      g_v);
    cudaGetSymbolAddress((void**)&krope,  g_krope);

    __half *xf, *cqf, *ckvf, *qf, *aof,
           *wdq, *wuq, *wdkv, *wuk, *wuv, *wkr, *wo,
           *kh_h, *kh_l, *vt_h, *vt_l;
    cudaGetSymbolAddress((void**)&xf,   g_xf);
    cudaGetSymbolAddress((void**)&cqf,  g_cqf);
    cudaGetSymbolAddress((void**)&ckvf, g_ckvf);
    cudaGetSymbolAddress((void**)&qf,   g_qf);
    cudaGetSymbolAddress((void**)&aof,  g_aof);
    cudaGetSymbolAddress((void**)&wdq,  g_wdq);
    cudaGetSymbolAddress((void**)&wuq,  g_wuq);
    cudaGetSymbolAddress((void**)&wdkv, g_wdkv);
    cudaGetSymbolAddress((void**)&wuk,  g_wuk);
    cudaGetSymbolAddress((void**)&wuv,  g_wuv);
    cudaGetSymbolAddress((void**)&wkr,  g_wkr);
    cudaGetSymbolAddress((void**)&wo,   g_wo);
    cudaGetSymbolAddress((void**)&kh_h, g_kh_h);  cudaGetSymbolAddress((void**)&kh_l, g_kh_l);
    cudaGetSymbolAddress((void**)&vt_h, g_vt_h);  cudaGetSymbolAddress((void**)&vt_l, g_vt_l);

    cudaFuncSetAttribute(gemm_f16,  cudaFuncAttributeMaxDynamicSharedMemorySize, GEMM_SMEM);
    cudaFuncSetAttribute(fa_kernel, cudaFuncAttributeMaxDynamicSharedMemorySize, FA_SMEM);

    const dim3 blk(256);
    const dim3 tb(32, 8);

    // 0-4: setup so ncu -s 5 profiles the first big GEMM
    conv_f16<<<(SQ * DM / 4 + 255) / 256, blk>>>(
        (const float4*)x, (uint2*)xf, SQ * DM / 4);
    transpose_f16w<<<dim3(PR / 32, DM / 32), tb>>>(W_DQ,  wdq,  PR, DM);
    transpose_f16w<<<dim3(DM / 32, PR / 32), tb>>>(W_UQ,  wuq,  DM, PR);
    transpose_f16w<<<dim3(PR / 32, DM / 32), tb>>>(W_DKV, wdkv, PR, DM);
    transpose_f16w<<<dim3(PR / 32, PR / 32), tb>>>(W_UK,  wuk,  PR, PR);

    // 5: cq = x @ W_DQ -> fp16 — PROFILED
    gemm_f16<<<dim3(PR / 128, SQ / 128, 1), blk, GEMM_SMEM>>>(
        xf, wdq, nullptr, cqf,
        SQ, PR, DM, DM, DM, PR, 0, 0, 0, 1.0f, nullptr);

    transpose_f16w<<<dim3(DM / 32, PR / 32), tb>>>(W_UV,     wuv, DM, PR);
    transpose_f16w<<<dim3(RP / 32, DM / 32), tb>>>(W_K_rope, wkr, RP, DM);
    transpose_f16w<<<dim3(DM / 32, DM / 32), tb>>>(W_O,      wo,  DM, DM);

    // ckv = x @ W_DKV -> fp16
    gemm_f16<<<dim3(PR / 128, SQ / 128, 1), blk, GEMM_SMEM>>>(
        xf, wdkv, nullptr, ckvf,
        SQ, PR, DM, DM, DM, PR, 0, 0, 0, 1.0f, nullptr);
    // krope = x @ W_K_rope -> fp32 (N=64)
    gemm_f16<<<dim3(1, SQ / 128, 1), blk, GEMM_SMEM>>>(
        xf, wkr, krope, nullptr,
        SQ, RP, DM, DM, DM, RP, 0, 0, 0, 1.0f, nullptr);
    // q = cq @ W_UQ -> fp32 (rope needs it)
    gemm_f16<<<dim3(DM / 128, SQ / 128, 1), blk, GEMM_SMEM>>>(
        cqf, wuq, q, nullptr,
        SQ, DM, PR, PR, PR, DM, 0, 0, 0, 1.0f, nullptr);
    // knope = ckv @ W_UK -> fp32
    gemm_f16<<<dim3(PR / 128, SQ / 128, 1), blk, GEMM_SMEM>>>(
        ckvf, wuk, knope, nullptr,
        SQ, PR, PR, PR, PR, PR, 0, 0, 0, 1.0f, nullptr);
    // v = ckv @ W_UV -> fp32
    gemm_f16<<<dim3(DM / 128, SQ / 128, 1), blk, GEMM_SMEM>>>(
        ckvf, wuv, v, nullptr,
        SQ, DM, PR, PR, PR, DM, 0, 0, 0, 1.0f, nullptr);

    // RoPE + operand prep
    rope_q_kernel<<<(SQ * NH * 32 + 255) / 256, blk>>>(q, past);
    rope_k_kernel<<<(SQ * 32 + 255) / 256, blk>>>(krope, past);
    conv_f16<<<(SQ * DM / 4 + 255) / 256, blk>>>(
        (const float4*)q, (uint2*)qf, SQ * DM / 4);
    assemble_khead16<<<(NH * SQ * DH + 255) / 256, blk>>>(knope, krope, kh_h, kh_l);
    transpose_v16<<<dim3(DH / 32, SQ / 32, NH), tb>>>(v, vt_h, vt_l);

    // fused attention: O = softmax(QK^T/sqrt(DH)) V -> fp16 [s][h*DH]
    fa_kernel<<<dim3(SQ / 128, NH), blk, FA_SMEM>>>(
        qf, kh_h, kh_l, vt_h, vt_l, aof);

    // out = attno @ W_O + b_O  (fp32)
    gemm_f16<<<dim3(DM / 128, SQ / 128, 1), blk, GEMM_SMEM>>>(
        aof, wo, out, nullptr,
        SQ, DM, DM, DM, DM, DM, 0, 0, 0, 1.0f, b_O);
}

// round 9
// speedup vs baseline: 4.8897x; 1.0751x over previous
#include <cuda_runtime.h>
#include <cuda_bf16.h>
#include <cuda_fp16.h>
#include <cstdint>
#include <math.h>

#define SQ   2048
#define DM   4096
#define PR   2048
#define NH   32
#define DH   128
#define RP   64

#define LOG2E  1.4426950408889634f
#define INV512 0.001953125f

// ===================== small helpers ========================================
static __device__ __forceinline__ uint32_t smem_u32(const void* p) {
    uint32_t a;
    asm("{ .reg .u64 t; cvta.to.shared.u64 t, %1; cvt.u32.u64 %0, t; }"
        : "=r"(a) : "l"(p));
    return a;
}

// pack two floats -> fp16x2 (lo half = a, hi half = b)
static __device__ __forceinline__ uint32_t cvt_f16x2(float a, float b) {
    uint32_t r;
    asm("cvt.rn.f16x2.f32 %0, %1, %2;" : "=r"(r) : "f"(b), "f"(a));
    return r;
}

#define LDSM4(r, addr) \
    asm volatile("ldmatrix.sync.aligned.m8n8.x4.shared.b16 {%0,%1,%2,%3}, [%4];" \
        : "=r"((r)[0]), "=r"((r)[1]), "=r"((r)[2]), "=r"((r)[3]) : "r"(addr))

#define MMA16(d, a, b0v, b1v) \
    asm volatile("mma.sync.aligned.m16n8k16.row.col.f32.f16.f16.f32 " \
        "{%0,%1,%2,%3}, {%4,%5,%6,%7}, {%8,%9}, {%0,%1,%2,%3};" \
        : "+f"((d)[0]), "+f"((d)[1]), "+f"((d)[2]), "+f"((d)[3]) \
        : "r"((a)[0]), "r"((a)[1]), "r"((a)[2]), "r"((a)[3]), "r"(b0v), "r"(b1v))

#define CP_ASYNC16(sp, gp) \
    asm volatile("cp.async.cg.shared.global [%0], [%1], 16;" :: "r"(sp), "l"(gp))
#define CP_COMMIT() asm volatile("cp.async.commit_group;" ::: "memory")
#define CP_WAIT3()  asm volatile("cp.async.wait_group 3;" ::: "memory")
#define CP_WAIT1()  asm volatile("cp.async.wait_group 1;" ::: "memory")

// ===================== scratch (device globals) =============================
__device__ float g_q    [(size_t)SQ * DM];
__device__ float g_knope[(size_t)SQ * PR];
__device__ float g_krope[(size_t)SQ * RP];

// single-fp16 activations
__device__ __half g_xf  [(size_t)SQ * DM];
__device__ __half g_cqf [(size_t)SQ * PR];
__device__ __half g_ckvf[(size_t)SQ * PR];
__device__ __half g_qf  [(size_t)SQ * DM];
__device__ __half g_vf  [(size_t)SQ * DM];
__device__ __half g_aof [(size_t)SQ * DM];

// single-fp16 weights ([N,K] K-major)
__device__ __half g_wdq [(size_t)PR * DM];
__device__ __half g_wuq [(size_t)DM * PR];
__device__ __half g_wdkv[(size_t)PR * DM];
__device__ __half g_wuk [(size_t)PR * PR];
__device__ __half g_wuv [(size_t)DM * PR];
__device__ __half g_wkr [(size_t)RP * DM];
__device__ __half g_wo  [(size_t)DM * DM];

// attention operands: K 2-limb (lo x512), V single
__device__ __half g_kh_h[(size_t)NH * SQ * DH], g_kh_l[(size_t)NH * SQ * DH];
__device__ __half g_vt_h[(size_t)NH * DH * SQ];

// ===================== single-fp16 HMMA GEMM ================================
// C = alpha * A @ B^T (+bias).  A: fp16 [M,K] row-major, B: fp16 [N,K] K-major.
// CTA tile 128x128, BK=32, 8 warps (2x4), warp tile 64x32, 4-stage cp.async.
#define STAGE_BYTES 20480
#define GEMM_SMEM   (4 * STAGE_BYTES)  // 81920

__global__ void __launch_bounds__(256, 2)
gemm_f16(const __half* __restrict__ Af, const __half* __restrict__ Bh,
         float* __restrict__ Cf, __half* __restrict__ Ch,
         int M, int N, int K, int lda, int ldb, int ldc,
         long long sA, long long sB, long long sC,
         float alpha, const float* __restrict__ bias)
{
    extern __shared__ char smem[];
    const uint32_t sbase = smem_u32(smem);
    const int tid  = threadIdx.x;
    const int lane = tid & 31;
    const int w    = tid >> 5;
    const int wm   = w & 1;
    const int wn   = w >> 1;

    const long long z = blockIdx.z;
    Af += z * sA;  Bh += z * sB;
    if (Cf) Cf += z * sC;
    if (Ch) Ch += z * sC;

    const int m0 = blockIdx.y * 128;
    const int n0 = blockIdx.x * 128;
    const int nk = K >> 5;

    const int lr   = tid >> 2;
    const int lcol = tid & 3;

    auto load_stage = [&](int kt, int slot) {
        const int k0 = kt << 5;
        const uint32_t sb = sbase + slot * STAGE_BYTES;
#pragma unroll
        for (int i = 0; i < 2; ++i) {
            const int r = lr + i * 64;
            const __half* gp = Af + (long long)(m0 + r) * lda + k0 + lcol * 8;
            CP_ASYNC16(sb + r * 80 + lcol * 16, gp);
        }
#pragma unroll
        for (int i = 0; i < 2; ++i) {
            const int r = lr + i * 64;
            int rn = n0 + r; if (rn >= N) rn = N - 1;
            const __half* gp = Bh + (long long)rn * ldb + k0 + lcol * 8;
            CP_ASYNC16(sb + 10240 + r * 80 + lcol * 16, gp);
        }
        CP_COMMIT();
    };

    const uint32_t aOff = (uint32_t)((wm * 64 + (lane & 15)) * 80 + ((lane >> 4) & 1) * 16);
    const uint32_t bOff = (uint32_t)((wn * 32 + ((lane >> 4) & 1) * 8 + (lane & 7)) * 80
                                     + ((lane >> 3) & 1) * 16);

    float acc[4][4][4];
#pragma unroll
    for (int a = 0; a < 4; a++)
#pragma unroll
        for (int b = 0; b < 4; b++)
#pragma unroll
            for (int c = 0; c < 4; c++) acc[a][b][c] = 0.0f;

    load_stage(0, 0);
    if (nk > 1) load_stage(1, 1); else CP_COMMIT();
    if (nk > 2) load_stage(2, 2); else CP_COMMIT();

    for (int kt = 0; kt < nk; ++kt) {
        if (kt + 3 < nk) load_stage(kt + 3, (kt + 3) & 3);
        else CP_COMMIT();
        CP_WAIT3();
        __syncthreads();

        const uint32_t sb = sbase + (kt & 3) * STAGE_BYTES;
#pragma unroll
        for (int kk = 0; kk < 2; ++kk) {
            uint32_t af[4][4], bh[2][4];
#pragma unroll
            for (int mt = 0; mt < 4; ++mt)
                LDSM4(af[mt], sb + aOff + mt * 1280 + kk * 32);
#pragma unroll
            for (int bt = 0; bt < 2; ++bt)
                LDSM4(bh[bt], sb + 10240 + bOff + bt * 1280 + kk * 32);
#pragma unroll
            for (int mt = 0; mt < 4; ++mt)
#pragma unroll
                for (int nt = 0; nt < 4; ++nt) {
                    const int bt = nt >> 1, s2 = (nt & 1) * 2;
                    MMA16(acc[mt][nt], af[mt], bh[bt][s2], bh[bt][s2 + 1]);
                }
        }
        __syncthreads();
    }

    const int er = lane >> 2;
    const int ec = (lane & 3) << 1;
#pragma unroll
    for (int mt = 0; mt < 4; ++mt) {
#pragma unroll
        for (int nt = 0; nt < 4; ++nt) {
            const int gr = m0 + wm * 64 + mt * 16 + er;
            const int gc = n0 + wn * 32 + nt * 8 + ec;
            if (gc >= N) continue;
            float v0 = acc[mt][nt][0] * alpha;
            float v1 = acc[mt][nt][1] * alpha;
            float v2 = acc[mt][nt][2] * alpha;
            float v3 = acc[mt][nt][3] * alpha;
            if (bias) {
                const float b0 = bias[gc], b1 = bias[gc + 1];
                v0 += b0; v1 += b1; v2 += b0; v3 += b1;
            }
            const long long o0 = (long long)gr * ldc + gc;
            const long long o1 = (long long)(gr + 8) * ldc + gc;
            if (Cf) {
                *(float2*)&Cf[o0] = make_float2(v0, v1);
                *(float2*)&Cf[o1] = make_float2(v2, v3);
            }
            if (Ch) {
                *(uint32_t*)&Ch[o0] = cvt_f16x2(v0, v1);
                *(uint32_t*)&Ch[o1] = cvt_f16x2(v2, v3);
            }
        }
    }
}

// ===================== fused flash attention =================================
// O = softmax(Q K^T / sqrt(DH)) V; online softmax.
// Q: fp16 [s][h*DH+d].  K: 2-limb fp16 [h][s][d] (lo x512).
// V^T: single fp16 [h][d][s].  O: fp16 [s][h*DH+d].
#define FA_QPITCH 272
#define FA_KPITCH 272
#define FA_VPITCH 144
#define FA_Q      0
#define FA_KBUF   34816                 // 2 bufs x (2 limbs x 64*272)
#define FA_VBUF   (FA_KBUF + 2 * 34816) // 2 bufs x (128*144)
#define FA_SMEM   (FA_VBUF + 2 * 18432) // 141312

__global__ void __launch_bounds__(256, 1)
fa_kernel(const __half* __restrict__ Qf,
          const __half* __restrict__ Kh, const __half* __restrict__ Kl,
          const __half* __restrict__ Vh,
          __half* __restrict__ O)
{
    extern __shared__ char smem[];
    const uint32_t sb = smem_u32(smem);
    const int tid  = threadIdx.x;
    const int lane = tid & 31;
    const int w    = tid >> 5;
    const int h    = blockIdx.y;
    const int m0   = blockIdx.x * 128;

    Kh += (size_t)h * SQ * DH;  Kl += (size_t)h * SQ * DH;
    Vh += (size_t)h * DH * SQ;

    {
        const __half* qg = Qf + (size_t)m0 * DM + h * DH;
#pragma unroll
        for (int i = 0; i < 8; ++i) {
            const int id = tid + i * 256;
            const int r = id >> 4, c = id & 15;
            CP_ASYNC16(sb + FA_Q + r * FA_QPITCH + c * 16, qg + (size_t)r * DM + c * 8);
        }
    }
    auto loadKV = [&](int c, int buf) {
        const int k0 = c << 6;
        const uint32_t kb = sb + FA_KBUF + buf * 34816;
#pragma unroll
        for (int i = 0; i < 4; ++i) {
            const int id = tid + i * 256;
            const int r = id >> 4, cc = id & 15;
            CP_ASYNC16(kb + r * FA_KPITCH + cc * 16,
                       Kh + (size_t)(k0 + r) * DH + cc * 8);
            CP_ASYNC16(kb + 17408 + r * FA_KPITCH + cc * 16,
                       Kl + (size_t)(k0 + r) * DH + cc * 8);
        }
        const uint32_t vb = sb + FA_VBUF + buf * 18432;
#pragma unroll
        for (int i = 0; i < 4; ++i) {
            const int id = tid + i * 256;
            const int r = id >> 3, cc = id & 7;
            CP_ASYNC16(vb + r * FA_VPITCH + cc * 16,
                       Vh + (size_t)r * SQ + k0 + cc * 8);
        }
    };

    loadKV(0, 0);
    CP_COMMIT();

    const uint32_t qOff = sb + FA_Q + (w * 16 + (lane & 15)) * FA_QPITCH
                          + ((lane >> 4) & 1) * 16;
    const uint32_t kOff = (uint32_t)((((lane >> 4) & 1) * 8 + (lane & 7)) * FA_KPITCH
                          + ((lane >> 3) & 1) * 16);
    const uint32_t vOff = (uint32_t)((((lane >> 4) & 1) * 8 + (lane & 7)) * FA_VPITCH
                          + ((lane >> 3) & 1) * 16);

    float acc_o[16][4];
#pragma unroll
    for (int i = 0; i < 16; ++i)
#pragma unroll
        for (int j = 0; j < 4; ++j) acc_o[i][j] = 0.0f;

    float mr0 = -1e30f, mr1 = -1e30f, l0 = 0.0f, l1 = 0.0f;
    const float sc_al = 0.08838834764831845f * LOG2E;

    const int NC = SQ / 64;
    for (int c = 0; c < NC; ++c) {
        if (c + 1 < NC) loadKV(c + 1, (c + 1) & 1);
        CP_COMMIT();
        CP_WAIT1();
        __syncthreads();

        const uint32_t kb = sb + FA_KBUF + (c & 1) * 34816;
        const uint32_t vb = sb + FA_VBUF + (c & 1) * 18432;

        float s[8][4], s2[8][4];
#pragma unroll
        for (int i = 0; i < 8; ++i)
#pragma unroll
            for (int j = 0; j < 4; ++j) { s[i][j] = 0.0f; s2[i][j] = 0.0f; }

#pragma unroll
        for (int kk = 0; kk < 8; ++kk) {
            uint32_t aq[4];
            LDSM4(aq, qOff + kk * 32);
#pragma unroll
            for (int ntp = 0; ntp < 4; ++ntp) {
                uint32_t kh4[4], kl4[4];
                const uint32_t kd = kb + kOff + ntp * (16 * FA_KPITCH) + kk * 32;
                LDSM4(kh4, kd);
                LDSM4(kl4, kd + 17408);
                MMA16(s[2 * ntp],      aq, kh4[0], kh4[1]);
                MMA16(s[2 * ntp + 1],  aq, kh4[2], kh4[3]);
                MMA16(s2[2 * ntp],     aq, kl4[0], kl4[1]);
                MMA16(s2[2 * ntp + 1], aq, kl4[2], kl4[3]);
            }
        }
#pragma unroll
        for (int nt = 0; nt < 8; ++nt)
#pragma unroll
            for (int j = 0; j < 4; ++j)
                s[nt][j] = (s[nt][j] + s2[nt][j] * INV512) * sc_al;

        float mx0 = -1e30f, mx1 = -1e30f;
#pragma unroll
        for (int nt = 0; nt < 8; ++nt) {
            mx0 = fmaxf(mx0, fmaxf(s[nt][0], s[nt][1]));
            mx1 = fmaxf(mx1, fmaxf(s[nt][2], s[nt][3]));
        }
        mx0 = fmaxf(mx0, __shfl_xor_sync(0xffffffffu, mx0, 1));
        mx0 = fmaxf(mx0, __shfl_xor_sync(0xffffffffu, mx0, 2));
        mx1 = fmaxf(mx1, __shfl_xor_sync(0xffffffffu, mx1, 1));
        mx1 = fmaxf(mx1, __shfl_xor_sync(0xffffffffu, mx1, 2));

        const float mn0 = fmaxf(mr0, mx0);
        const float mn1 = fmaxf(mr1, mx1);
        const float sc0 = exp2f(mr0 - mn0);
        const float sc1 = exp2f(mr1 - mn1);

        float rs0 = 0.0f, rs1 = 0.0f;
#pragma unroll
        for (int nt = 0; nt < 8; ++nt) {
            s[nt][0] = exp2f(s[nt][0] - mn0);
            s[nt][1] = exp2f(s[nt][1] - mn0);
            s[nt][2] = exp2f(s[nt][2] - mn1);
            s[nt][3] = exp2f(s[nt][3] - mn1);
            rs0 += s[nt][0] + s[nt][1];
            rs1 += s[nt][2] + s[nt][3];
        }
        rs0 += __shfl_xor_sync(0xffffffffu, rs0, 1);
        rs0 += __shfl_xor_sync(0xffffffffu, rs0, 2);
        rs1 += __shfl_xor_sync(0xffffffffu, rs1, 1);
        rs1 += __shfl_xor_sync(0xffffffffu, rs1, 2);

        l0 = l0 * sc0 + rs0;
        l1 = l1 * sc1 + rs1;
        mr0 = mn0;  mr1 = mn1;

#pragma unroll
        for (int nt = 0; nt < 16; ++nt) {
            acc_o[nt][0] *= sc0;  acc_o[nt][1] *= sc0;
            acc_o[nt][2] *= sc1;  acc_o[nt][3] *= sc1;
        }

#pragma unroll
        for (int kg = 0; kg < 4; ++kg) {
            uint32_t A[4];
            A[0] = cvt_f16x2(s[2 * kg][0],     s[2 * kg][1]);
            A[1] = cvt_f16x2(s[2 * kg][2],     s[2 * kg][3]);
            A[2] = cvt_f16x2(s[2 * kg + 1][0], s[2 * kg + 1][1]);
            A[3] = cvt_f16x2(s[2 * kg + 1][2], s[2 * kg + 1][3]);
#pragma unroll
            for (int dp = 0; dp < 8; ++dp) {
                uint32_t vh4[4];
                LDSM4(vh4, vb + vOff + dp * (16 * FA_VPITCH) + kg * 32);
                MMA16(acc_o[2 * dp],     A, vh4[0], vh4[1]);
                MMA16(acc_o[2 * dp + 1], A, vh4[2], vh4[3]);
            }
        }
        __syncthreads();
    }

    const float i0 = 1.0f / l0;
    const float i1 = 1.0f / l1;
    const int er = lane >> 2;
    const int ec = (lane & 3) << 1;
    const int gr0 = m0 + w * 16 + er;
    __half* ob = O + (size_t)gr0 * DM + h * DH + ec;
#pragma unroll
    for (int nt = 0; nt < 16; ++nt) {
        *(uint32_t*)(ob + nt * 8) =
            cvt_f16x2(acc_o[nt][0] * i0, acc_o[nt][1] * i0);
        *(uint32_t*)(ob + (size_t)8 * DM + nt * 8) =
            cvt_f16x2(acc_o[nt][2] * i1, acc_o[nt][3] * i1);
    }
}

// ===================== fp32 -> fp16 convert ==================================
__global__ void conv_f16(const float4* __restrict__ in, uint2* __restrict__ o, int n4)
{
    const int i = blockIdx.x * blockDim.x + threadIdx.x;
    if (i >= n4) return;
    const float4 f = in[i];
    o[i] = make_uint2(cvt_f16x2(f.x, f.y), cvt_f16x2(f.z, f.w));
}

// ===================== transpose fp32 [K,N] -> fp16 [N,K] ====================
__global__ void transpose_f16w(const float* __restrict__ in,
                               __half* __restrict__ o, int ldin, int ldout)
{
    __shared__ float t[32][33];
    const int c0 = blockIdx.x * 32, r0 = blockIdx.y * 32;
    const int tx = threadIdx.x, ty = threadIdx.y;
#pragma unroll
    for (int j = 0; j < 32; j += 8)
        t[ty + j][tx] = in[(long long)(r0 + ty + j) * ldin + c0 + tx];
    __syncthreads();
#pragma unroll
    for (int j = 0; j < 32; j += 8)
        o[(long long)(c0 + ty + j) * ldout + r0 + tx] = __float2half_rn(t[tx][ty + j]);
}

// per-head V transpose: vf fp16 [s][h*128+d] -> vt [h][d][s] fp16
__global__ void transpose_vh(const __half* __restrict__ in, __half* __restrict__ o)
{
    __shared__ __half t[32][40];
    const long long z = blockIdx.z;
    in += z * DH;
    o  += z * (long long)DH * SQ;
    const int c0 = blockIdx.x * 32, r0 = blockIdx.y * 32;   // c0: d, r0: s
    const int tx = threadIdx.x, ty = threadIdx.y;
#pragma unroll
    for (int j = 0; j < 32; j += 8)
        t[ty + j][tx] = in[(long long)(r0 + ty + j) * DM + c0 + tx];
    __syncthreads();
#pragma unroll
    for (int j = 0; j < 32; j += 8)
        o[(long long)(c0 + ty + j) * SQ + r0 + tx] = t[tx][ty + j];
}

// ===================== RoPE ==================================================
__device__ __forceinline__ void rope_pair(float* base, int i, int pos)
{
    const float f = __expf(-(2.0f * (float)i / 128.0f) * 9.210340371976184f);
    const float ang = (float)pos * f;
    const float c = cosf(ang), s = sinf(ang);
    const float a = base[i];
    const float b = base[i + 32];
    base[i]      = a * c - b * s;
    base[i + 32] = b * c + a * s;
}

// fused: read fp32 q, rope rope-half in registers, emit fp16 qf
__global__ void rope_conv_q(const float* __restrict__ q, __half* __restrict__ qf,
                            const int* __restrict__ past)
{
    const int idx = blockIdx.x * blockDim.x + threadIdx.x;
    if (idx >= SQ * NH * 32) return;
    const int s = idx / (NH * 32);
    const int r = idx % (NH * 32);
    const int h = r / 32;
    const int i = r % 32;
    const float* base = q + (size_t)s * DM + h * DH;
    __half* ob = qf + (size_t)s * DM + h * DH;

    const float fr = __expf(-(2.0f * (float)i / 128.0f) * 9.210340371976184f);
    const float ang = (float)(past[0] + s) * fr;
    const float c = cosf(ang), sn = sinf(ang);
    const float a = base[64 + i];
    const float b = base[96 + i];
    ob[64 + i] = __float2half_rn(a * c - b * sn);
    ob[96 + i] = __float2half_rn(b * c + a * sn);
    ob[i]      = __float2half_rn(base[i]);
    ob[i + 32] = __float2half_rn(base[i + 32]);
}

__global__ void rope_k_kernel(float* krope, const int* past)
{
    const int idx = blockIdx.x * blockDim.x + threadIdx.x;
    if (idx >= SQ * 32) return;
    rope_pair(krope + (size_t)(idx / 32) * RP, idx % 32, past[0] + idx / 32);
}

// ===================== assemble K heads -> 2-limb fp16 [h][s][d] =============
__global__ void assemble_khead16(const float* __restrict__ knope,
                                 const float* __restrict__ krope,
                                 __half* __restrict__ khi, __half* __restrict__ klo)
{
    const int idx = blockIdx.x * blockDim.x + threadIdx.x;
    if (idx >= NH * SQ * DH) return;
    const int d = idx & (DH - 1);
    const int s = (idx >> 7) & (SQ - 1);
    const int h = idx >> 18;
    float v;
    if (d < 64) v = knope[(size_t)s * PR + h * 64 + d];
    else        v = krope[(size_t)s * RP + (d - 64)];
    const __half hb = __float2half_rn(v);
    khi[idx] = hb;
    klo[idx] = __float2half_rn((v - __half2float(hb)) * 512.0f);
}

// ===================== launch ================================================
extern "C" void kernel_launch(void* const* d_in, const int* in_sizes, int n_in,
                              void* d_out, int out_size)
{
    const float* x        = (const float*)d_in[0];
    const float* W_DQ     = (const float*)d_in[1];
    const float* W_UQ     = (const float*)d_in[2];
    const float* W_DKV    = (const float*)d_in[3];
    const float* W_UK     = (const float*)d_in[4];
    const float* W_UV     = (const float*)d_in[5];
    const float* W_K_rope = (const float*)d_in[6];
    const float* W_O      = (const float*)d_in[7];
    const float* b_O      = (const float*)d_in[8];
    const int*   past     = (const int*)d_in[9];
    float* out = (float*)d_out;

    float *q, *knope, *krope;
    cudaGetSymbolAddress((void**)&q,      g_q);
    cudaGetSymbolAddress((void**)&knope,  g_knope);
    cudaGetSymbolAddress((void**)&krope,  g_krope);

    __half *xf, *cqf, *ckvf, *qf, *vf, *aof,
           *wdq, *wuq, *wdkv, *wuk, *wuv, *wkr, *wo,
           *kh_h, *kh_l, *vt_h;
    cudaGetSymbolAddress((void**)&xf,   g_xf);
    cudaGetSymbolAddress((void**)&cqf,  g_cqf);
    cudaGetSymbolAddress((void**)&ckvf, g_ckvf);
    cudaGetSymbolAddress((void**)&qf,   g_qf);
    cudaGetSymbolAddress((void**)&vf,   g_vf);
    cudaGetSymbolAddress((void**)&aof,  g_aof);
    cudaGetSymbolAddress((void**)&wdq,  g_wdq);
    cudaGetSymbolAddress((void**)&wuq,  g_wuq);
    cudaGetSymbolAddress((void**)&wdkv, g_wdkv);
    cudaGetSymbolAddress((void**)&wuk,  g_wuk);
    cudaGetSymbolAddress((void**)&wuv,  g_wuv);
    cudaGetSymbolAddress((void**)&wkr,  g_wkr);
    cudaGetSymbolAddress((void**)&wo,   g_wo);
    cudaGetSymbolAddress((void**)&kh_h, g_kh_h);  cudaGetSymbolAddress((void**)&kh_l, g_kh_l);
    cudaGetSymbolAddress((void**)&vt_h, g_vt_h);

    cudaFuncSetAttribute(gemm_f16,  cudaFuncAttributeMaxDynamicSharedMemorySize, GEMM_SMEM);
    cudaFuncSetAttribute(fa_kernel, cudaFuncAttributeMaxDynamicSharedMemorySize, FA_SMEM);

    const dim3 blk(256);
    const dim3 tb(32, 8);

    // 0-4: setup so ncu -s 5 profiles the first big GEMM
    conv_f16<<<(SQ * DM / 4 + 255) / 256, blk>>>(
        (const float4*)x, (uint2*)xf, SQ * DM / 4);
    transpose_f16w<<<dim3(PR / 32, DM / 32), tb>>>(W_DQ,  wdq,  PR, DM);
    transpose_f16w<<<dim3(DM / 32, PR / 32), tb>>>(W_UQ,  wuq,  DM, PR);
    transpose_f16w<<<dim3(PR / 32, DM / 32), tb>>>(W_DKV, wdkv, PR, DM);
    transpose_f16w<<<dim3(PR / 32, PR / 32), tb>>>(W_UK,  wuk,  PR, PR);

    // 5: cq = x @ W_DQ -> fp16 — PROFILED
    gemm_f16<<<dim3(PR / 128, SQ / 128, 1), blk, GEMM_SMEM>>>(
        xf, wdq, nullptr, cqf,
        SQ, PR, DM, DM, DM, PR, 0, 0, 0, 1.0f, nullptr);

    transpose_f16w<<<dim3(DM / 32, PR / 32), tb>>>(W_UV,     wuv, DM, PR);
    transpose_f16w<<<dim3(RP / 32, DM / 32), tb>>>(W_K_rope, wkr, RP, DM);
    transpose_f16w<<<dim3(DM / 32, DM / 32), tb>>>(W_O,      wo,  DM, DM);

    // ckv = x @ W_DKV -> fp16
    gemm_f16<<<dim3(PR / 128, SQ / 128, 1), blk, GEMM_SMEM>>>(
        xf, wdkv, nullptr, ckvf,
        SQ, PR, DM, DM, DM, PR, 0, 0, 0, 1.0f, nullptr);
    // krope = x @ W_K_rope -> fp32 (N=64)
    gemm_f16<<<dim3(1, SQ / 128, 1), blk, GEMM_SMEM>>>(
        xf, wkr, krope, nullptr,
        SQ, RP, DM, DM, DM, RP, 0, 0, 0, 1.0f, nullptr);
    // q = cq @ W_UQ -> fp32 (rope needs it)
    gemm_f16<<<dim3(DM / 128, SQ / 128, 1), blk, GEMM_SMEM>>>(
        cqf, wuq, q, nullptr,
        SQ, DM, PR, PR, PR, DM, 0, 0, 0, 1.0f, nullptr);
    // knope = ckv @ W_UK -> fp32
    gemm_f16<<<dim3(PR / 128, SQ / 128, 1), blk, GEMM_SMEM>>>(
        ckvf, wuk, knope, nullptr,
        SQ, PR, PR, PR, PR, PR, 0, 0, 0, 1.0f, nullptr);
    // v = ckv @ W_UV -> fp16 directly
    gemm_f16<<<dim3(DM / 128, SQ / 128, 1), blk, GEMM_SMEM>>>(
        ckvf, wuv, nullptr, vf,
        SQ, DM, PR, PR, PR, DM, 0, 0, 0, 1.0f, nullptr);

    // RoPE + operand prep
    rope_k_kernel<<<(SQ * 32 + 255) / 256, blk>>>(krope, past);
    rope_conv_q<<<(SQ * NH * 32 + 255) / 256, blk>>>(q, qf, past);
    assemble_khead16<<<(NH * SQ * DH + 255) / 256, blk>>>(knope, krope, kh_h, kh_l);
    transpose_vh<<<dim3(DH / 32, SQ / 32, NH), tb>>>(vf, vt_h);

    // fused attention: O = softmax(QK^T/sqrt(DH)) V -> fp16 [s][h*DH]
    fa_kernel<<<dim3(SQ / 128, NH), blk, FA_SMEM>>>(
        qf, kh_h, kh_l, vt_h, aof);

    // out = attno @ W_O + b_O  (fp32)
    gemm_f16<<<dim3(DM / 128, SQ / 128, 1), blk, GEMM_SMEM>>>(
        aof, wo, out, nullptr,
        SQ, DM, DM, DM, DM, DM, 0, 0, 0, 1.0f, b_O);
}

// round 10
// speedup vs baseline: 5.3720x; 1.0986x over previous
#include <cuda_runtime.h>
#include <cuda_bf16.h>
#include <cuda_fp16.h>
#include <cstdint>
#include <math.h>

#define SQ   2048
#define DM   4096
#define PR   2048
#define NH   32
#define DH   128
#define RP   64
#define NKV  6144           // knope(2048) | v(4096)

#define LOG2E  1.4426950408889634f

// ===================== small helpers ========================================
static __device__ __forceinline__ uint32_t smem_u32(const void* p) {
    uint32_t a;
    asm("{ .reg .u64 t; cvta.to.shared.u64 t, %1; cvt.u32.u64 %0, t; }"
        : "=r"(a) : "l"(p));
    return a;
}

// pack two floats -> fp16x2 (lo half = a, hi half = b)
static __device__ __forceinline__ uint32_t cvt_f16x2(float a, float b) {
    uint32_t r;
    asm("cvt.rn.f16x2.f32 %0, %1, %2;" : "=r"(r) : "f"(b), "f"(a));
    return r;
}

#define LDSM4(r, addr) \
    asm volatile("ldmatrix.sync.aligned.m8n8.x4.shared.b16 {%0,%1,%2,%3}, [%4];" \
        : "=r"((r)[0]), "=r"((r)[1]), "=r"((r)[2]), "=r"((r)[3]) : "r"(addr))

#define MMA16(d, a, b0v, b1v) \
    asm volatile("mma.sync.aligned.m16n8k16.row.col.f32.f16.f16.f32 " \
        "{%0,%1,%2,%3}, {%4,%5,%6,%7}, {%8,%9}, {%0,%1,%2,%3};" \
        : "+f"((d)[0]), "+f"((d)[1]), "+f"((d)[2]), "+f"((d)[3]) \
        : "r"((a)[0]), "r"((a)[1]), "r"((a)[2]), "r"((a)[3]), "r"(b0v), "r"(b1v))

#define CP_ASYNC16(sp, gp) \
    asm volatile("cp.async.cg.shared.global [%0], [%1], 16;" :: "r"(sp), "l"(gp))
#define CP_COMMIT() asm volatile("cp.async.commit_group;" ::: "memory")
#define CP_WAIT3()  asm volatile("cp.async.wait_group 3;" ::: "memory")
#define CP_WAIT1()  asm volatile("cp.async.wait_group 1;" ::: "memory")

// ===================== scratch (device globals) =============================
__device__ float g_krope[(size_t)SQ * RP];

__device__ __half g_xf  [(size_t)SQ * DM];
__device__ __half g_cqkv[(size_t)SQ * 4096];     // cq | ckv
__device__ __half g_qf  [(size_t)SQ * DM];       // q (roped in place)
__device__ __half g_kvf [(size_t)SQ * NKV];      // knope | v
__device__ __half g_aof [(size_t)SQ * DM];

// fp16 weights ([N,K] K-major)
__device__ __half g_wdqkv[(size_t)4096 * DM];    // [W_DQ; W_DKV]
__device__ __half g_wuq  [(size_t)DM * PR];
__device__ __half g_wukuv[(size_t)NKV * PR];     // [W_UK; W_UV]
__device__ __half g_wkr  [(size_t)RP * DM];
__device__ __half g_wo   [(size_t)DM * DM];

// attention operands (single fp16)
__device__ __half g_kh[(size_t)NH * SQ * DH];
__device__ __half g_vt[(size_t)NH * DH * SQ];

// ===================== single-fp16 HMMA GEMM ================================
// C = alpha * A @ B^T (+bias).  A: fp16 [M,K] row-major, B: fp16 [N,K] K-major.
// CTA tile 128x128, BK=32, 8 warps (2x4), warp tile 64x32, 4-stage cp.async.
#define STAGE_BYTES 20480
#define GEMM_SMEM   (4 * STAGE_BYTES)  // 81920

__global__ void __launch_bounds__(256, 2)
gemm_f16(const __half* __restrict__ Af, const __half* __restrict__ Bh,
         float* __restrict__ Cf, __half* __restrict__ Ch,
         int M, int N, int K, int lda, int ldb, int ldc,
         float alpha, const float* __restrict__ bias)
{
    extern __shared__ char smem[];
    const uint32_t sbase = smem_u32(smem);
    const int tid  = threadIdx.x;
    const int lane = tid & 31;
    const int w    = tid >> 5;
    const int wm   = w & 1;
    const int wn   = w >> 1;

    const int m0 = blockIdx.y * 128;
    const int n0 = blockIdx.x * 128;
    const int nk = K >> 5;

    const int lr   = tid >> 2;
    const int lcol = tid & 3;

    auto load_stage = [&](int kt, int slot) {
        const int k0 = kt << 5;
        const uint32_t sb = sbase + slot * STAGE_BYTES;
#pragma unroll
        for (int i = 0; i < 2; ++i) {
            const int r = lr + i * 64;
            const __half* gp = Af + (long long)(m0 + r) * lda + k0 + lcol * 8;
            CP_ASYNC16(sb + r * 80 + lcol * 16, gp);
        }
#pragma unroll
        for (int i = 0; i < 2; ++i) {
            const int r = lr + i * 64;
            int rn = n0 + r; if (rn >= N) rn = N - 1;
            const __half* gp = Bh + (long long)rn * ldb + k0 + lcol * 8;
            CP_ASYNC16(sb + 10240 + r * 80 + lcol * 16, gp);
        }
        CP_COMMIT();
    };

    const uint32_t aOff = (uint32_t)((wm * 64 + (lane & 15)) * 80 + ((lane >> 4) & 1) * 16);
    const uint32_t bOff = (uint32_t)((wn * 32 + ((lane >> 4) & 1) * 8 + (lane & 7)) * 80
                                     + ((lane >> 3) & 1) * 16);

    float acc[4][4][4];
#pragma unroll
    for (int a = 0; a < 4; a++)
#pragma unroll
        for (int b = 0; b < 4; b++)
#pragma unroll
            for (int c = 0; c < 4; c++) acc[a][b][c] = 0.0f;

    load_stage(0, 0);
    if (nk > 1) load_stage(1, 1); else CP_COMMIT();
    if (nk > 2) load_stage(2, 2); else CP_COMMIT();

    for (int kt = 0; kt < nk; ++kt) {
        if (kt + 3 < nk) load_stage(kt + 3, (kt + 3) & 3);
        else CP_COMMIT();
        CP_WAIT3();
        __syncthreads();

        const uint32_t sb = sbase + (kt & 3) * STAGE_BYTES;
#pragma unroll
        for (int kk = 0; kk < 2; ++kk) {
            uint32_t af[4][4], bh[2][4];
#pragma unroll
            for (int mt = 0; mt < 4; ++mt)
                LDSM4(af[mt], sb + aOff + mt * 1280 + kk * 32);
#pragma unroll
            for (int bt = 0; bt < 2; ++bt)
                LDSM4(bh[bt], sb + 10240 + bOff + bt * 1280 + kk * 32);
#pragma unroll
            for (int mt = 0; mt < 4; ++mt)
#pragma unroll
                for (int nt = 0; nt < 4; ++nt) {
                    const int bt = nt >> 1, s2 = (nt & 1) * 2;
                    MMA16(acc[mt][nt], af[mt], bh[bt][s2], bh[bt][s2 + 1]);
                }
        }
        __syncthreads();
    }

    const int er = lane >> 2;
    const int ec = (lane & 3) << 1;
#pragma unroll
    for (int mt = 0; mt < 4; ++mt) {
#pragma unroll
        for (int nt = 0; nt < 4; ++nt) {
            const int gr = m0 + wm * 64 + mt * 16 + er;
            const int gc = n0 + wn * 32 + nt * 8 + ec;
            if (gc >= N) continue;
            float v0 = acc[mt][nt][0] * alpha;
            float v1 = acc[mt][nt][1] * alpha;
            float v2 = acc[mt][nt][2] * alpha;
            float v3 = acc[mt][nt][3] * alpha;
            if (bias) {
                const float b0 = bias[gc], b1 = bias[gc + 1];
                v0 += b0; v1 += b1; v2 += b0; v3 += b1;
            }
            const long long o0 = (long long)gr * ldc + gc;
            const long long o1 = (long long)(gr + 8) * ldc + gc;
            if (Cf) {
                *(float2*)&Cf[o0] = make_float2(v0, v1);
                *(float2*)&Cf[o1] = make_float2(v2, v3);
            }
            if (Ch) {
                *(uint32_t*)&Ch[o0] = cvt_f16x2(v0, v1);
                *(uint32_t*)&Ch[o1] = cvt_f16x2(v2, v3);
            }
        }
    }
}

// ===================== fused flash attention =================================
// O = softmax(Q K^T / sqrt(DH)) V; online softmax.  All operands single fp16.
// Q: [s][h*DH+d].  K: [h][s][d].  V^T: [h][d][s].  O: [s][h*DH+d].
#define FA_QPITCH 272
#define FA_KPITCH 272
#define FA_VPITCH 144
#define FA_Q      0
#define FA_KBUF   34816                 // 2 bufs x 64*272
#define FA_VBUF   (FA_KBUF + 2 * 17408) // 2 bufs x 128*144
#define FA_SMEM   (FA_VBUF + 2 * 18432) // 106496

__global__ void __launch_bounds__(256, 1)
fa_kernel(const __half* __restrict__ Qf, const __half* __restrict__ Kh,
          const __half* __restrict__ Vh, __half* __restrict__ O)
{
    extern __shared__ char smem[];
    const uint32_t sb = smem_u32(smem);
    const int tid  = threadIdx.x;
    const int lane = tid & 31;
    const int w    = tid >> 5;
    const int h    = blockIdx.y;
    const int m0   = blockIdx.x * 128;

    Kh += (size_t)h * SQ * DH;
    Vh += (size_t)h * DH * SQ;

    {
        const __half* qg = Qf + (size_t)m0 * DM + h * DH;
#pragma unroll
        for (int i = 0; i < 8; ++i) {
            const int id = tid + i * 256;
            const int r = id >> 4, c = id & 15;
            CP_ASYNC16(sb + FA_Q + r * FA_QPITCH + c * 16, qg + (size_t)r * DM + c * 8);
        }
    }
    auto loadKV = [&](int c, int buf) {
        const int k0 = c << 6;
        const uint32_t kb = sb + FA_KBUF + buf * 17408;
#pragma unroll
        for (int i = 0; i < 4; ++i) {
            const int id = tid + i * 256;
            const int r = id >> 4, cc = id & 15;
            CP_ASYNC16(kb + r * FA_KPITCH + cc * 16,
                       Kh + (size_t)(k0 + r) * DH + cc * 8);
        }
        const uint32_t vb = sb + FA_VBUF + buf * 18432;
#pragma unroll
        for (int i = 0; i < 4; ++i) {
            const int id = tid + i * 256;
            const int r = id >> 3, cc = id & 7;
            CP_ASYNC16(vb + r * FA_VPITCH + cc * 16,
                       Vh + (size_t)r * SQ + k0 + cc * 8);
        }
    };

    loadKV(0, 0);
    CP_COMMIT();

    const uint32_t qOff = sb + FA_Q + (w * 16 + (lane & 15)) * FA_QPITCH
                          + ((lane >> 4) & 1) * 16;
    const uint32_t kOff = (uint32_t)((((lane >> 4) & 1) * 8 + (lane & 7)) * FA_KPITCH
                          + ((lane >> 3) & 1) * 16);
    const uint32_t vOff = (uint32_t)((((lane >> 4) & 1) * 8 + (lane & 7)) * FA_VPITCH
                          + ((lane >> 3) & 1) * 16);

    float acc_o[16][4];
#pragma unroll
    for (int i = 0; i < 16; ++i)
#pragma unroll
        for (int j = 0; j < 4; ++j) acc_o[i][j] = 0.0f;

    float mr0 = -1e30f, mr1 = -1e30f, l0 = 0.0f, l1 = 0.0f;
    const float sc_al = 0.08838834764831845f * LOG2E;

    const int NC = SQ / 64;
    for (int c = 0; c < NC; ++c) {
        if (c + 1 < NC) loadKV(c + 1, (c + 1) & 1);
        CP_COMMIT();
        CP_WAIT1();
        __syncthreads();

        const uint32_t kb = sb + FA_KBUF + (c & 1) * 17408;
        const uint32_t vb = sb + FA_VBUF + (c & 1) * 18432;

        float s[8][4];
#pragma unroll
        for (int i = 0; i < 8; ++i)
#pragma unroll
            for (int j = 0; j < 4; ++j) s[i][j] = 0.0f;

#pragma unroll
        for (int kk = 0; kk < 8; ++kk) {
            uint32_t aq[4];
            LDSM4(aq, qOff + kk * 32);
#pragma unroll
            for (int ntp = 0; ntp < 4; ++ntp) {
                uint32_t kh4[4];
                LDSM4(kh4, kb + kOff + ntp * (16 * FA_KPITCH) + kk * 32);
                MMA16(s[2 * ntp],     aq, kh4[0], kh4[1]);
                MMA16(s[2 * ntp + 1], aq, kh4[2], kh4[3]);
            }
        }
#pragma unroll
        for (int nt = 0; nt < 8; ++nt)
#pragma unroll
            for (int j = 0; j < 4; ++j)
                s[nt][j] *= sc_al;

        float mx0 = -1e30f, mx1 = -1e30f;
#pragma unroll
        for (int nt = 0; nt < 8; ++nt) {
            mx0 = fmaxf(mx0, fmaxf(s[nt][0], s[nt][1]));
            mx1 = fmaxf(mx1, fmaxf(s[nt][2], s[nt][3]));
        }
        mx0 = fmaxf(mx0, __shfl_xor_sync(0xffffffffu, mx0, 1));
        mx0 = fmaxf(mx0, __shfl_xor_sync(0xffffffffu, mx0, 2));
        mx1 = fmaxf(mx1, __shfl_xor_sync(0xffffffffu, mx1, 1));
        mx1 = fmaxf(mx1, __shfl_xor_sync(0xffffffffu, mx1, 2));

        const float mn0 = fmaxf(mr0, mx0);
        const float mn1 = fmaxf(mr1, mx1);
        const float sc0 = exp2f(mr0 - mn0);
        const float sc1 = exp2f(mr1 - mn1);

        float rs0 = 0.0f, rs1 = 0.0f;
#pragma unroll
        for (int nt = 0; nt < 8; ++nt) {
            s[nt][0] = exp2f(s[nt][0] - mn0);
            s[nt][1] = exp2f(s[nt][1] - mn0);
            s[nt][2] = exp2f(s[nt][2] - mn1);
            s[nt][3] = exp2f(s[nt][3] - mn1);
            rs0 += s[nt][0] + s[nt][1];
            rs1 += s[nt][2] + s[nt][3];
        }
        rs0 += __shfl_xor_sync(0xffffffffu, rs0, 1);
        rs0 += __shfl_xor_sync(0xffffffffu, rs0, 2);
        rs1 += __shfl_xor_sync(0xffffffffu, rs1, 1);
        rs1 += __shfl_xor_sync(0xffffffffu, rs1, 2);

        l0 = l0 * sc0 + rs0;
        l1 = l1 * sc1 + rs1;
        mr0 = mn0;  mr1 = mn1;

#pragma unroll
        for (int nt = 0; nt < 16; ++nt) {
            acc_o[nt][0] *= sc0;  acc_o[nt][1] *= sc0;
            acc_o[nt][2] *= sc1;  acc_o[nt][3] *= sc1;
        }

#pragma unroll
        for (int kg = 0; kg < 4; ++kg) {
            uint32_t A[4];
            A[0] = cvt_f16x2(s[2 * kg][0],     s[2 * kg][1]);
            A[1] = cvt_f16x2(s[2 * kg][2],     s[2 * kg][3]);
            A[2] = cvt_f16x2(s[2 * kg + 1][0], s[2 * kg + 1][1]);
            A[3] = cvt_f16x2(s[2 * kg + 1][2], s[2 * kg + 1][3]);
#pragma unroll
            for (int dp = 0; dp < 8; ++dp) {
                uint32_t vh4[4];
                LDSM4(vh4, vb + vOff + dp * (16 * FA_VPITCH) + kg * 32);
                MMA16(acc_o[2 * dp],     A, vh4[0], vh4[1]);
                MMA16(acc_o[2 * dp + 1], A, vh4[2], vh4[3]);
            }
        }
        __syncthreads();
    }

    const float i0 = 1.0f / l0;
    const float i1 = 1.0f / l1;
    const int er = lane >> 2;
    const int ec = (lane & 3) << 1;
    const int gr0 = m0 + w * 16 + er;
    __half* ob = O + (size_t)gr0 * DM + h * DH + ec;
#pragma unroll
    for (int nt = 0; nt < 16; ++nt) {
        *(uint32_t*)(ob + nt * 8) =
            cvt_f16x2(acc_o[nt][0] * i0, acc_o[nt][1] * i0);
        *(uint32_t*)(ob + (size_t)8 * DM + nt * 8) =
            cvt_f16x2(acc_o[nt][2] * i1, acc_o[nt][3] * i1);
    }
}

// ===================== fp32 -> fp16 convert ==================================
__global__ void conv_f16(const float4* __restrict__ in, uint2* __restrict__ o, int n4)
{
    const int i = blockIdx.x * blockDim.x + threadIdx.x;
    if (i >= n4) return;
    const float4 f = in[i];
    o[i] = make_uint2(cvt_f16x2(f.x, f.y), cvt_f16x2(f.z, f.w));
}

// ===================== transpose fp32 [K,N] -> fp16 [N,K] ====================
__global__ void transpose_f16w(const float* __restrict__ in,
                               __half* __restrict__ o, int ldin, int ldout)
{
    __shared__ float t[32][33];
    const int c0 = blockIdx.x * 32, r0 = blockIdx.y * 32;
    const int tx = threadIdx.x, ty = threadIdx.y;
#pragma unroll
    for (int j = 0; j < 32; j += 8)
        t[ty + j][tx] = in[(long long)(r0 + ty + j) * ldin + c0 + tx];
    __syncthreads();
#pragma unroll
    for (int j = 0; j < 32; j += 8)
        o[(long long)(c0 + ty + j) * ldout + r0 + tx] = __float2half_rn(t[tx][ty + j]);
}

// per-head V transpose: kvf fp16 [s][2048 + h*128 + d] -> vt [h][d][s]
__global__ void transpose_vh(const __half* __restrict__ in, __half* __restrict__ o)
{
    __shared__ __half t[32][40];
    const long long z = blockIdx.z;
    in += PR + z * DH;                   // skip knope columns
    o  += z * (long long)DH * SQ;
    const int c0 = blockIdx.x * 32, r0 = blockIdx.y * 32;
    const int tx = threadIdx.x, ty = threadIdx.y;
#pragma unroll
    for (int j = 0; j < 32; j += 8)
        t[ty + j][tx] = in[(long long)(r0 + ty + j) * NKV + c0 + tx];
    __syncthreads();
#pragma unroll
    for (int j = 0; j < 32; j += 8)
        o[(long long)(c0 + ty + j) * SQ + r0 + tx] = t[tx][ty + j];
}

// ===================== RoPE ==================================================
// in-place fp16 rope of q's rope-half (each thread owns disjoint elements)
__global__ void rope_q16(__half* __restrict__ q, const int* __restrict__ past)
{
    const int idx = blockIdx.x * blockDim.x + threadIdx.x;
    if (idx >= SQ * NH * 32) return;
    const int s = idx / (NH * 32);
    const int r = idx % (NH * 32);
    const int h = r / 32;
    const int i = r % 32;
    __half* base = q + (size_t)s * DM + h * DH + 64;

    const float fr = __expf(-(2.0f * (float)i / 128.0f) * 9.210340371976184f);
    const float ang = (float)(past[0] + s) * fr;
    const float c = cosf(ang), sn = sinf(ang);
    const float a = __half2float(base[i]);
    const float b = __half2float(base[i + 32]);
    base[i]      = __float2half_rn(a * c - b * sn);
    base[i + 32] = __float2half_rn(b * c + a * sn);
}

__global__ void rope_k_kernel(float* krope, const int* past)
{
    const int idx = blockIdx.x * blockDim.x + threadIdx.x;
    if (idx >= SQ * 32) return;
    const int s = idx / 32;
    const int i = idx % 32;
    float* base = krope + (size_t)s * RP;
    const float fr = __expf(-(2.0f * (float)i / 128.0f) * 9.210340371976184f);
    const float ang = (float)(past[0] + s) * fr;
    const float c = cosf(ang), sn = sinf(ang);
    const float a = base[i];
    const float b = base[i + 32];
    base[i]      = a * c - b * sn;
    base[i + 32] = b * c + a * sn;
}

// ===================== assemble K heads -> fp16 [h][s][d] ====================
__global__ void assemble_khead16(const __half* __restrict__ kvf,
                                 const float* __restrict__ krope,
                                 __half* __restrict__ kh)
{
    const int idx = blockIdx.x * blockDim.x + threadIdx.x;
    if (idx >= NH * SQ * DH) return;
    const int d = idx & (DH - 1);
    const int s = (idx >> 7) & (SQ - 1);
    const int h = idx >> 18;
    __half v;
    if (d < 64) v = kvf[(size_t)s * NKV + h * 64 + d];
    else        v = __float2half_rn(krope[(size_t)s * RP + (d - 64)]);
    kh[idx] = v;
}

// ===================== launch ================================================
extern "C" void kernel_launch(void* const* d_in, const int* in_sizes, int n_in,
                              void* d_out, int out_size)
{
    const float* x        = (const float*)d_in[0];
    const float* W_DQ     = (const float*)d_in[1];
    const float* W_UQ     = (const float*)d_in[2];
    const float* W_DKV    = (const float*)d_in[3];
    const float* W_UK     = (const float*)d_in[4];
    const float* W_UV     = (const float*)d_in[5];
    const float* W_K_rope = (const float*)d_in[6];
    const float* W_O      = (const float*)d_in[7];
    const float* b_O      = (const float*)d_in[8];
    const int*   past     = (const int*)d_in[9];
    float* out = (float*)d_out;

    float* krope;
    cudaGetSymbolAddress((void**)&krope, g_krope);

    __half *xf, *cqkv, *qf, *kvf, *aof,
           *wdqkv, *wuq, *wukuv, *wkr, *wo, *kh, *vt;
    cudaGetSymbolAddress((void**)&xf,    g_xf);
    cudaGetSymbolAddress((void**)&cqkv,  g_cqkv);
    cudaGetSymbolAddress((void**)&qf,    g_qf);
    cudaGetSymbolAddress((void**)&kvf,   g_kvf);
    cudaGetSymbolAddress((void**)&aof,   g_aof);
    cudaGetSymbolAddress((void**)&wdqkv, g_wdqkv);
    cudaGetSymbolAddress((void**)&wuq,   g_wuq);
    cudaGetSymbolAddress((void**)&wukuv, g_wukuv);
    cudaGetSymbolAddress((void**)&wkr,   g_wkr);
    cudaGetSymbolAddress((void**)&wo,    g_wo);
    cudaGetSymbolAddress((void**)&kh,    g_kh);
    cudaGetSymbolAddress((void**)&vt,    g_vt);

    cudaFuncSetAttribute(gemm_f16,  cudaFuncAttributeMaxDynamicSharedMemorySize, GEMM_SMEM);
    cudaFuncSetAttribute(fa_kernel, cudaFuncAttributeMaxDynamicSharedMemorySize, FA_SMEM);

    const dim3 blk(256);
    const dim3 tb(32, 8);

    // 0-4: setup so ncu -s 5 profiles the fused cq|ckv GEMM
    conv_f16<<<(SQ * DM / 4 + 255) / 256, blk>>>(
        (const float4*)x, (uint2*)xf, SQ * DM / 4);
    transpose_f16w<<<dim3(PR / 32, DM / 32), tb>>>(W_DQ,  wdqkv,                      PR, DM);
    transpose_f16w<<<dim3(PR / 32, DM / 32), tb>>>(W_DKV, wdqkv + (size_t)PR * DM,    PR, DM);
    transpose_f16w<<<dim3(PR / 32, PR / 32), tb>>>(W_UK,  wukuv,                      PR, PR);
    transpose_f16w<<<dim3(DM / 32, PR / 32), tb>>>(W_UQ,  wuq,                        DM, PR);

    // 5: cq|ckv = x @ [W_DQ; W_DKV]  (N=4096, fp16 out) — PROFILED
    gemm_f16<<<dim3(4096 / 128, SQ / 128), blk, GEMM_SMEM>>>(
        xf, wdqkv, nullptr, cqkv,
        SQ, 4096, DM, DM, DM, 4096, 1.0f, nullptr);

    transpose_f16w<<<dim3(DM / 32, PR / 32), tb>>>(W_UV,     wukuv + (size_t)PR * PR, DM, PR);
    transpose_f16w<<<dim3(RP / 32, DM / 32), tb>>>(W_K_rope, wkr,                     RP, DM);
    transpose_f16w<<<dim3(DM / 32, DM / 32), tb>>>(W_O,      wo,                      DM, DM);

    // knope|v = ckv @ [W_UK; W_UV]  (N=6144, fp16 out)
    gemm_f16<<<dim3(NKV / 128, SQ / 128), blk, GEMM_SMEM>>>(
        cqkv + PR, wukuv, nullptr, kvf,
        SQ, NKV, PR, 4096, PR, NKV, 1.0f, nullptr);

    // q = cq @ W_UQ  (fp16 out, roped in place next)
    gemm_f16<<<dim3(DM / 128, SQ / 128), blk, GEMM_SMEM>>>(
        cqkv, wuq, nullptr, qf,
        SQ, DM, PR, 4096, PR, DM, 1.0f, nullptr);

    // krope = x @ W_K_rope  (fp32 out, N=64)
    gemm_f16<<<dim3(1, SQ / 128), blk, GEMM_SMEM>>>(
        xf, wkr, krope, nullptr,
        SQ, RP, DM, DM, DM, RP, 1.0f, nullptr);

    // RoPE + operand prep
    rope_k_kernel<<<(SQ * 32 + 255) / 256, blk>>>(krope, past);
    rope_q16<<<(SQ * NH * 32 + 255) / 256, blk>>>(qf, past);
    assemble_khead16<<<(NH * SQ * DH + 255) / 256, blk>>>(kvf, krope, kh);
    transpose_vh<<<dim3(DH / 32, SQ / 32, NH), tb>>>(kvf, vt);

    // fused attention -> fp16 [s][h*DH]
    fa_kernel<<<dim3(SQ / 128, NH), blk, FA_SMEM>>>(qf, kh, vt, aof);

    // out = attno @ W_O + b_O  (fp32)
    gemm_f16<<<dim3(DM / 128, SQ / 128), blk, GEMM_SMEM>>>(
        aof, wo, out, nullptr,
        SQ, DM, DM, DM, DM, DM, 1.0f, b_O);
}